// round 8
// baseline (speedup 1.0000x reference)
#include <cuda_runtime.h>
#include <cuda_bf16.h>
#include <cstdint>

#define NN 50000
#define DD 128
#define EE 800000

// ---------------- scratch (static device globals: no allocation) ----------------
__device__ __align__(16) float g_agg[NN * DD];
__device__ __align__(16) float g_y1[NN * DD];
__device__ __align__(16) float g_y2[NN * DD];
__device__ __align__(16) float g_stats[1536];  // 6 banks x 256 (sum[128], sq[128]); zero at launch start
__device__ __align__(16) float g_s2[DD];       // outer BN scale/shift
__device__ __align__(16) float g_t2[DD];
__device__ int g_is64;
// bf16 weight images, W^T as [N][K] row-major: 6 matrices, hi+lo split
__device__ __align__(16) unsigned short g_whi[6 * DD * DD];
__device__ __align__(16) unsigned short g_wlo[6 * DD * DD];
// CSR (edges bucketed by dst) — built once per launch
__device__ int g_deg[50176];
__device__ int g_off[50176];
__device__ int g_cursor[50176];
__device__ int g_srcs[EE];

__device__ __forceinline__ uint32_t smem_to_u32(const void* p) {
    uint32_t a;
    asm("{ .reg .u64 t; cvta.to.shared.u64 t, %1; cvt.u32.u64 %0, t; }" : "=r"(a) : "l"(p));
    return a;
}

#define LDMX4(r0, r1, r2, r3, addr) \
    asm volatile("ldmatrix.sync.aligned.m8n8.x4.shared.b16 {%0,%1,%2,%3}, [%4];" \
                 : "=r"(r0), "=r"(r1), "=r"(r2), "=r"(r3) : "r"(addr))

#define MMA16816(d, a, b) \
    asm volatile("mma.sync.aligned.m16n8k16.row.col.f32.bf16.bf16.f32 " \
                 "{%0,%1,%2,%3}, {%4,%5,%6,%7}, {%8,%9}, {%0,%1,%2,%3};" \
                 : "+f"((d)[0]), "+f"((d)[1]), "+f"((d)[2]), "+f"((d)[3]) \
                 : "r"((a)[0]), "r"((a)[1]), "r"((a)[2]), "r"((a)[3]), "r"((b)[0]), "r"((b)[1]))

// ======= prep: weight transpose+split, zero degree array, detect dtype — ONE kernel =======
__global__ void prep_k(const float* __restrict__ W1, const float* __restrict__ W2,
                       const int* __restrict__ ei32)
{
    int b = blockIdx.x;                      // 384 blocks
    int wi = b >> 6;
    int id = ((b & 63) << 8) + threadIdx.x;
    const float* W = (wi < 3) ? (W1 + (size_t)wi * 16384) : (W2 + (size_t)(wi - 3) * 16384);
    int k = id >> 7, n = id & 127;
    float v = W[k * 128 + n];
    __nv_bfloat16 hb = __float2bfloat16(v);
    __nv_bfloat16 lb = __float2bfloat16(v - __bfloat162float(hb));
    g_whi[(size_t)wi * 16384 + n * 128 + k] = __bfloat16_as_ushort(hb);
    g_wlo[(size_t)wi * 16384 + n * 128 + k] = __bfloat16_as_ushort(lb);

    if (b < 196) g_deg[b * 256 + threadIdx.x] = 0;

    if (b == 0 && threadIdx.x == 0) {
        int is64 = 1;
#pragma unroll
        for (int i = 0; i < 8; i++)
            if (ei32[2 * i + 1] != 0) is64 = 0;
        g_is64 = is64;
    }
}

// ---------------- count: 4 edges/thread, vector loads ----------------
__global__ void count4_k(const int* __restrict__ ei32) {   // 782 x 256
    int e0 = (blockIdx.x * 256 + threadIdx.x) * 4;
    if (e0 >= EE) return;                     // EE % 4 == 0: no partial tail
    int d[4];
    if (g_is64) {
        int4 q0 = *(const int4*)&ei32[2 * (EE + e0)];
        int4 q1 = *(const int4*)&ei32[2 * (EE + e0) + 4];
        d[0] = q0.x; d[1] = q0.z; d[2] = q1.x; d[3] = q1.z;
    } else {
        int4 q = *(const int4*)&ei32[EE + e0];
        d[0] = q.x; d[1] = q.y; d[2] = q.z; d[3] = q.w;
    }
#pragma unroll
    for (int j = 0; j < 4; j++) atomicAdd(&g_deg[d[j]], 1);
}

// ---------------- exclusive scan over 50176 degrees: ONE block ----------------
__global__ void scan_k() {                    // 1 x 1024; each thread owns 49 elems
    __shared__ int ssum[1024];
    int t = threadIdx.x;
    int base = t * 49;                        // 1024*49 = 50176
    int s = 0;
#pragma unroll 7
    for (int i = 0; i < 49; i++) s += g_deg[base + i];
    ssum[t] = s;
    __syncthreads();
    for (int o = 1; o < 1024; o <<= 1) {
        int v = (t >= o) ? ssum[t - o] : 0;
        __syncthreads();
        ssum[t] += v;
        __syncthreads();
    }
    int run = ssum[t] - s;                    // exclusive prefix
#pragma unroll 7
    for (int i = 0; i < 49; i++) {
        int d = g_deg[base + i];
        g_off[base + i] = run;
        g_cursor[base + i] = run;
        run += d;
    }
}

// ---------------- fill: 4 edges/thread, vector loads ----------------
__global__ void fill4_k(const int* __restrict__ ei32) {    // 782 x 256
    int e0 = (blockIdx.x * 256 + threadIdx.x) * 4;
    if (e0 >= EE) return;
    int s[4], d[4];
    if (g_is64) {
        int4 p0 = *(const int4*)&ei32[2 * e0];
        int4 p1 = *(const int4*)&ei32[2 * e0 + 4];
        s[0] = p0.x; s[1] = p0.z; s[2] = p1.x; s[3] = p1.z;
        int4 q0 = *(const int4*)&ei32[2 * (EE + e0)];
        int4 q1 = *(const int4*)&ei32[2 * (EE + e0) + 4];
        d[0] = q0.x; d[1] = q0.z; d[2] = q1.x; d[3] = q1.z;
    } else {
        int4 p = *(const int4*)&ei32[e0];
        s[0] = p.x; s[1] = p.y; s[2] = p.z; s[3] = p.w;
        int4 q = *(const int4*)&ei32[EE + e0];
        d[0] = q.x; d[1] = q.y; d[2] = q.z; d[3] = q.w;
    }
#pragma unroll
    for (int j = 0; j < 4; j++) {
        int pos = atomicAdd(&g_cursor[d[j]], 1);
        g_srcs[pos] = s[j];
    }
}

// ------- aggregation: per-node gather + register sum; TRANS applies prev outer BN ----
template <int TRANS>
__global__ void __launch_bounds__(256) agg_k(const float* __restrict__ P) {
    int w = blockIdx.x * 8 + (threadIdx.x >> 5);  // 6250 blocks -> 50000 warps
    int lane = threadIdx.x & 31;
    int s = g_off[w], t = g_off[w + 1];
    float4 sv, tv;
    if (TRANS) {
        sv = *(const float4*)(g_s2 + lane * 4);
        tv = *(const float4*)(g_t2 + lane * 4);
    }
    float4 acc = make_float4(0.f, 0.f, 0.f, 0.f);
    int e = s;
    for (; e + 1 < t; e += 2) {
        int s0 = g_srcs[e], s1 = g_srcs[e + 1];
        float4 v0 = *(const float4*)(P + (size_t)s0 * DD + lane * 4);
        float4 v1 = *(const float4*)(P + (size_t)s1 * DD + lane * 4);
        if (TRANS) {
            v0.x = fmaf(v0.x, sv.x, tv.x); v0.y = fmaf(v0.y, sv.y, tv.y);
            v0.z = fmaf(v0.z, sv.z, tv.z); v0.w = fmaf(v0.w, sv.w, tv.w);
            v1.x = fmaf(v1.x, sv.x, tv.x); v1.y = fmaf(v1.y, sv.y, tv.y);
            v1.z = fmaf(v1.z, sv.z, tv.z); v1.w = fmaf(v1.w, sv.w, tv.w);
        }
        acc.x += fmaxf(v0.x, 0.f) + fmaxf(v1.x, 0.f);
        acc.y += fmaxf(v0.y, 0.f) + fmaxf(v1.y, 0.f);
        acc.z += fmaxf(v0.z, 0.f) + fmaxf(v1.z, 0.f);
        acc.w += fmaxf(v0.w, 0.f) + fmaxf(v1.w, 0.f);
    }
    if (e < t) {
        int s0 = g_srcs[e];
        float4 v0 = *(const float4*)(P + (size_t)s0 * DD + lane * 4);
        if (TRANS) {
            v0.x = fmaf(v0.x, sv.x, tv.x); v0.y = fmaf(v0.y, sv.y, tv.y);
            v0.z = fmaf(v0.z, sv.z, tv.z); v0.w = fmaf(v0.w, sv.w, tv.w);
        }
        acc.x += fmaxf(v0.x, 0.f);
        acc.y += fmaxf(v0.y, 0.f);
        acc.z += fmaxf(v0.z, 0.f);
        acc.w += fmaxf(v0.w, 0.f);
    }
    *(float4*)(g_agg + (size_t)w * DD + lane * 4) = acc;
}

// ---------------- HMMA GEMM (128x128x128, bf16-split, fused BN-stats epilogue) ----
// MODE 1: A = (1+eps)*own + agg ; own = P[row] (TRANS=0) or relu(P[row]*s2+t2) (TRANS=1)
// MODE 2: A = relu(y1*s1+t1), s1/t1 computed inline per block from statIn + bn params
#define TSTRIDE 136
#define TBYTES  (128 * TSTRIDE * 2)
#define BIAS_OFF 0
#define AHI_OFF  1024
#define ALO_OFF  (AHI_OFF + TBYTES)
#define BHI_OFF  (ALO_OFF + TBYTES)
#define BLO_OFF  (BHI_OFF + TBYTES)
#define STAT_OFF (BLO_OFF + TBYTES)
#define SN_OFF   (STAT_OFF + 1024)
#define GEMM_SMEM (SN_OFF + 1024)

template <int MODE, int TRANS>
__global__ void __launch_bounds__(256, 1) gemm_tc_k(
    const float* __restrict__ A0, const float* __restrict__ epsp, int layer,
    const unsigned short* __restrict__ whi, const unsigned short* __restrict__ wlo,
    const float* __restrict__ bias, float* __restrict__ Y,
    float* __restrict__ statOut,
    const float* __restrict__ statIn, const float* __restrict__ bnG, const float* __restrict__ bnB)
{
    extern __shared__ __align__(16) char smem[];
    uint32_t sb = smem_to_u32(smem);
    int tid = threadIdx.x;
    int wid = tid >> 5, lane = tid & 31;
    int rowBase = blockIdx.x * 128;

    if (tid < 128) *(float*)(smem + BIAS_OFF + tid * 4) = bias[tid];
    ((float*)(smem + STAT_OFF))[tid] = 0.f;

    float* sN = (float*)(smem + SN_OFF);      // 128 scale + 128 shift
    float* tN = sN + 128;
    if (MODE == 2) {
        if (tid < 128) {
            float mu  = statIn[tid] * (1.0f / NN);
            float var = statIn[128 + tid] * (1.0f / NN) - mu * mu;
            float sc  = bnG[tid] * rsqrtf(var + 1e-5f);
            sN[tid] = sc;
            tN[tid] = bnB[tid] - mu * sc;
        }
        __syncthreads();
    }

    // ---- B tiles ----
    {
        const uint4* sh = (const uint4*)whi;
        const uint4* sl = (const uint4*)wlo;
#pragma unroll
        for (int i = 0; i < 8; i++) {
            int id = i * 256 + tid;
            int r = id >> 4, c16 = id & 15;
            uint32_t dst = (uint32_t)(r * (TSTRIDE * 2) + c16 * 16);
            *(uint4*)(smem + BHI_OFF + dst) = sh[id];
            *(uint4*)(smem + BLO_OFF + dst) = sl[id];
        }
    }

    // ---- A tile: fused transform + bf16 split ----
    float epsv = (MODE == 1) ? (1.0f + epsp[layer]) : 0.0f;
#pragma unroll
    for (int it = 0; it < 8; it++) {
        int id = it * 256 + tid;
        int row = id >> 4;
        int col = (id & 15) * 8;
        int gr = rowBase + row;
        float v[8];
#pragma unroll
        for (int j = 0; j < 8; j++) v[j] = 0.f;
        if (gr < NN) {
            float4 p0 = *(const float4*)(A0 + (size_t)gr * DD + col);
            float4 p1 = *(const float4*)(A0 + (size_t)gr * DD + col + 4);
            v[0] = p0.x; v[1] = p0.y; v[2] = p0.z; v[3] = p0.w;
            v[4] = p1.x; v[5] = p1.y; v[6] = p1.z; v[7] = p1.w;
            if (MODE == 1) {
                if (TRANS) {
#pragma unroll
                    for (int j = 0; j < 8; j++)
                        v[j] = fmaxf(fmaf(v[j], g_s2[col + j], g_t2[col + j]), 0.f);
                }
                float4 a0 = *(const float4*)(g_agg + (size_t)gr * DD + col);
                float4 a1 = *(const float4*)(g_agg + (size_t)gr * DD + col + 4);
                v[0] = fmaf(epsv, v[0], a0.x); v[1] = fmaf(epsv, v[1], a0.y);
                v[2] = fmaf(epsv, v[2], a0.z); v[3] = fmaf(epsv, v[3], a0.w);
                v[4] = fmaf(epsv, v[4], a1.x); v[5] = fmaf(epsv, v[5], a1.y);
                v[6] = fmaf(epsv, v[6], a1.z); v[7] = fmaf(epsv, v[7], a1.w);
            } else {
#pragma unroll
                for (int j = 0; j < 8; j++)
                    v[j] = fmaxf(fmaf(v[j], sN[col + j], tN[col + j]), 0.f);
            }
        }
        uint32_t h[4], l[4];
#pragma unroll
        for (int j = 0; j < 4; j++) {
            __nv_bfloat16 h0 = __float2bfloat16(v[2 * j]);
            __nv_bfloat16 h1 = __float2bfloat16(v[2 * j + 1]);
            __nv_bfloat16 l0 = __float2bfloat16(v[2 * j] - __bfloat162float(h0));
            __nv_bfloat16 l1 = __float2bfloat16(v[2 * j + 1] - __bfloat162float(h1));
            h[j] = ((uint32_t)__bfloat16_as_ushort(h1) << 16) | __bfloat16_as_ushort(h0);
            l[j] = ((uint32_t)__bfloat16_as_ushort(l1) << 16) | __bfloat16_as_ushort(l0);
        }
        uint32_t off = (uint32_t)(row * (TSTRIDE * 2) + col * 2);
        *(uint4*)(smem + AHI_OFF + off) = make_uint4(h[0], h[1], h[2], h[3]);
        *(uint4*)(smem + ALO_OFF + off) = make_uint4(l[0], l[1], l[2], l[3]);
    }
    __syncthreads();

    // ---- warp MMA mainloop ----
    int wm = wid & 1, wn = wid >> 1;
    int m0 = wm * 64, n0 = wn * 32;

    float acc[4][4][4];
#pragma unroll
    for (int i = 0; i < 4; i++)
#pragma unroll
        for (int j = 0; j < 4; j++)
#pragma unroll
            for (int q = 0; q < 4; q++) acc[i][j][q] = 0.f;

    uint32_t aOff = (uint32_t)((m0 + (lane & 15)) * (TSTRIDE * 2) + (lane >> 4) * 16);
    uint32_t bOff = (uint32_t)((n0 + (lane & 7) + (lane >> 4) * 8) * (TSTRIDE * 2) + ((lane >> 3) & 1) * 16);

#pragma unroll
    for (int ks = 0; ks < 8; ks++) {
        uint32_t kByte = (uint32_t)(ks * 32);
        uint32_t ah[4][4], al[4][4], bh[4][2], bl[4][2];
#pragma unroll
        for (int i = 0; i < 4; i++) {
            uint32_t ad = sb + AHI_OFF + aOff + kByte + (uint32_t)(i * 16 * TSTRIDE * 2);
            LDMX4(ah[i][0], ah[i][1], ah[i][2], ah[i][3], ad);
        }
#pragma unroll
        for (int i = 0; i < 4; i++) {
            uint32_t ad = sb + ALO_OFF + aOff + kByte + (uint32_t)(i * 16 * TSTRIDE * 2);
            LDMX4(al[i][0], al[i][1], al[i][2], al[i][3], ad);
        }
#pragma unroll
        for (int jj = 0; jj < 2; jj++) {
            uint32_t bd = sb + BHI_OFF + bOff + kByte + (uint32_t)(jj * 16 * TSTRIDE * 2);
            uint32_t r0, r1, r2, r3;
            LDMX4(r0, r1, r2, r3, bd);
            bh[2 * jj][0] = r0; bh[2 * jj][1] = r1;
            bh[2 * jj + 1][0] = r2; bh[2 * jj + 1][1] = r3;
            bd = sb + BLO_OFF + bOff + kByte + (uint32_t)(jj * 16 * TSTRIDE * 2);
            LDMX4(r0, r1, r2, r3, bd);
            bl[2 * jj][0] = r0; bl[2 * jj][1] = r1;
            bl[2 * jj + 1][0] = r2; bl[2 * jj + 1][1] = r3;
        }
#pragma unroll
        for (int i = 0; i < 4; i++)
#pragma unroll
            for (int j = 0; j < 4; j++) MMA16816(acc[i][j], ah[i], bh[j]);
#pragma unroll
        for (int i = 0; i < 4; i++)
#pragma unroll
            for (int j = 0; j < 4; j++) MMA16816(acc[i][j], ah[i], bl[j]);
#pragma unroll
        for (int i = 0; i < 4; i++)
#pragma unroll
            for (int j = 0; j < 4; j++) MMA16816(acc[i][j], al[i], bh[j]);
    }

    // ---- epilogue: bias, store, fused BN stats ----
    float* scs = (float*)(smem + STAT_OFF);
    float* scq = scs + 128;
    int rq = lane >> 2, cq = (lane & 3) * 2;
    const float* bs = (const float*)(smem + BIAS_OFF);

    float ps[4][2], pq[4][2];
#pragma unroll
    for (int j = 0; j < 4; j++) { ps[j][0] = ps[j][1] = 0.f; pq[j][0] = pq[j][1] = 0.f; }

#pragma unroll
    for (int i = 0; i < 4; i++) {
        int r0g = rowBase + m0 + i * 16 + rq;
#pragma unroll
        for (int j = 0; j < 4; j++) {
            int cg = n0 + j * 8 + cq;
            float bx = bs[cg], by = bs[cg + 1];
            if (r0g < NN) {
                float v0 = acc[i][j][0] + bx, v1 = acc[i][j][1] + by;
                *(float2*)(Y + (size_t)r0g * DD + cg) = make_float2(v0, v1);
                ps[j][0] += v0; pq[j][0] += v0 * v0;
                ps[j][1] += v1; pq[j][1] += v1 * v1;
            }
            if (r0g + 8 < NN) {
                float v2 = acc[i][j][2] + bx, v3 = acc[i][j][3] + by;
                *(float2*)(Y + (size_t)(r0g + 8) * DD + cg) = make_float2(v2, v3);
                ps[j][0] += v2; pq[j][0] += v2 * v2;
                ps[j][1] += v3; pq[j][1] += v3 * v3;
            }
        }
    }
#pragma unroll
    for (int j = 0; j < 4; j++)
#pragma unroll
        for (int c = 0; c < 2; c++) {
#pragma unroll
            for (int m = 4; m <= 16; m <<= 1) {
                ps[j][c] += __shfl_xor_sync(0xFFFFFFFFu, ps[j][c], m);
                pq[j][c] += __shfl_xor_sync(0xFFFFFFFFu, pq[j][c], m);
            }
        }
    if (rq == 0) {
#pragma unroll
        for (int j = 0; j < 4; j++)
#pragma unroll
            for (int c = 0; c < 2; c++) {
                atomicAdd(&scs[n0 + j * 8 + cq + c], ps[j][c]);
                atomicAdd(&scq[n0 + j * 8 + cq + c], pq[j][c]);
            }
    }
    __syncthreads();
    if (tid < 128) {
        atomicAdd(&statOut[tid],       scs[tid]);
        atomicAdd(&statOut[128 + tid], scq[tid]);
    }
}

// -------- outer BN: compute g_s2/g_t2 from bank, then zero the layer's two banks -----
__global__ void bn2_k(const float* __restrict__ sIn, float* __restrict__ zeroBase,
                      const float* __restrict__ g, const float* __restrict__ b)
{
    int t = threadIdx.x;    // 256
    float sc = 0.f, sh = 0.f;
    if (t < 128) {
        float mu  = sIn[t] * (1.0f / NN);
        float var = sIn[128 + t] * (1.0f / NN) - mu * mu;
        sc = g[t] * rsqrtf(var + 1e-5f);
        sh = b[t] - mu * sc;
    }
    __syncthreads();        // all reads of the banks done before zeroing
    if (t < 128) { g_s2[t] = sc; g_t2[t] = sh; }
    zeroBase[2 * t]     = 0.f;      // zero 512 floats = banks 2l and 2l+1
    zeroBase[2 * t + 1] = 0.f;
}

// ---------------- final output: out = y2*s2+t2 (no relu, last layer) ----------------
__global__ void finalize_k(float* __restrict__ out) {
    int i = blockIdx.x * 256 + threadIdx.x;   // 6250 * 256 = NN*DD/4
    int d4 = (i * 4) & 127;
    float4 v = ((const float4*)g_y2)[i];
    float4 s = *(const float4*)(g_s2 + d4);
    float4 t = *(const float4*)(g_t2 + d4);
    v.x = fmaf(v.x, s.x, t.x);
    v.y = fmaf(v.y, s.y, t.y);
    v.z = fmaf(v.z, s.z, t.z);
    v.w = fmaf(v.w, s.w, t.w);
    ((float4*)out)[i] = v;
}

extern "C" void kernel_launch(void* const* d_in, const int* in_sizes, int n_in,
                              void* d_out, int out_size)
{
    const float* x    = (const float*)d_in[0];
    const int*   ei32 = (const int*)d_in[1];
    const float* eps  = (const float*)d_in[2];
    const float* W1   = (const float*)d_in[3];
    const float* b1   = (const float*)d_in[4];
    const float* bn1g = (const float*)d_in[5];
    const float* bn1b = (const float*)d_in[6];
    const float* W2   = (const float*)d_in[7];
    const float* b2   = (const float*)d_in[8];
    const float* bn2g = (const float*)d_in[9];
    const float* bn2b = (const float*)d_in[10];

    float *y1p, *y2p, *statsp;
    unsigned short *whip, *wlop;
    cudaGetSymbolAddress((void**)&y1p,    g_y1);
    cudaGetSymbolAddress((void**)&y2p,    g_y2);
    cudaGetSymbolAddress((void**)&statsp, g_stats);
    cudaGetSymbolAddress((void**)&whip,   g_whi);
    cudaGetSymbolAddress((void**)&wlop,   g_wlo);

    cudaFuncSetAttribute((const void*)gemm_tc_k<1, 0>, cudaFuncAttributeMaxDynamicSharedMemorySize, GEMM_SMEM);
    cudaFuncSetAttribute((const void*)gemm_tc_k<1, 1>, cudaFuncAttributeMaxDynamicSharedMemorySize, GEMM_SMEM);
    cudaFuncSetAttribute((const void*)gemm_tc_k<2, 0>, cudaFuncAttributeMaxDynamicSharedMemorySize, GEMM_SMEM);

    const int gemmBlocks = (NN + 127) / 128;   // 391

    // prep: 4 launches
    prep_k<<<384, 256>>>(W1, W2, ei32);
    count4_k<<<782, 256>>>(ei32);
    scan_k<<<1, 1024>>>();
    fill4_k<<<782, 256>>>(ei32);

    for (int l = 0; l < 3; l++) {
        float* bank1 = statsp + (size_t)(2 * l) * 256;       // gemm1 stats
        float* bank2 = statsp + (size_t)(2 * l + 1) * 256;   // gemm2 stats
        if (l == 0) {
            agg_k<0><<<6250, 256>>>(x);
            gemm_tc_k<1, 0><<<gemmBlocks, 256, GEMM_SMEM>>>(x, eps, l,
                whip + (size_t)l * 16384, wlop + (size_t)l * 16384,
                b1 + (size_t)l * DD, y1p, bank1, nullptr, nullptr, nullptr);
        } else {
            agg_k<1><<<6250, 256>>>(y2p);
            gemm_tc_k<1, 1><<<gemmBlocks, 256, GEMM_SMEM>>>(y2p, eps, l,
                whip + (size_t)l * 16384, wlop + (size_t)l * 16384,
                b1 + (size_t)l * DD, y1p, bank1, nullptr, nullptr, nullptr);
        }
        gemm_tc_k<2, 0><<<gemmBlocks, 256, GEMM_SMEM>>>(y1p, eps, l,
            whip + (size_t)(3 + l) * 16384, wlop + (size_t)(3 + l) * 16384,
            b2 + (size_t)l * DD, y2p, bank2,
            bank1, bn1g + (size_t)l * DD, bn1b + (size_t)l * DD);
        bn2_k<<<1, 256>>>(bank2, bank1 /* zeroes banks 2l & 2l+1 */,
                          bn2g + (size_t)l * DD, bn2b + (size_t)l * DD);
    }
    finalize_k<<<6250, 256>>>((float*)d_out);
}

// round 9
// speedup vs baseline: 1.2304x; 1.2304x over previous
#include <cuda_runtime.h>
#include <cuda_bf16.h>
#include <cstdint>

#define NN 50000
#define DD 128
#define EE 800000

// ---------------- scratch (static device globals: no allocation) ----------------
__device__ __align__(16) float g_agg[NN * DD];
__device__ __align__(16) float g_y1[NN * DD];
__device__ __align__(16) float g_y2[NN * DD];
__device__ __align__(16) float g_stats[512];   // sum1, sq1, sum2, sq2 (self-zeroing)
__device__ __align__(16) float g_s1[DD];
__device__ __align__(16) float g_t1[DD];
__device__ __align__(16) float g_s2[DD];
__device__ __align__(16) float g_t2[DD];
__device__ int g_is64;
__device__ __align__(16) unsigned short g_whi[6 * DD * DD];
__device__ __align__(16) unsigned short g_wlo[6 * DD * DD];
__device__ int g_deg[50176];
__device__ int g_scan[50176];
__device__ int g_off[50176];
__device__ int g_cursor[50176];
__device__ int g_bsum[64];
__device__ int g_srcs[EE];

__device__ __forceinline__ uint32_t smem_to_u32(const void* p) {
    uint32_t a;
    asm("{ .reg .u64 t; cvta.to.shared.u64 t, %1; cvt.u32.u64 %0, t; }" : "=r"(a) : "l"(p));
    return a;
}

#define LDMX4(r0, r1, r2, r3, addr) \
    asm volatile("ldmatrix.sync.aligned.m8n8.x4.shared.b16 {%0,%1,%2,%3}, [%4];" \
                 : "=r"(r0), "=r"(r1), "=r"(r2), "=r"(r3) : "r"(addr))

#define MMA16816(d, a, b) \
    asm volatile("mma.sync.aligned.m16n8k16.row.col.f32.bf16.bf16.f32 " \
                 "{%0,%1,%2,%3}, {%4,%5,%6,%7}, {%8,%9}, {%0,%1,%2,%3};" \
                 : "+f"((d)[0]), "+f"((d)[1]), "+f"((d)[2]), "+f"((d)[3]) \
                 : "r"((a)[0]), "r"((a)[1]), "r"((a)[2]), "r"((a)[3]), "r"((b)[0]), "r"((b)[1]))

// -------- prep: weight transpose+split + zero degrees + detect dtype (ONE kernel) ------
__global__ void wprep_k(const float* __restrict__ W1, const float* __restrict__ W2,
                        const int* __restrict__ ei32)
{
    int b = blockIdx.x;                      // 384 blocks
    int wi = b >> 6;
    int id = ((b & 63) << 8) + threadIdx.x;
    const float* W = (wi < 3) ? (W1 + (size_t)wi * 16384) : (W2 + (size_t)(wi - 3) * 16384);
    int k = id >> 7, n = id & 127;
    float v = W[k * 128 + n];
    __nv_bfloat16 hb = __float2bfloat16(v);
    __nv_bfloat16 lb = __float2bfloat16(v - __bfloat162float(hb));
    g_whi[(size_t)wi * 16384 + n * 128 + k] = __bfloat16_as_ushort(hb);
    g_wlo[(size_t)wi * 16384 + n * 128 + k] = __bfloat16_as_ushort(lb);

    if (b < 196) g_deg[b * 256 + threadIdx.x] = 0;

    if (b == 0 && threadIdx.x == 0) {
        int is64 = 1;
#pragma unroll
        for (int i = 0; i < 8; i++)
            if (ei32[2 * i + 1] != 0) is64 = 0;
        g_is64 = is64;
    }
}

// ================= CSR build =================
__global__ void count_k(const int* __restrict__ ei32) {   // 3125 x 256
    int e = blockIdx.x * 256 + threadIdx.x;
    if (e >= EE) return;
    int d = g_is64 ? ei32[2 * (EE + e)] : ei32[EE + e];
    atomicAdd(&g_deg[d], 1);
}
__global__ void scan1_k() {                 // 49 x 1024
    __shared__ int sm[1024];
    int t = threadIdx.x;
    int gid = blockIdx.x * 1024 + t;
    int v = (gid < NN) ? g_deg[gid] : 0;
    sm[t] = v;
    __syncthreads();
    for (int o = 1; o < 1024; o <<= 1) {
        int tv = (t >= o) ? sm[t - o] : 0;
        __syncthreads();
        sm[t] += tv;
        __syncthreads();
    }
    g_scan[gid] = sm[t] - v;
    if (t == 1023) g_bsum[blockIdx.x] = sm[1023];
}
// scan3 with inline block-prefix from g_bsum (parallel loads + tree reduce; no scan2)
__global__ void scan3_k() {                 // 49 x 1024
    __shared__ int sb[64];
    int t = threadIdx.x;
    if (t < 64) sb[t] = (t < blockIdx.x && t < 49) ? g_bsum[t] : 0;
    __syncthreads();
    if (t < 32) sb[t] += sb[t + 32];
    __syncthreads();
    if (t < 16) sb[t] += sb[t + 16];
    __syncthreads();
    if (t < 8) sb[t] += sb[t + 8];
    __syncthreads();
    if (t < 4) sb[t] += sb[t + 4];
    __syncthreads();
    if (t < 2) sb[t] += sb[t + 2];
    __syncthreads();
    if (t == 0) sb[0] += sb[1];
    __syncthreads();
    int gid = blockIdx.x * 1024 + t;
    int o = g_scan[gid] + sb[0];
    g_off[gid] = o;
    g_cursor[gid] = o;
}
__global__ void fill_k(const int* __restrict__ ei32) {    // 3125 x 256
    int e = blockIdx.x * 256 + threadIdx.x;
    if (e >= EE) return;
    int s, d;
    if (g_is64) { s = ei32[2 * e]; d = ei32[2 * (EE + e)]; }
    else        { s = ei32[e];     d = ei32[EE + e]; }
    int pos = atomicAdd(&g_cursor[d], 1);
    g_srcs[pos] = s;
}

// ------- aggregation: per-node gather + register sum; TRANS applies prev outer BN ----
template <int TRANS>
__global__ void __launch_bounds__(256) agg_k(const float* __restrict__ P) {
    int w = blockIdx.x * 8 + (threadIdx.x >> 5);  // 6250 blocks -> 50000 warps
    int lane = threadIdx.x & 31;
    int s = g_off[w], t = g_off[w + 1];
    float4 sv, tv;
    if (TRANS) {
        sv = *(const float4*)(g_s2 + lane * 4);
        tv = *(const float4*)(g_t2 + lane * 4);
    }
    float4 acc = make_float4(0.f, 0.f, 0.f, 0.f);
    int e = s;
    for (; e + 3 < t; e += 4) {
        int s0 = g_srcs[e], s1 = g_srcs[e + 1], s2i = g_srcs[e + 2], s3 = g_srcs[e + 3];
        float4 v0 = *(const float4*)(P + (size_t)s0 * DD + lane * 4);
        float4 v1 = *(const float4*)(P + (size_t)s1 * DD + lane * 4);
        float4 v2 = *(const float4*)(P + (size_t)s2i * DD + lane * 4);
        float4 v3 = *(const float4*)(P + (size_t)s3 * DD + lane * 4);
        if (TRANS) {
            v0.x = fmaf(v0.x, sv.x, tv.x); v0.y = fmaf(v0.y, sv.y, tv.y);
            v0.z = fmaf(v0.z, sv.z, tv.z); v0.w = fmaf(v0.w, sv.w, tv.w);
            v1.x = fmaf(v1.x, sv.x, tv.x); v1.y = fmaf(v1.y, sv.y, tv.y);
            v1.z = fmaf(v1.z, sv.z, tv.z); v1.w = fmaf(v1.w, sv.w, tv.w);
            v2.x = fmaf(v2.x, sv.x, tv.x); v2.y = fmaf(v2.y, sv.y, tv.y);
            v2.z = fmaf(v2.z, sv.z, tv.z); v2.w = fmaf(v2.w, sv.w, tv.w);
            v3.x = fmaf(v3.x, sv.x, tv.x); v3.y = fmaf(v3.y, sv.y, tv.y);
            v3.z = fmaf(v3.z, sv.z, tv.z); v3.w = fmaf(v3.w, sv.w, tv.w);
        }
        acc.x += fmaxf(v0.x, 0.f) + fmaxf(v1.x, 0.f) + fmaxf(v2.x, 0.f) + fmaxf(v3.x, 0.f);
        acc.y += fmaxf(v0.y, 0.f) + fmaxf(v1.y, 0.f) + fmaxf(v2.y, 0.f) + fmaxf(v3.y, 0.f);
        acc.z += fmaxf(v0.z, 0.f) + fmaxf(v1.z, 0.f) + fmaxf(v2.z, 0.f) + fmaxf(v3.z, 0.f);
        acc.w += fmaxf(v0.w, 0.f) + fmaxf(v1.w, 0.f) + fmaxf(v2.w, 0.f) + fmaxf(v3.w, 0.f);
    }
    for (; e < t; e++) {
        int s0 = g_srcs[e];
        float4 v0 = *(const float4*)(P + (size_t)s0 * DD + lane * 4);
        if (TRANS) {
            v0.x = fmaf(v0.x, sv.x, tv.x); v0.y = fmaf(v0.y, sv.y, tv.y);
            v0.z = fmaf(v0.z, sv.z, tv.z); v0.w = fmaf(v0.w, sv.w, tv.w);
        }
        acc.x += fmaxf(v0.x, 0.f);
        acc.y += fmaxf(v0.y, 0.f);
        acc.z += fmaxf(v0.z, 0.f);
        acc.w += fmaxf(v0.w, 0.f);
    }
    *(float4*)(g_agg + (size_t)w * DD + lane * 4) = acc;
}

// ---------------- HMMA GEMM (128x128x128, bf16-split, fused BN-stats epilogue) ----
#define TSTRIDE 136
#define TBYTES  (128 * TSTRIDE * 2)
#define BIAS_OFF 0
#define AHI_OFF  1024
#define ALO_OFF  (AHI_OFF + TBYTES)
#define BHI_OFF  (ALO_OFF + TBYTES)
#define BLO_OFF  (BHI_OFF + TBYTES)
#define STAT_OFF (BLO_OFF + TBYTES)
#define GEMM_SMEM (STAT_OFF + 1024)

template <int MODE, int TRANS>
__global__ void __launch_bounds__(256, 1) gemm_tc_k(
    const float* __restrict__ A0, const float* __restrict__ epsp, int layer,
    const unsigned short* __restrict__ whi, const unsigned short* __restrict__ wlo,
    const float* __restrict__ bias, float* __restrict__ Y,
    float* __restrict__ colsum, float* __restrict__ colsq)
{
    extern __shared__ __align__(16) char smem[];
    uint32_t sb = smem_to_u32(smem);
    int tid = threadIdx.x;
    int wid = tid >> 5, lane = tid & 31;
    int rowBase = blockIdx.x * 128;

    if (tid < 128) *(float*)(smem + BIAS_OFF + tid * 4) = bias[tid];
    ((float*)(smem + STAT_OFF))[tid] = 0.f;

    // ---- B tiles ----
    {
        const uint4* sh = (const uint4*)whi;
        const uint4* sl = (const uint4*)wlo;
#pragma unroll
        for (int i = 0; i < 8; i++) {
            int id = i * 256 + tid;
            int r = id >> 4, c16 = id & 15;
            uint32_t dst = (uint32_t)(r * (TSTRIDE * 2) + c16 * 16);
            *(uint4*)(smem + BHI_OFF + dst) = sh[id];
            *(uint4*)(smem + BLO_OFF + dst) = sl[id];
        }
    }

    // ---- A tile: fused transform + bf16 split ----
    float epsv = (MODE == 1) ? (1.0f + epsp[layer]) : 0.0f;
#pragma unroll
    for (int it = 0; it < 8; it++) {
        int id = it * 256 + tid;
        int row = id >> 4;
        int col = (id & 15) * 8;
        int gr = rowBase + row;
        float v[8];
#pragma unroll
        for (int j = 0; j < 8; j++) v[j] = 0.f;
        if (gr < NN) {
            float4 p0 = *(const float4*)(A0 + (size_t)gr * DD + col);
            float4 p1 = *(const float4*)(A0 + (size_t)gr * DD + col + 4);
            v[0] = p0.x; v[1] = p0.y; v[2] = p0.z; v[3] = p0.w;
            v[4] = p1.x; v[5] = p1.y; v[6] = p1.z; v[7] = p1.w;
            if (MODE == 1) {
                if (TRANS) {
#pragma unroll
                    for (int j = 0; j < 8; j++)
                        v[j] = fmaxf(fmaf(v[j], g_s2[col + j], g_t2[col + j]), 0.f);
                }
                float4 a0 = *(const float4*)(g_agg + (size_t)gr * DD + col);
                float4 a1 = *(const float4*)(g_agg + (size_t)gr * DD + col + 4);
                v[0] = fmaf(epsv, v[0], a0.x); v[1] = fmaf(epsv, v[1], a0.y);
                v[2] = fmaf(epsv, v[2], a0.z); v[3] = fmaf(epsv, v[3], a0.w);
                v[4] = fmaf(epsv, v[4], a1.x); v[5] = fmaf(epsv, v[5], a1.y);
                v[6] = fmaf(epsv, v[6], a1.z); v[7] = fmaf(epsv, v[7], a1.w);
            } else {
#pragma unroll
                for (int j = 0; j < 8; j++)
                    v[j] = fmaxf(fmaf(v[j], g_s1[col + j], g_t1[col + j]), 0.f);
            }
        }
        uint32_t h[4], l[4];
#pragma unroll
        for (int j = 0; j < 4; j++) {
            __nv_bfloat16 h0 = __float2bfloat16(v[2 * j]);
            __nv_bfloat16 h1 = __float2bfloat16(v[2 * j + 1]);
            __nv_bfloat16 l0 = __float2bfloat16(v[2 * j] - __bfloat162float(h0));
            __nv_bfloat16 l1 = __float2bfloat16(v[2 * j + 1] - __bfloat162float(h1));
            h[j] = ((uint32_t)__bfloat16_as_ushort(h1) << 16) | __bfloat16_as_ushort(h0);
            l[j] = ((uint32_t)__bfloat16_as_ushort(l1) << 16) | __bfloat16_as_ushort(l0);
        }
        uint32_t off = (uint32_t)(row * (TSTRIDE * 2) + col * 2);
        *(uint4*)(smem + AHI_OFF + off) = make_uint4(h[0], h[1], h[2], h[3]);
        *(uint4*)(smem + ALO_OFF + off) = make_uint4(l[0], l[1], l[2], l[3]);
    }
    __syncthreads();

    // ---- warp MMA mainloop ----
    int wm = wid & 1, wn = wid >> 1;
    int m0 = wm * 64, n0 = wn * 32;

    float acc[4][4][4];
#pragma unroll
    for (int i = 0; i < 4; i++)
#pragma unroll
        for (int j = 0; j < 4; j++)
#pragma unroll
            for (int q = 0; q < 4; q++) acc[i][j][q] = 0.f;

    uint32_t aOff = (uint32_t)((m0 + (lane & 15)) * (TSTRIDE * 2) + (lane >> 4) * 16);
    uint32_t bOff = (uint32_t)((n0 + (lane & 7) + (lane >> 4) * 8) * (TSTRIDE * 2) + ((lane >> 3) & 1) * 16);

#pragma unroll
    for (int ks = 0; ks < 8; ks++) {
        uint32_t kByte = (uint32_t)(ks * 32);
        uint32_t ah[4][4], al[4][4], bh[4][2], bl[4][2];
#pragma unroll
        for (int i = 0; i < 4; i++) {
            uint32_t ad = sb + AHI_OFF + aOff + kByte + (uint32_t)(i * 16 * TSTRIDE * 2);
            LDMX4(ah[i][0], ah[i][1], ah[i][2], ah[i][3], ad);
        }
#pragma unroll
        for (int i = 0; i < 4; i++) {
            uint32_t ad = sb + ALO_OFF + aOff + kByte + (uint32_t)(i * 16 * TSTRIDE * 2);
            LDMX4(al[i][0], al[i][1], al[i][2], al[i][3], ad);
        }
#pragma unroll
        for (int jj = 0; jj < 2; jj++) {
            uint32_t bd = sb + BHI_OFF + bOff + kByte + (uint32_t)(jj * 16 * TSTRIDE * 2);
            uint32_t r0, r1, r2, r3;
            LDMX4(r0, r1, r2, r3, bd);
            bh[2 * jj][0] = r0; bh[2 * jj][1] = r1;
            bh[2 * jj + 1][0] = r2; bh[2 * jj + 1][1] = r3;
            bd = sb + BLO_OFF + bOff + kByte + (uint32_t)(jj * 16 * TSTRIDE * 2);
            LDMX4(r0, r1, r2, r3, bd);
            bl[2 * jj][0] = r0; bl[2 * jj][1] = r1;
            bl[2 * jj + 1][0] = r2; bl[2 * jj + 1][1] = r3;
        }
#pragma unroll
        for (int i = 0; i < 4; i++)
#pragma unroll
            for (int j = 0; j < 4; j++) MMA16816(acc[i][j], ah[i], bh[j]);
#pragma unroll
        for (int i = 0; i < 4; i++)
#pragma unroll
            for (int j = 0; j < 4; j++) MMA16816(acc[i][j], ah[i], bl[j]);
#pragma unroll
        for (int i = 0; i < 4; i++)
#pragma unroll
            for (int j = 0; j < 4; j++) MMA16816(acc[i][j], al[i], bh[j]);
    }

    // ---- epilogue: bias, store, fused BN stats ----
    float* scs = (float*)(smem + STAT_OFF);
    float* scq = scs + 128;
    int rq = lane >> 2, cq = (lane & 3) * 2;
    const float* bs = (const float*)(smem + BIAS_OFF);

    float ps[4][2], pq[4][2];
#pragma unroll
    for (int j = 0; j < 4; j++) { ps[j][0] = ps[j][1] = 0.f; pq[j][0] = pq[j][1] = 0.f; }

#pragma unroll
    for (int i = 0; i < 4; i++) {
        int r0g = rowBase + m0 + i * 16 + rq;
#pragma unroll
        for (int j = 0; j < 4; j++) {
            int cg = n0 + j * 8 + cq;
            float bx = bs[cg], by = bs[cg + 1];
            if (r0g < NN) {
                float v0 = acc[i][j][0] + bx, v1 = acc[i][j][1] + by;
                *(float2*)(Y + (size_t)r0g * DD + cg) = make_float2(v0, v1);
                ps[j][0] += v0; pq[j][0] += v0 * v0;
                ps[j][1] += v1; pq[j][1] += v1 * v1;
            }
            if (r0g + 8 < NN) {
                float v2 = acc[i][j][2] + bx, v3 = acc[i][j][3] + by;
                *(float2*)(Y + (size_t)(r0g + 8) * DD + cg) = make_float2(v2, v3);
                ps[j][0] += v2; pq[j][0] += v2 * v2;
                ps[j][1] += v3; pq[j][1] += v3 * v3;
            }
        }
    }
#pragma unroll
    for (int j = 0; j < 4; j++)
#pragma unroll
        for (int c = 0; c < 2; c++) {
#pragma unroll
            for (int m = 4; m <= 16; m <<= 1) {
                ps[j][c] += __shfl_xor_sync(0xFFFFFFFFu, ps[j][c], m);
                pq[j][c] += __shfl_xor_sync(0xFFFFFFFFu, pq[j][c], m);
            }
        }
    if (rq == 0) {
#pragma unroll
        for (int j = 0; j < 4; j++)
#pragma unroll
            for (int c = 0; c < 2; c++) {
                atomicAdd(&scs[n0 + j * 8 + cq + c], ps[j][c]);
                atomicAdd(&scq[n0 + j * 8 + cq + c], pq[j][c]);
            }
    }
    __syncthreads();
    if (tid < 128) {
        atomicAdd(&colsum[tid], scs[tid]);
        atomicAdd(&colsq[tid],  scq[tid]);
    }
}

// ---------------- BN scale/shift (reads stats bank, then zeroes it) ----------------
__global__ void bn_stats_k(float* __restrict__ cs, float* __restrict__ cq,
                           const float* __restrict__ g, const float* __restrict__ b,
                           float* __restrict__ sOut, float* __restrict__ tOut)
{
    int d = threadIdx.x;
    float su = cs[d], sq = cq[d];
    float mu  = su * (1.0f / NN);
    float var = sq * (1.0f / NN) - mu * mu;
    float sc  = g[d] * rsqrtf(var + 1e-5f);
    sOut[d] = sc;
    tOut[d] = b[d] - mu * sc;
    cs[d] = 0.f;
    cq[d] = 0.f;
}

// ---------------- final output: out = y2*s2+t2 ----------------
__global__ void finalize_k(float* __restrict__ out) {
    int i = blockIdx.x * 256 + threadIdx.x;
    int d4 = (i * 4) & 127;
    float4 v = ((const float4*)g_y2)[i];
    float4 s = *(const float4*)(g_s2 + d4);
    float4 t = *(const float4*)(g_t2 + d4);
    v.x = fmaf(v.x, s.x, t.x);
    v.y = fmaf(v.y, s.y, t.y);
    v.z = fmaf(v.z, s.z, t.z);
    v.w = fmaf(v.w, s.w, t.w);
    ((float4*)out)[i] = v;
}

extern "C" void kernel_launch(void* const* d_in, const int* in_sizes, int n_in,
                              void* d_out, int out_size)
{
    const float* x    = (const float*)d_in[0];
    const int*   ei32 = (const int*)d_in[1];
    const float* eps  = (const float*)d_in[2];
    const float* W1   = (const float*)d_in[3];
    const float* b1   = (const float*)d_in[4];
    const float* bn1g = (const float*)d_in[5];
    const float* bn1b = (const float*)d_in[6];
    const float* W2   = (const float*)d_in[7];
    const float* b2   = (const float*)d_in[8];
    const float* bn2g = (const float*)d_in[9];
    const float* bn2b = (const float*)d_in[10];

    float *y1p, *y2p, *statsp, *s1p, *t1p, *s2p, *t2p;
    unsigned short *whip, *wlop;
    cudaGetSymbolAddress((void**)&y1p,    g_y1);
    cudaGetSymbolAddress((void**)&y2p,    g_y2);
    cudaGetSymbolAddress((void**)&statsp, g_stats);
    cudaGetSymbolAddress((void**)&s1p,    g_s1);
    cudaGetSymbolAddress((void**)&t1p,    g_t1);
    cudaGetSymbolAddress((void**)&s2p,    g_s2);
    cudaGetSymbolAddress((void**)&t2p,    g_t2);
    cudaGetSymbolAddress((void**)&whip,   g_whi);
    cudaGetSymbolAddress((void**)&wlop,   g_wlo);

    cudaFuncSetAttribute((const void*)gemm_tc_k<1, 0>, cudaFuncAttributeMaxDynamicSharedMemorySize, GEMM_SMEM);
    cudaFuncSetAttribute((const void*)gemm_tc_k<1, 1>, cudaFuncAttributeMaxDynamicSharedMemorySize, GEMM_SMEM);
    cudaFuncSetAttribute((const void*)gemm_tc_k<2, 0>, cudaFuncAttributeMaxDynamicSharedMemorySize, GEMM_SMEM);

    const int gemmBlocks = (NN + 127) / 128;   // 391

    // one-time prep (6 launches)
    wprep_k<<<384, 256>>>(W1, W2, ei32);
    count_k<<<3125, 256>>>(ei32);
    scan1_k<<<49, 1024>>>();
    scan3_k<<<49, 1024>>>();
    fill_k<<<3125, 256>>>(ei32);

    for (int l = 0; l < 3; l++) {
        if (l == 0) {
            agg_k<0><<<6250, 256>>>(x);
            gemm_tc_k<1, 0><<<gemmBlocks, 256, GEMM_SMEM>>>(x, eps, l,
                whip + (size_t)l * 16384, wlop + (size_t)l * 16384,
                b1 + (size_t)l * DD, y1p, statsp, statsp + 128);
        } else {
            agg_k<1><<<6250, 256>>>(y2p);
            gemm_tc_k<1, 1><<<gemmBlocks, 256, GEMM_SMEM>>>(y2p, eps, l,
                whip + (size_t)l * 16384, wlop + (size_t)l * 16384,
                b1 + (size_t)l * DD, y1p, statsp, statsp + 128);
        }
        bn_stats_k<<<1, 128>>>(statsp, statsp + 128,
                               bn1g + (size_t)l * DD, bn1b + (size_t)l * DD, s1p, t1p);
        gemm_tc_k<2, 0><<<gemmBlocks, 256, GEMM_SMEM>>>(y1p, eps, l,
            whip + (size_t)(3 + l) * 16384, wlop + (size_t)(3 + l) * 16384,
            b2 + (size_t)l * DD, y2p, statsp + 256, statsp + 384);
        bn_stats_k<<<1, 128>>>(statsp + 256, statsp + 384,
                               bn2g + (size_t)l * DD, bn2b + (size_t)l * DD, s2p, t2p);
    }
    finalize_k<<<6250, 256>>>((float*)d_out);
}

// round 11
// speedup vs baseline: 1.2705x; 1.0326x over previous
#include <cuda_runtime.h>
#include <cuda_bf16.h>
#include <cuda_fp16.h>
#include <cstdint>

#define NN 50000
#define DD 128
#define EE 800000

// ---------------- scratch (static device globals: no allocation) ----------------
__device__ __align__(16) float g_agg[NN * DD];
__device__ __align__(16) float g_y1[NN * DD];
__device__ __align__(16) float g_y2[NN * DD];
__device__ __align__(16) unsigned short g_hf[NN * DD];   // fp16 gather image
__device__ __align__(16) float g_stats[512];   // sum1, sq1, sum2, sq2 (self-zeroing)
__device__ __align__(16) float g_s1[DD];
__device__ __align__(16) float g_t1[DD];
__device__ __align__(16) float g_s2[DD];
__device__ __align__(16) float g_t2[DD];
__device__ int g_is64;
__device__ __align__(16) unsigned short g_whi[6 * DD * DD];
__device__ __align__(16) unsigned short g_wlo[6 * DD * DD];
__device__ int g_deg[50176];
__device__ int g_scan[50176];
__device__ int g_off[50176];
__device__ int g_cursor[50176];
__device__ int g_bsum[64];
__device__ int g_srcs[EE];

__device__ __forceinline__ uint32_t smem_to_u32(const void* p) {
    uint32_t a;
    asm("{ .reg .u64 t; cvta.to.shared.u64 t, %1; cvt.u32.u64 %0, t; }" : "=r"(a) : "l"(p));
    return a;
}

#define LDMX4(r0, r1, r2, r3, addr) \
    asm volatile("ldmatrix.sync.aligned.m8n8.x4.shared.b16 {%0,%1,%2,%3}, [%4];" \
                 : "=r"(r0), "=r"(r1), "=r"(r2), "=r"(r3) : "r"(addr))

#define MMA16816(d, a, b) \
    asm volatile("mma.sync.aligned.m16n8k16.row.col.f32.bf16.bf16.f32 " \
                 "{%0,%1,%2,%3}, {%4,%5,%6,%7}, {%8,%9}, {%0,%1,%2,%3};" \
                 : "+f"((d)[0]), "+f"((d)[1]), "+f"((d)[2]), "+f"((d)[3]) \
                 : "r"((a)[0]), "r"((a)[1]), "r"((a)[2]), "r"((a)[3]), "r"((b)[0]), "r"((b)[1]))

// -------- prep: weight transpose+split + zero degrees + detect dtype (ONE kernel) ------
__global__ void wprep_k(const float* __restrict__ W1, const float* __restrict__ W2,
                        const int* __restrict__ ei32)
{
    int b = blockIdx.x;                      // 384 blocks
    int wi = b >> 6;
    int id = ((b & 63) << 8) + threadIdx.x;
    const float* W = (wi < 3) ? (W1 + (size_t)wi * 16384) : (W2 + (size_t)(wi - 3) * 16384);
    int k = id >> 7, n = id & 127;
    float v = W[k * 128 + n];
    __nv_bfloat16 hb = __float2bfloat16(v);
    __nv_bfloat16 lb = __float2bfloat16(v - __bfloat162float(hb));
    g_whi[(size_t)wi * 16384 + n * 128 + k] = __bfloat16_as_ushort(hb);
    g_wlo[(size_t)wi * 16384 + n * 128 + k] = __bfloat16_as_ushort(lb);

    if (b < 196) g_deg[b * 256 + threadIdx.x] = 0;

    if (b == 0 && threadIdx.x == 0) {
        int is64 = 1;
#pragma unroll
        for (int i = 0; i < 8; i++)
            if (ei32[2 * i + 1] != 0) is64 = 0;
        g_is64 = is64;
    }
}

// ================= CSR build =================
__global__ void count_k(const int* __restrict__ ei32) {   // 3125 x 256
    int e = blockIdx.x * 256 + threadIdx.x;
    if (e >= EE) return;
    int d = g_is64 ? ei32[2 * (EE + e)] : ei32[EE + e];
    atomicAdd(&g_deg[d], 1);
}
__global__ void scan1_k() {                 // 49 x 1024
    __shared__ int sm[1024];
    int t = threadIdx.x;
    int gid = blockIdx.x * 1024 + t;
    int v = (gid < NN) ? g_deg[gid] : 0;
    sm[t] = v;
    __syncthreads();
    for (int o = 1; o < 1024; o <<= 1) {
        int tv = (t >= o) ? sm[t - o] : 0;
        __syncthreads();
        sm[t] += tv;
        __syncthreads();
    }
    g_scan[gid] = sm[t] - v;
    if (t == 1023) g_bsum[blockIdx.x] = sm[1023];
}
__global__ void scan3_k() {                 // 49 x 1024; block prefix from g_bsum inline
    __shared__ int sb[64];
    int t = threadIdx.x;
    if (t < 64) sb[t] = (t < blockIdx.x && t < 49) ? g_bsum[t] : 0;
    __syncthreads();
    if (t < 32) sb[t] += sb[t + 32];
    __syncthreads();
    if (t < 16) sb[t] += sb[t + 16];
    __syncthreads();
    if (t < 8) sb[t] += sb[t + 8];
    __syncthreads();
    if (t < 4) sb[t] += sb[t + 4];
    __syncthreads();
    if (t < 2) sb[t] += sb[t + 2];
    __syncthreads();
    if (t == 0) sb[0] += sb[1];
    __syncthreads();
    int gid = blockIdx.x * 1024 + t;
    int o = g_scan[gid] + sb[0];
    g_off[gid] = o;
    g_cursor[gid] = o;
}
__global__ void fill_k(const int* __restrict__ ei32) {    // 3125 x 256
    int e = blockIdx.x * 256 + threadIdx.x;
    if (e >= EE) return;
    int s, d;
    if (g_is64) { s = ei32[2 * e]; d = ei32[2 * (EE + e)]; }
    else        { s = ei32[e];     d = ei32[EE + e]; }
    int pos = atomicAdd(&g_cursor[d], 1);
    g_srcs[pos] = s;
}

// --------- quantize features to fp16 gather image ---------
// TRANS=0: g_hf = x (raw; agg applies relu)
// TRANS=1: g_hf = relu(y2*s2 + t2)  == h for l>0 (message AND own)
template <int TRANS>
__global__ void q_k(const float* __restrict__ P) {        // 3125 x 256, 8 elems/thread
    int base = (blockIdx.x * 256 + threadIdx.x) * 8;
    int col = base & 127;
    float4 p0 = *(const float4*)(P + base);
    float4 p1 = *(const float4*)(P + base + 4);
    float v[8] = {p0.x, p0.y, p0.z, p0.w, p1.x, p1.y, p1.z, p1.w};
    if (TRANS) {
        float4 s0 = *(const float4*)(g_s2 + col);
        float4 s1 = *(const float4*)(g_s2 + col + 4);
        float4 t0 = *(const float4*)(g_t2 + col);
        float4 t1 = *(const float4*)(g_t2 + col + 4);
        v[0] = fmaxf(fmaf(v[0], s0.x, t0.x), 0.f);
        v[1] = fmaxf(fmaf(v[1], s0.y, t0.y), 0.f);
        v[2] = fmaxf(fmaf(v[2], s0.z, t0.z), 0.f);
        v[3] = fmaxf(fmaf(v[3], s0.w, t0.w), 0.f);
        v[4] = fmaxf(fmaf(v[4], s1.x, t1.x), 0.f);
        v[5] = fmaxf(fmaf(v[5], s1.y, t1.y), 0.f);
        v[6] = fmaxf(fmaf(v[6], s1.z, t1.z), 0.f);
        v[7] = fmaxf(fmaf(v[7], s1.w, t1.w), 0.f);
    }
    unsigned short o[8];
#pragma unroll
    for (int j = 0; j < 8; j++) o[j] = __half_as_ushort(__float2half_rn(v[j]));
    uint32_t w0 = (uint32_t)o[0] | ((uint32_t)o[1] << 16);
    uint32_t w1 = (uint32_t)o[2] | ((uint32_t)o[3] << 16);
    uint32_t w2 = (uint32_t)o[4] | ((uint32_t)o[5] << 16);
    uint32_t w3 = (uint32_t)o[6] | ((uint32_t)o[7] << 16);
    *(uint4*)(g_hf + base) = make_uint4(w0, w1, w2, w3);
}

// ------- aggregation: fp16 gather + fp32 register sum (relu on the fly) ----
// lane owns 4 halves (lane*4 .. lane*4+3); warp covers exactly one 128-col row
__device__ __forceinline__ void add4(float* acc, uint2 q) {
    float2 f0 = __half22float2(*(__half2*)&q.x);
    float2 f1 = __half22float2(*(__half2*)&q.y);
    acc[0] += fmaxf(f0.x, 0.f);
    acc[1] += fmaxf(f0.y, 0.f);
    acc[2] += fmaxf(f1.x, 0.f);
    acc[3] += fmaxf(f1.y, 0.f);
}
__global__ void __launch_bounds__(256) agg_k() {
    int w = blockIdx.x * 8 + (threadIdx.x >> 5);  // 6250 blocks -> 50000 warps
    int lane = threadIdx.x & 31;
    int s = g_off[w], t = g_off[w + 1];
    const unsigned short* H = g_hf;
    int lc = lane * 4;                            // 4 halves per lane (32*4 = 128)
    float acc[4] = {0.f, 0.f, 0.f, 0.f};
    int e = s;
    for (; e + 3 < t; e += 4) {
        int s0 = g_srcs[e], s1 = g_srcs[e + 1], s2i = g_srcs[e + 2], s3 = g_srcs[e + 3];
        uint2 q0 = *(const uint2*)(H + (size_t)s0 * DD + lc);
        uint2 q1 = *(const uint2*)(H + (size_t)s1 * DD + lc);
        uint2 q2 = *(const uint2*)(H + (size_t)s2i * DD + lc);
        uint2 q3 = *(const uint2*)(H + (size_t)s3 * DD + lc);
        add4(acc, q0); add4(acc, q1); add4(acc, q2); add4(acc, q3);
    }
    for (; e < t; e++) {
        int s0 = g_srcs[e];
        uint2 q0 = *(const uint2*)(H + (size_t)s0 * DD + lc);
        add4(acc, q0);
    }
    *(float4*)(g_agg + (size_t)w * DD + lc) = make_float4(acc[0], acc[1], acc[2], acc[3]);
}

// ---------------- HMMA GEMM (128x128x128, bf16-split, fused BN-stats epilogue) ----
// MODE 1: A = (1+eps)*own + agg ; own = A0 fp32 (TRANS=0) or g_hf fp16 (TRANS=1)
// MODE 2: A = relu(y1*s1+t1)
#define TSTRIDE 136
#define TBYTES  (128 * TSTRIDE * 2)
#define BIAS_OFF 0
#define AHI_OFF  1024
#define ALO_OFF  (AHI_OFF + TBYTES)
#define BHI_OFF  (ALO_OFF + TBYTES)
#define BLO_OFF  (BHI_OFF + TBYTES)
#define STAT_OFF (BLO_OFF + TBYTES)
#define GEMM_SMEM (STAT_OFF + 1024)

template <int MODE, int TRANS>
__global__ void __launch_bounds__(256, 1) gemm_tc_k(
    const float* __restrict__ A0, const float* __restrict__ epsp, int layer,
    const unsigned short* __restrict__ whi, const unsigned short* __restrict__ wlo,
    const float* __restrict__ bias, float* __restrict__ Y,
    float* __restrict__ colsum, float* __restrict__ colsq)
{
    extern __shared__ __align__(16) char smem[];
    uint32_t sb = smem_to_u32(smem);
    int tid = threadIdx.x;
    int wid = tid >> 5, lane = tid & 31;
    int rowBase = blockIdx.x * 128;

    if (tid < 128) *(float*)(smem + BIAS_OFF + tid * 4) = bias[tid];
    ((float*)(smem + STAT_OFF))[tid] = 0.f;

    // ---- B tiles ----
    {
        const uint4* sh = (const uint4*)whi;
        const uint4* sl = (const uint4*)wlo;
#pragma unroll
        for (int i = 0; i < 8; i++) {
            int id = i * 256 + tid;
            int r = id >> 4, c16 = id & 15;
            uint32_t dst = (uint32_t)(r * (TSTRIDE * 2) + c16 * 16);
            *(uint4*)(smem + BHI_OFF + dst) = sh[id];
            *(uint4*)(smem + BLO_OFF + dst) = sl[id];
        }
    }

    // ---- A tile: fused transform + bf16 split ----
    float epsv = (MODE == 1) ? (1.0f + epsp[layer]) : 0.0f;
#pragma unroll
    for (int it = 0; it < 8; it++) {
        int id = it * 256 + tid;
        int row = id >> 4;
        int col = (id & 15) * 8;
        int gr = rowBase + row;
        float v[8];
#pragma unroll
        for (int j = 0; j < 8; j++) v[j] = 0.f;
        if (gr < NN) {
            if (MODE == 1) {
                float own[8];
                if (TRANS) {
                    uint4 q = *(const uint4*)(g_hf + (size_t)gr * DD + col);
                    __half2* hp = (__half2*)&q;
#pragma unroll
                    for (int j = 0; j < 4; j++) {
                        float2 f = __half22float2(hp[j]);
                        own[2 * j] = f.x;
                        own[2 * j + 1] = f.y;
                    }
                } else {
                    float4 p0 = *(const float4*)(A0 + (size_t)gr * DD + col);
                    float4 p1 = *(const float4*)(A0 + (size_t)gr * DD + col + 4);
                    own[0] = p0.x; own[1] = p0.y; own[2] = p0.z; own[3] = p0.w;
                    own[4] = p1.x; own[5] = p1.y; own[6] = p1.z; own[7] = p1.w;
                }
                float4 a0 = *(const float4*)(g_agg + (size_t)gr * DD + col);
                float4 a1 = *(const float4*)(g_agg + (size_t)gr * DD + col + 4);
                v[0] = fmaf(epsv, own[0], a0.x); v[1] = fmaf(epsv, own[1], a0.y);
                v[2] = fmaf(epsv, own[2], a0.z); v[3] = fmaf(epsv, own[3], a0.w);
                v[4] = fmaf(epsv, own[4], a1.x); v[5] = fmaf(epsv, own[5], a1.y);
                v[6] = fmaf(epsv, own[6], a1.z); v[7] = fmaf(epsv, own[7], a1.w);
            } else {
                float4 p0 = *(const float4*)(A0 + (size_t)gr * DD + col);
                float4 p1 = *(const float4*)(A0 + (size_t)gr * DD + col + 4);
                v[0] = p0.x; v[1] = p0.y; v[2] = p0.z; v[3] = p0.w;
                v[4] = p1.x; v[5] = p1.y; v[6] = p1.z; v[7] = p1.w;
#pragma unroll
                for (int j = 0; j < 8; j++)
                    v[j] = fmaxf(fmaf(v[j], g_s1[col + j], g_t1[col + j]), 0.f);
            }
        }
        uint32_t h[4], l[4];
#pragma unroll
        for (int j = 0; j < 4; j++) {
            __nv_bfloat16 h0 = __float2bfloat16(v[2 * j]);
            __nv_bfloat16 h1 = __float2bfloat16(v[2 * j + 1]);
            __nv_bfloat16 l0 = __float2bfloat16(v[2 * j] - __bfloat162float(h0));
            __nv_bfloat16 l1 = __float2bfloat16(v[2 * j + 1] - __bfloat162float(h1));
            h[j] = ((uint32_t)__bfloat16_as_ushort(h1) << 16) | __bfloat16_as_ushort(h0);
            l[j] = ((uint32_t)__bfloat16_as_ushort(l1) << 16) | __bfloat16_as_ushort(l0);
        }
        uint32_t off = (uint32_t)(row * (TSTRIDE * 2) + col * 2);
        *(uint4*)(smem + AHI_OFF + off) = make_uint4(h[0], h[1], h[2], h[3]);
        *(uint4*)(smem + ALO_OFF + off) = make_uint4(l[0], l[1], l[2], l[3]);
    }
    __syncthreads();

    // ---- warp MMA mainloop ----
    int wm = wid & 1, wn = wid >> 1;
    int m0 = wm * 64, n0 = wn * 32;

    float acc[4][4][4];
#pragma unroll
    for (int i = 0; i < 4; i++)
#pragma unroll
        for (int j = 0; j < 4; j++)
#pragma unroll
            for (int q = 0; q < 4; q++) acc[i][j][q] = 0.f;

    uint32_t aOff = (uint32_t)((m0 + (lane & 15)) * (TSTRIDE * 2) + (lane >> 4) * 16);
    uint32_t bOff = (uint32_t)((n0 + (lane & 7) + (lane >> 4) * 8) * (TSTRIDE * 2) + ((lane >> 3) & 1) * 16);

#pragma unroll
    for (int ks = 0; ks < 8; ks++) {
        uint32_t kByte = (uint32_t)(ks * 32);
        uint32_t ah[4][4], al[4][4], bh[4][2], bl[4][2];
#pragma unroll
        for (int i = 0; i < 4; i++) {
            uint32_t ad = sb + AHI_OFF + aOff + kByte + (uint32_t)(i * 16 * TSTRIDE * 2);
            LDMX4(ah[i][0], ah[i][1], ah[i][2], ah[i][3], ad);
        }
#pragma unroll
        for (int i = 0; i < 4; i++) {
            uint32_t ad = sb + ALO_OFF + aOff + kByte + (uint32_t)(i * 16 * TSTRIDE * 2);
            LDMX4(al[i][0], al[i][1], al[i][2], al[i][3], ad);
        }
#pragma unroll
        for (int jj = 0; jj < 2; jj++) {
            uint32_t bd = sb + BHI_OFF + bOff + kByte + (uint32_t)(jj * 16 * TSTRIDE * 2);
            uint32_t r0, r1, r2, r3;
            LDMX4(r0, r1, r2, r3, bd);
            bh[2 * jj][0] = r0; bh[2 * jj][1] = r1;
            bh[2 * jj + 1][0] = r2; bh[2 * jj + 1][1] = r3;
            bd = sb + BLO_OFF + bOff + kByte + (uint32_t)(jj * 16 * TSTRIDE * 2);
            LDMX4(r0, r1, r2, r3, bd);
            bl[2 * jj][0] = r0; bl[2 * jj][1] = r1;
            bl[2 * jj + 1][0] = r2; bl[2 * jj + 1][1] = r3;
        }
#pragma unroll
        for (int i = 0; i < 4; i++)
#pragma unroll
            for (int j = 0; j < 4; j++) MMA16816(acc[i][j], ah[i], bh[j]);
#pragma unroll
        for (int i = 0; i < 4; i++)
#pragma unroll
            for (int j = 0; j < 4; j++) MMA16816(acc[i][j], ah[i], bl[j]);
#pragma unroll
        for (int i = 0; i < 4; i++)
#pragma unroll
            for (int j = 0; j < 4; j++) MMA16816(acc[i][j], al[i], bh[j]);
    }

    // ---- epilogue: bias, store, fused BN stats ----
    float* scs = (float*)(smem + STAT_OFF);
    float* scq = scs + 128;
    int rq = lane >> 2, cq = (lane & 3) * 2;
    const float* bs = (const float*)(smem + BIAS_OFF);

    float ps[4][2], pq[4][2];
#pragma unroll
    for (int j = 0; j < 4; j++) { ps[j][0] = ps[j][1] = 0.f; pq[j][0] = pq[j][1] = 0.f; }

#pragma unroll
    for (int i = 0; i < 4; i++) {
        int r0g = rowBase + m0 + i * 16 + rq;
#pragma unroll
        for (int j = 0; j < 4; j++) {
            int cg = n0 + j * 8 + cq;
            float bx = bs[cg], by = bs[cg + 1];
            if (r0g < NN) {
                float v0 = acc[i][j][0] + bx, v1 = acc[i][j][1] + by;
                *(float2*)(Y + (size_t)r0g * DD + cg) = make_float2(v0, v1);
                ps[j][0] += v0; pq[j][0] += v0 * v0;
                ps[j][1] += v1; pq[j][1] += v1 * v1;
            }
            if (r0g + 8 < NN) {
                float v2 = acc[i][j][2] + bx, v3 = acc[i][j][3] + by;
                *(float2*)(Y + (size_t)(r0g + 8) * DD + cg) = make_float2(v2, v3);
                ps[j][0] += v2; pq[j][0] += v2 * v2;
                ps[j][1] += v3; pq[j][1] += v3 * v3;
            }
        }
    }
#pragma unroll
    for (int j = 0; j < 4; j++)
#pragma unroll
        for (int c = 0; c < 2; c++) {
#pragma unroll
            for (int m = 4; m <= 16; m <<= 1) {
                ps[j][c] += __shfl_xor_sync(0xFFFFFFFFu, ps[j][c], m);
                pq[j][c] += __shfl_xor_sync(0xFFFFFFFFu, pq[j][c], m);
            }
        }
    if (rq == 0) {
#pragma unroll
        for (int j = 0; j < 4; j++)
#pragma unroll
            for (int c = 0; c < 2; c++) {
                atomicAdd(&scs[n0 + j * 8 + cq + c], ps[j][c]);
                atomicAdd(&scq[n0 + j * 8 + cq + c], pq[j][c]);
            }
    }
    __syncthreads();
    if (tid < 128) {
        atomicAdd(&colsum[tid], scs[tid]);
        atomicAdd(&colsq[tid],  scq[tid]);
    }
}

// ---------------- BN scale/shift (reads stats bank, then zeroes it) ----------------
__global__ void bn_stats_k(float* __restrict__ cs, float* __restrict__ cq,
                           const float* __restrict__ g, const float* __restrict__ b,
                           float* __restrict__ sOut, float* __restrict__ tOut)
{
    int d = threadIdx.x;
    float su = cs[d], sq = cq[d];
    float mu  = su * (1.0f / NN);
    float var = sq * (1.0f / NN) - mu * mu;
    float sc  = g[d] * rsqrtf(var + 1e-5f);
    sOut[d] = sc;
    tOut[d] = b[d] - mu * sc;
    cs[d] = 0.f;
    cq[d] = 0.f;
}

// ---------------- final output: out = y2*s2+t2 ----------------
__global__ void finalize_k(float* __restrict__ out) {
    int i = blockIdx.x * 256 + threadIdx.x;
    int d4 = (i * 4) & 127;
    float4 v = ((const float4*)g_y2)[i];
    float4 s = *(const float4*)(g_s2 + d4);
    float4 t = *(const float4*)(g_t2 + d4);
    v.x = fmaf(v.x, s.x, t.x);
    v.y = fmaf(v.y, s.y, t.y);
    v.z = fmaf(v.z, s.z, t.z);
    v.w = fmaf(v.w, s.w, t.w);
    ((float4*)out)[i] = v;
}

extern "C" void kernel_launch(void* const* d_in, const int* in_sizes, int n_in,
                              void* d_out, int out_size)
{
    const float* x    = (const float*)d_in[0];
    const int*   ei32 = (const int*)d_in[1];
    const float* eps  = (const float*)d_in[2];
    const float* W1   = (const float*)d_in[3];
    const float* b1   = (const float*)d_in[4];
    const float* bn1g = (const float*)d_in[5];
    const float* bn1b = (const float*)d_in[6];
    const float* W2   = (const float*)d_in[7];
    const float* b2   = (const float*)d_in[8];
    const float* bn2g = (const float*)d_in[9];
    const float* bn2b = (const float*)d_in[10];

    float *y1p, *y2p, *statsp, *s1p, *t1p, *s2p, *t2p;
    unsigned short *whip, *wlop;
    cudaGetSymbolAddress((void**)&y1p,    g_y1);
    cudaGetSymbolAddress((void**)&y2p,    g_y2);
    cudaGetSymbolAddress((void**)&statsp, g_stats);
    cudaGetSymbolAddress((void**)&s1p,    g_s1);
    cudaGetSymbolAddress((void**)&t1p,    g_t1);
    cudaGetSymbolAddress((void**)&s2p,    g_s2);
    cudaGetSymbolAddress((void**)&t2p,    g_t2);
    cudaGetSymbolAddress((void**)&whip,   g_whi);
    cudaGetSymbolAddress((void**)&wlop,   g_wlo);

    cudaFuncSetAttribute((const void*)gemm_tc_k<1, 0>, cudaFuncAttributeMaxDynamicSharedMemorySize, GEMM_SMEM);
    cudaFuncSetAttribute((const void*)gemm_tc_k<1, 1>, cudaFuncAttributeMaxDynamicSharedMemorySize, GEMM_SMEM);
    cudaFuncSetAttribute((const void*)gemm_tc_k<2, 0>, cudaFuncAttributeMaxDynamicSharedMemorySize, GEMM_SMEM);

    const int gemmBlocks = (NN + 127) / 128;   // 391

    // one-time prep
    wprep_k<<<384, 256>>>(W1, W2, ei32);
    count_k<<<3125, 256>>>(ei32);
    scan1_k<<<49, 1024>>>();
    scan3_k<<<49, 1024>>>();
    fill_k<<<3125, 256>>>(ei32);

    for (int l = 0; l < 3; l++) {
        if (l == 0) {
            q_k<0><<<3125, 256>>>(x);
            agg_k<<<6250, 256>>>();
            gemm_tc_k<1, 0><<<gemmBlocks, 256, GEMM_SMEM>>>(x, eps, l,
                whip + (size_t)l * 16384, wlop + (size_t)l * 16384,
                b1 + (size_t)l * DD, y1p, statsp, statsp + 128);
        } else {
            q_k<1><<<3125, 256>>>(y2p);
            agg_k<<<6250, 256>>>();
            gemm_tc_k<1, 1><<<gemmBlocks, 256, GEMM_SMEM>>>(y2p, eps, l,
                whip + (size_t)l * 16384, wlop + (size_t)l * 16384,
                b1 + (size_t)l * DD, y1p, statsp, statsp + 128);
        }
        bn_stats_k<<<1, 128>>>(statsp, statsp + 128,
                               bn1g + (size_t)l * DD, bn1b + (size_t)l * DD, s1p, t1p);
        gemm_tc_k<2, 0><<<gemmBlocks, 256, GEMM_SMEM>>>(y1p, eps, l,
            whip + (size_t)(3 + l) * 16384, wlop + (size_t)(3 + l) * 16384,
            b2 + (size_t)l * DD, y2p, statsp + 256, statsp + 384);
        bn_stats_k<<<1, 128>>>(statsp + 256, statsp + 384,
                               bn2g + (size_t)l * DD, bn2b + (size_t)l * DD, s2p, t2p);
    }
    finalize_k<<<6250, 256>>>((float*)d_out);
}

// round 13
// speedup vs baseline: 1.3831x; 1.0886x over previous
#include <cuda_runtime.h>
#include <cuda_bf16.h>
#include <cuda_fp16.h>
#include <cstdint>

#define NN 50000
#define DD 128
#define EE 800000
#define NTILES 391
#define GEMM_GRID 148

// ---------------- scratch (static device globals: no allocation) ----------------
__device__ __align__(16) float g_agg[NN * DD];
__device__ __align__(16) float g_y1[NN * DD];
__device__ __align__(16) float g_y2[NN * DD];
__device__ __align__(16) unsigned short g_hf[NN * DD];   // fp16 gather image
__device__ __align__(16) float g_stats[512];   // bank1[256], bank2[256]; zero at launch start
__device__ __align__(16) float g_s2[DD];       // outer BN scale/shift
__device__ __align__(16) float g_t2[DD];
__device__ int g_is64;
__device__ __align__(16) unsigned short g_whi[6 * DD * DD];
__device__ __align__(16) unsigned short g_wlo[6 * DD * DD];
__device__ int g_deg[50176];
__device__ int g_scan[50176];
__device__ int g_off[50176];
__device__ int g_cursor[50176];
__device__ int g_bsum[64];
__device__ int g_srcs[EE];

__device__ __forceinline__ uint32_t smem_to_u32(const void* p) {
    uint32_t a;
    asm("{ .reg .u64 t; cvta.to.shared.u64 t, %1; cvt.u32.u64 %0, t; }" : "=r"(a) : "l"(p));
    return a;
}

#define LDMX4(r0, r1, r2, r3, addr) \
    asm volatile("ldmatrix.sync.aligned.m8n8.x4.shared.b16 {%0,%1,%2,%3}, [%4];" \
                 : "=r"(r0), "=r"(r1), "=r"(r2), "=r"(r3) : "r"(addr))

#define MMA16816(d, a, b) \
    asm volatile("mma.sync.aligned.m16n8k16.row.col.f32.bf16.bf16.f32 " \
                 "{%0,%1,%2,%3}, {%4,%5,%6,%7}, {%8,%9}, {%0,%1,%2,%3};" \
                 : "+f"((d)[0]), "+f"((d)[1]), "+f"((d)[2]), "+f"((d)[3]) \
                 : "r"((a)[0]), "r"((a)[1]), "r"((a)[2]), "r"((a)[3]), "r"((b)[0]), "r"((b)[1]))

// -------- prep: weight transpose+split + zero degrees + detect dtype (ONE kernel) ------
__global__ void wprep_k(const float* __restrict__ W1, const float* __restrict__ W2,
                        const int* __restrict__ ei32)
{
    int b = blockIdx.x;                      // 384 blocks
    int wi = b >> 6;
    int id = ((b & 63) << 8) + threadIdx.x;
    const float* W = (wi < 3) ? (W1 + (size_t)wi * 16384) : (W2 + (size_t)(wi - 3) * 16384);
    int k = id >> 7, n = id & 127;
    float v = W[k * 128 + n];
    __nv_bfloat16 hb = __float2bfloat16(v);
    __nv_bfloat16 lb = __float2bfloat16(v - __bfloat162float(hb));
    g_whi[(size_t)wi * 16384 + n * 128 + k] = __bfloat16_as_ushort(hb);
    g_wlo[(size_t)wi * 16384 + n * 128 + k] = __bfloat16_as_ushort(lb);

    if (b < 196) g_deg[b * 256 + threadIdx.x] = 0;

    if (b == 0 && threadIdx.x == 0) {
        int is64 = 1;
#pragma unroll
        for (int i = 0; i < 8; i++)
            if (ei32[2 * i + 1] != 0) is64 = 0;
        g_is64 = is64;
    }
}

// ================= CSR build =================
__global__ void count_k(const int* __restrict__ ei32) {   // 3125 x 256
    int e = blockIdx.x * 256 + threadIdx.x;
    if (e >= EE) return;
    int d = g_is64 ? ei32[2 * (EE + e)] : ei32[EE + e];
    atomicAdd(&g_deg[d], 1);
}
__global__ void scan1_k() {                 // 49 x 1024
    __shared__ int sm[1024];
    int t = threadIdx.x;
    int gid = blockIdx.x * 1024 + t;
    int v = (gid < NN) ? g_deg[gid] : 0;
    sm[t] = v;
    __syncthreads();
    for (int o = 1; o < 1024; o <<= 1) {
        int tv = (t >= o) ? sm[t - o] : 0;
        __syncthreads();
        sm[t] += tv;
        __syncthreads();
    }
    g_scan[gid] = sm[t] - v;
    if (t == 1023) g_bsum[blockIdx.x] = sm[1023];
}
__global__ void scan3_k() {                 // 49 x 1024; block prefix from g_bsum inline
    __shared__ int sb[64];
    int t = threadIdx.x;
    if (t < 64) sb[t] = (t < blockIdx.x && t < 49) ? g_bsum[t] : 0;
    __syncthreads();
    if (t < 32) sb[t] += sb[t + 32];
    __syncthreads();
    if (t < 16) sb[t] += sb[t + 16];
    __syncthreads();
    if (t < 8) sb[t] += sb[t + 8];
    __syncthreads();
    if (t < 4) sb[t] += sb[t + 4];
    __syncthreads();
    if (t < 2) sb[t] += sb[t + 2];
    __syncthreads();
    if (t == 0) sb[0] += sb[1];
    __syncthreads();
    int gid = blockIdx.x * 1024 + t;
    int o = g_scan[gid] + sb[0];
    g_off[gid] = o;
    g_cursor[gid] = o;
}
__global__ void fill_k(const int* __restrict__ ei32) {    // 3125 x 256
    int e = blockIdx.x * 256 + threadIdx.x;
    if (e >= EE) return;
    int s, d;
    if (g_is64) { s = ei32[2 * e]; d = ei32[2 * (EE + e)]; }
    else        { s = ei32[e];     d = ei32[EE + e]; }
    int pos = atomicAdd(&g_cursor[d], 1);
    g_srcs[pos] = s;
}

// --------- quantize features to fp16 gather image ---------
// TRANS=0: g_hf = x ; TRANS=1: g_hf = relu(y2*s2 + t2)
template <int TRANS>
__global__ void q_k(const float* __restrict__ P) {        // 3125 x 256, 8 elems/thread
    int base = (blockIdx.x * 256 + threadIdx.x) * 8;
    int col = base & 127;
    float4 p0 = *(const float4*)(P + base);
    float4 p1 = *(const float4*)(P + base + 4);
    float v[8] = {p0.x, p0.y, p0.z, p0.w, p1.x, p1.y, p1.z, p1.w};
    if (TRANS) {
        float4 s0 = *(const float4*)(g_s2 + col);
        float4 s1 = *(const float4*)(g_s2 + col + 4);
        float4 t0 = *(const float4*)(g_t2 + col);
        float4 t1 = *(const float4*)(g_t2 + col + 4);
        v[0] = fmaxf(fmaf(v[0], s0.x, t0.x), 0.f);
        v[1] = fmaxf(fmaf(v[1], s0.y, t0.y), 0.f);
        v[2] = fmaxf(fmaf(v[2], s0.z, t0.z), 0.f);
        v[3] = fmaxf(fmaf(v[3], s0.w, t0.w), 0.f);
        v[4] = fmaxf(fmaf(v[4], s1.x, t1.x), 0.f);
        v[5] = fmaxf(fmaf(v[5], s1.y, t1.y), 0.f);
        v[6] = fmaxf(fmaf(v[6], s1.z, t1.z), 0.f);
        v[7] = fmaxf(fmaf(v[7], s1.w, t1.w), 0.f);
    }
    unsigned short o[8];
#pragma unroll
    for (int j = 0; j < 8; j++) o[j] = __half_as_ushort(__float2half_rn(v[j]));
    uint32_t w0 = (uint32_t)o[0] | ((uint32_t)o[1] << 16);
    uint32_t w1 = (uint32_t)o[2] | ((uint32_t)o[3] << 16);
    uint32_t w2 = (uint32_t)o[4] | ((uint32_t)o[5] << 16);
    uint32_t w3 = (uint32_t)o[6] | ((uint32_t)o[7] << 16);
    *(uint4*)(g_hf + base) = make_uint4(w0, w1, w2, w3);
}

// ------- aggregation: fp16 gather + fp32 register sum (relu on the fly) ----
__device__ __forceinline__ void add4(float* acc, uint2 q) {
    float2 f0 = __half22float2(*(__half2*)&q.x);
    float2 f1 = __half22float2(*(__half2*)&q.y);
    acc[0] += fmaxf(f0.x, 0.f);
    acc[1] += fmaxf(f0.y, 0.f);
    acc[2] += fmaxf(f1.x, 0.f);
    acc[3] += fmaxf(f1.y, 0.f);
}
__global__ void __launch_bounds__(256) agg_k() {
    int w = blockIdx.x * 8 + (threadIdx.x >> 5);  // 6250 blocks -> 50000 warps
    int lane = threadIdx.x & 31;
    int s = g_off[w], t = g_off[w + 1];
    const unsigned short* H = g_hf;
    int lc = lane * 4;                            // 4 halves/lane; warp covers a row
    float acc[4] = {0.f, 0.f, 0.f, 0.f};
    int e = s;
    for (; e + 3 < t; e += 4) {
        int s0 = g_srcs[e], s1 = g_srcs[e + 1], s2i = g_srcs[e + 2], s3 = g_srcs[e + 3];
        uint2 q0 = *(const uint2*)(H + (size_t)s0 * DD + lc);
        uint2 q1 = *(const uint2*)(H + (size_t)s1 * DD + lc);
        uint2 q2 = *(const uint2*)(H + (size_t)s2i * DD + lc);
        uint2 q3 = *(const uint2*)(H + (size_t)s3 * DD + lc);
        add4(acc, q0); add4(acc, q1); add4(acc, q2); add4(acc, q3);
    }
    for (; e < t; e++) {
        int s0 = g_srcs[e];
        uint2 q0 = *(const uint2*)(H + (size_t)s0 * DD + lc);
        add4(acc, q0);
    }
    *(float4*)(g_agg + (size_t)w * DD + lc) = make_float4(acc[0], acc[1], acc[2], acc[3]);
}

// ---------------- persistent HMMA GEMM (grid-stride over 391 tiles) ----------------
// MODE 1: A = (1+eps)*own + agg ; own = A0 fp32 (TRANS=0) or g_hf fp16 (TRANS=1)
// MODE 2: A = relu(y1*s1+t1), s1/t1 inline from statIn + bn params
#define TSTRIDE 136
#define TBYTES  (128 * TSTRIDE * 2)
#define BIAS_OFF 0
#define AHI_OFF  1024
#define ALO_OFF  (AHI_OFF + TBYTES)
#define BHI_OFF  (ALO_OFF + TBYTES)
#define BLO_OFF  (BHI_OFF + TBYTES)
#define STAT_OFF (BLO_OFF + TBYTES)
#define SN_OFF   (STAT_OFF + 1024)
#define GEMM_SMEM (SN_OFF + 1024)

template <int MODE, int TRANS>
__global__ void __launch_bounds__(256, 1) gemm_tc_k(
    const float* __restrict__ A0, const float* __restrict__ epsp, int layer,
    const unsigned short* __restrict__ whi, const unsigned short* __restrict__ wlo,
    const float* __restrict__ bias, float* __restrict__ Y,
    float* __restrict__ statOut,
    const float* __restrict__ statIn, const float* __restrict__ bnG, const float* __restrict__ bnB)
{
    extern __shared__ __align__(16) char smem[];
    uint32_t sb = smem_to_u32(smem);
    int tid = threadIdx.x;
    int wid = tid >> 5, lane = tid & 31;

    if (tid < 128) *(float*)(smem + BIAS_OFF + tid * 4) = bias[tid];
    ((float*)(smem + STAT_OFF))[tid] = 0.f;

    float* sN = (float*)(smem + SN_OFF);   // inline s1/t1 for MODE 2
    float* tN = sN + 128;
    if (MODE == 2) {
        if (tid < 128) {
            float mu  = statIn[tid] * (1.0f / NN);
            float var = statIn[128 + tid] * (1.0f / NN) - mu * mu;
            float sc  = bnG[tid] * rsqrtf(var + 1e-5f);
            sN[tid] = sc;
            tN[tid] = bnB[tid] - mu * sc;
        }
    }
    __syncthreads();   // sN/tN (and bias) visible to ALL threads before first A-transform

    // ---- B tiles: loaded ONCE per block ----
    {
        const uint4* sh = (const uint4*)whi;
        const uint4* sl = (const uint4*)wlo;
#pragma unroll
        for (int i = 0; i < 8; i++) {
            int id = i * 256 + tid;
            int r = id >> 4, c16 = id & 15;
            uint32_t dst = (uint32_t)(r * (TSTRIDE * 2) + c16 * 16);
            *(uint4*)(smem + BHI_OFF + dst) = sh[id];
            *(uint4*)(smem + BLO_OFF + dst) = sl[id];
        }
    }

    float epsv = (MODE == 1) ? (1.0f + epsp[layer]) : 0.0f;
    int wm = wid & 1, wn = wid >> 1;
    int m0 = wm * 64, n0 = wn * 32;
    uint32_t aOff = (uint32_t)((m0 + (lane & 15)) * (TSTRIDE * 2) + (lane >> 4) * 16);
    uint32_t bOff = (uint32_t)((n0 + (lane & 7) + (lane >> 4) * 8) * (TSTRIDE * 2) + ((lane >> 3) & 1) * 16);
    int rq = lane >> 2, cq = (lane & 3) * 2;

    // BN stats: accumulate in registers across tiles, flush once at end
    float ps[4][2], pq[4][2];
#pragma unroll
    for (int j = 0; j < 4; j++) { ps[j][0] = ps[j][1] = 0.f; pq[j][0] = pq[j][1] = 0.f; }

    for (int tile = blockIdx.x; tile < NTILES; tile += gridDim.x) {
        int rowBase = tile * 128;

        // ---- A tile: fused transform + bf16 split ----
#pragma unroll
        for (int it = 0; it < 8; it++) {
            int id = it * 256 + tid;
            int row = id >> 4;
            int col = (id & 15) * 8;
            int gr = rowBase + row;
            float v[8];
#pragma unroll
            for (int j = 0; j < 8; j++) v[j] = 0.f;
            if (gr < NN) {
                if (MODE == 1) {
                    float own[8];
                    if (TRANS) {
                        uint4 q = *(const uint4*)(g_hf + (size_t)gr * DD + col);
                        __half2* hp = (__half2*)&q;
#pragma unroll
                        for (int j = 0; j < 4; j++) {
                            float2 f = __half22float2(hp[j]);
                            own[2 * j] = f.x;
                            own[2 * j + 1] = f.y;
                        }
                    } else {
                        float4 p0 = *(const float4*)(A0 + (size_t)gr * DD + col);
                        float4 p1 = *(const float4*)(A0 + (size_t)gr * DD + col + 4);
                        own[0] = p0.x; own[1] = p0.y; own[2] = p0.z; own[3] = p0.w;
                        own[4] = p1.x; own[5] = p1.y; own[6] = p1.z; own[7] = p1.w;
                    }
                    float4 a0 = *(const float4*)(g_agg + (size_t)gr * DD + col);
                    float4 a1 = *(const float4*)(g_agg + (size_t)gr * DD + col + 4);
                    v[0] = fmaf(epsv, own[0], a0.x); v[1] = fmaf(epsv, own[1], a0.y);
                    v[2] = fmaf(epsv, own[2], a0.z); v[3] = fmaf(epsv, own[3], a0.w);
                    v[4] = fmaf(epsv, own[4], a1.x); v[5] = fmaf(epsv, own[5], a1.y);
                    v[6] = fmaf(epsv, own[6], a1.z); v[7] = fmaf(epsv, own[7], a1.w);
                } else {
                    float4 p0 = *(const float4*)(A0 + (size_t)gr * DD + col);
                    float4 p1 = *(const float4*)(A0 + (size_t)gr * DD + col + 4);
                    v[0] = p0.x; v[1] = p0.y; v[2] = p0.z; v[3] = p0.w;
                    v[4] = p1.x; v[5] = p1.y; v[6] = p1.z; v[7] = p1.w;
#pragma unroll
                    for (int j = 0; j < 8; j++)
                        v[j] = fmaxf(fmaf(v[j], sN[col + j], tN[col + j]), 0.f);
                }
            }
            uint32_t h[4], l[4];
#pragma unroll
            for (int j = 0; j < 4; j++) {
                __nv_bfloat16 h0 = __float2bfloat16(v[2 * j]);
                __nv_bfloat16 h1 = __float2bfloat16(v[2 * j + 1]);
                __nv_bfloat16 l0 = __float2bfloat16(v[2 * j] - __bfloat162float(h0));
                __nv_bfloat16 l1 = __float2bfloat16(v[2 * j + 1] - __bfloat162float(h1));
                h[j] = ((uint32_t)__bfloat16_as_ushort(h1) << 16) | __bfloat16_as_ushort(h0);
                l[j] = ((uint32_t)__bfloat16_as_ushort(l1) << 16) | __bfloat16_as_ushort(l0);
            }
            uint32_t off = (uint32_t)(row * (TSTRIDE * 2) + col * 2);
            *(uint4*)(smem + AHI_OFF + off) = make_uint4(h[0], h[1], h[2], h[3]);
            *(uint4*)(smem + ALO_OFF + off) = make_uint4(l[0], l[1], l[2], l[3]);
        }
        __syncthreads();

        // ---- warp MMA mainloop ----
        float acc[4][4][4];
#pragma unroll
        for (int i = 0; i < 4; i++)
#pragma unroll
            for (int j = 0; j < 4; j++)
#pragma unroll
                for (int q = 0; q < 4; q++) acc[i][j][q] = 0.f;

#pragma unroll
        for (int ks = 0; ks < 8; ks++) {
            uint32_t kByte = (uint32_t)(ks * 32);
            uint32_t ah[4][4], al[4][4], bh[4][2], bl[4][2];
#pragma unroll
            for (int i = 0; i < 4; i++) {
                uint32_t ad = sb + AHI_OFF + aOff + kByte + (uint32_t)(i * 16 * TSTRIDE * 2);
                LDMX4(ah[i][0], ah[i][1], ah[i][2], ah[i][3], ad);
            }
#pragma unroll
            for (int i = 0; i < 4; i++) {
                uint32_t ad = sb + ALO_OFF + aOff + kByte + (uint32_t)(i * 16 * TSTRIDE * 2);
                LDMX4(al[i][0], al[i][1], al[i][2], al[i][3], ad);
            }
#pragma unroll
            for (int jj = 0; jj < 2; jj++) {
                uint32_t bd = sb + BHI_OFF + bOff + kByte + (uint32_t)(jj * 16 * TSTRIDE * 2);
                uint32_t r0, r1, r2, r3;
                LDMX4(r0, r1, r2, r3, bd);
                bh[2 * jj][0] = r0; bh[2 * jj][1] = r1;
                bh[2 * jj + 1][0] = r2; bh[2 * jj + 1][1] = r3;
                bd = sb + BLO_OFF + bOff + kByte + (uint32_t)(jj * 16 * TSTRIDE * 2);
                LDMX4(r0, r1, r2, r3, bd);
                bl[2 * jj][0] = r0; bl[2 * jj][1] = r1;
                bl[2 * jj + 1][0] = r2; bl[2 * jj + 1][1] = r3;
            }
#pragma unroll
            for (int i = 0; i < 4; i++)
#pragma unroll
                for (int j = 0; j < 4; j++) MMA16816(acc[i][j], ah[i], bh[j]);
#pragma unroll
            for (int i = 0; i < 4; i++)
#pragma unroll
                for (int j = 0; j < 4; j++) MMA16816(acc[i][j], ah[i], bl[j]);
#pragma unroll
            for (int i = 0; i < 4; i++)
#pragma unroll
                for (int j = 0; j < 4; j++) MMA16816(acc[i][j], al[i], bh[j]);
        }

        // ---- epilogue: bias, store, accumulate BN stats into regs ----
        const float* bs = (const float*)(smem + BIAS_OFF);
#pragma unroll
        for (int i = 0; i < 4; i++) {
            int r0g = rowBase + m0 + i * 16 + rq;
#pragma unroll
            for (int j = 0; j < 4; j++) {
                int cg = n0 + j * 8 + cq;
                float bx = bs[cg], by = bs[cg + 1];
                if (r0g < NN) {
                    float v0 = acc[i][j][0] + bx, v1 = acc[i][j][1] + by;
                    *(float2*)(Y + (size_t)r0g * DD + cg) = make_float2(v0, v1);
                    ps[j][0] += v0; pq[j][0] += v0 * v0;
                    ps[j][1] += v1; pq[j][1] += v1 * v1;
                }
                if (r0g + 8 < NN) {
                    float v2 = acc[i][j][2] + bx, v3 = acc[i][j][3] + by;
                    *(float2*)(Y + (size_t)(r0g + 8) * DD + cg) = make_float2(v2, v3);
                    ps[j][0] += v2; pq[j][0] += v2 * v2;
                    ps[j][1] += v3; pq[j][1] += v3 * v3;
                }
            }
        }
        __syncthreads();   // mainloop reads done before next tile's A-store
    }

    // ---- one-time stats flush ----
    float* scs = (float*)(smem + STAT_OFF);
    float* scq = scs + 128;
#pragma unroll
    for (int j = 0; j < 4; j++)
#pragma unroll
        for (int c = 0; c < 2; c++) {
#pragma unroll
            for (int m = 4; m <= 16; m <<= 1) {
                ps[j][c] += __shfl_xor_sync(0xFFFFFFFFu, ps[j][c], m);
                pq[j][c] += __shfl_xor_sync(0xFFFFFFFFu, pq[j][c], m);
            }
        }
    if (rq == 0) {
#pragma unroll
        for (int j = 0; j < 4; j++)
#pragma unroll
            for (int c = 0; c < 2; c++) {
                atomicAdd(&scs[n0 + j * 8 + cq + c], ps[j][c]);
                atomicAdd(&scq[n0 + j * 8 + cq + c], pq[j][c]);
            }
    }
    __syncthreads();
    if (tid < 128) {
        atomicAdd(&statOut[tid],       scs[tid]);
        atomicAdd(&statOut[128 + tid], scq[tid]);
    }
}

// -------- outer BN: compute g_s2/g_t2 from bank2, then zero BOTH banks -----
__global__ void bn2_k(const float* __restrict__ sIn, float* __restrict__ zeroBase,
                      const float* __restrict__ g, const float* __restrict__ b)
{
    int t = threadIdx.x;    // 256
    float sc = 0.f, sh = 0.f;
    if (t < 128) {
        float mu  = sIn[t] * (1.0f / NN);
        float var = sIn[128 + t] * (1.0f / NN) - mu * mu;
        sc = g[t] * rsqrtf(var + 1e-5f);
        sh = b[t] - mu * sc;
    }
    __syncthreads();        // all reads done before zeroing
    if (t < 128) { g_s2[t] = sc; g_t2[t] = sh; }
    zeroBase[2 * t]     = 0.f;   // zero 512 floats (both banks)
    zeroBase[2 * t + 1] = 0.f;
}

// ---------------- final output: out = y2*s2+t2 ----------------
__global__ void finalize_k(float* __restrict__ out) {
    int i = blockIdx.x * 256 + threadIdx.x;
    int d4 = (i * 4) & 127;
    float4 v = ((const float4*)g_y2)[i];
    float4 s = *(const float4*)(g_s2 + d4);
    float4 t = *(const float4*)(g_t2 + d4);
    v.x = fmaf(v.x, s.x, t.x);
    v.y = fmaf(v.y, s.y, t.y);
    v.z = fmaf(v.z, s.z, t.z);
    v.w = fmaf(v.w, s.w, t.w);
    ((float4*)out)[i] = v;
}

extern "C" void kernel_launch(void* const* d_in, const int* in_sizes, int n_in,
                              void* d_out, int out_size)
{
    const float* x    = (const float*)d_in[0];
    const int*   ei32 = (const int*)d_in[1];
    const float* eps  = (const float*)d_in[2];
    const float* W1   = (const float*)d_in[3];
    const float* b1   = (const float*)d_in[4];
    const float* bn1g = (const float*)d_in[5];
    const float* bn1b = (const float*)d_in[6];
    const float* W2   = (const float*)d_in[7];
    const float* b2   = (const float*)d_in[8];
    const float* bn2g = (const float*)d_in[9];
    const float* bn2b = (const float*)d_in[10];

    float *y1p, *y2p, *statsp;
    unsigned short *whip, *wlop;
    cudaGetSymbolAddress((void**)&y1p,    g_y1);
    cudaGetSymbolAddress((void**)&y2p,    g_y2);
    cudaGetSymbolAddress((void**)&statsp, g_stats);
    cudaGetSymbolAddress((void**)&whip,   g_whi);
    cudaGetSymbolAddress((void**)&wlop,   g_wlo);

    cudaFuncSetAttribute((const void*)gemm_tc_k<1, 0>, cudaFuncAttributeMaxDynamicSharedMemorySize, GEMM_SMEM);
    cudaFuncSetAttribute((const void*)gemm_tc_k<1, 1>, cudaFuncAttributeMaxDynamicSharedMemorySize, GEMM_SMEM);
    cudaFuncSetAttribute((const void*)gemm_tc_k<2, 0>, cudaFuncAttributeMaxDynamicSharedMemorySize, GEMM_SMEM);

    // one-time prep
    wprep_k<<<384, 256>>>(W1, W2, ei32);
    count_k<<<3125, 256>>>(ei32);
    scan1_k<<<49, 1024>>>();
    scan3_k<<<49, 1024>>>();
    fill_k<<<3125, 256>>>(ei32);

    for (int l = 0; l < 3; l++) {
        float* bank1 = statsp;
        float* bank2 = statsp + 256;
        if (l == 0) {
            q_k<0><<<3125, 256>>>(x);
            agg_k<<<6250, 256>>>();
            gemm_tc_k<1, 0><<<GEMM_GRID, 256, GEMM_SMEM>>>(x, eps, l,
                whip + (size_t)l * 16384, wlop + (size_t)l * 16384,
                b1 + (size_t)l * DD, y1p, bank1, nullptr, nullptr, nullptr);
        } else {
            q_k<1><<<3125, 256>>>(y2p);
            agg_k<<<6250, 256>>>();
            gemm_tc_k<1, 1><<<GEMM_GRID, 256, GEMM_SMEM>>>(y2p, eps, l,
                whip + (size_t)l * 16384, wlop + (size_t)l * 16384,
                b1 + (size_t)l * DD, y1p, bank1, nullptr, nullptr, nullptr);
        }
        gemm_tc_k<2, 0><<<GEMM_GRID, 256, GEMM_SMEM>>>(y1p, eps, l,
            whip + (size_t)(3 + l) * 16384, wlop + (size_t)(3 + l) * 16384,
            b2 + (size_t)l * DD, y2p, bank2,
            bank1, bn1g + (size_t)l * DD, bn1b + (size_t)l * DD);
        bn2_k<<<1, 256>>>(bank2, statsp, bn2g + (size_t)l * DD, bn2b + (size_t)l * DD);
    }
    finalize_k<<<6250, 256>>>((float*)d_out);
}

// round 14
// speedup vs baseline: 1.3936x; 1.0076x over previous
#include <cuda_runtime.h>
#include <cuda_bf16.h>
#include <cuda_fp16.h>
#include <cstdint>

#define NN 50000
#define DD 128
#define EE 800000
#define NTILES 391
#define GEMM_GRID 148

// ---------------- scratch (static device globals: no allocation) ----------------
__device__ __align__(16) float g_agg[NN * DD];
__device__ __align__(16) float g_y1[NN * DD];
__device__ __align__(16) float g_y2[NN * DD];
__device__ __align__(16) unsigned short g_hf[NN * DD];   // fp16 gather image
__device__ __align__(16) float g_stats[1536];  // 6 banks x 256 (sum[128], sq[128]); zeroed by wprep_k
__device__ int g_is64;
__device__ __align__(16) unsigned short g_whi[6 * DD * DD];
__device__ __align__(16) unsigned short g_wlo[6 * DD * DD];
__device__ int g_deg[50176];
__device__ int g_scan[50176];
__device__ int g_off[50176];
__device__ int g_cursor[50176];
__device__ int g_bsum[64];
__device__ int g_srcs[EE];

__device__ __forceinline__ uint32_t smem_to_u32(const void* p) {
    uint32_t a;
    asm("{ .reg .u64 t; cvta.to.shared.u64 t, %1; cvt.u32.u64 %0, t; }" : "=r"(a) : "l"(p));
    return a;
}

#define LDMX4(r0, r1, r2, r3, addr) \
    asm volatile("ldmatrix.sync.aligned.m8n8.x4.shared.b16 {%0,%1,%2,%3}, [%4];" \
                 : "=r"(r0), "=r"(r1), "=r"(r2), "=r"(r3) : "r"(addr))

#define MMA16816(d, a, b) \
    asm volatile("mma.sync.aligned.m16n8k16.row.col.f32.bf16.bf16.f32 " \
                 "{%0,%1,%2,%3}, {%4,%5,%6,%7}, {%8,%9}, {%0,%1,%2,%3};" \
                 : "+f"((d)[0]), "+f"((d)[1]), "+f"((d)[2]), "+f"((d)[3]) \
                 : "r"((a)[0]), "r"((a)[1]), "r"((a)[2]), "r"((a)[3]), "r"((b)[0]), "r"((b)[1]))

// BN scale/shift from a stats bank (tid < 128 computes into smem arrays)
__device__ __forceinline__ void bn_inline(int tid, const float* statIn,
                                          const float* bnG, const float* bnB,
                                          float* sN, float* tN)
{
    if (tid < 128) {
        float mu  = statIn[tid] * (1.0f / NN);
        float var = statIn[128 + tid] * (1.0f / NN) - mu * mu;
        float sc  = bnG[tid] * rsqrtf(var + 1e-5f);
        sN[tid] = sc;
        tN[tid] = bnB[tid] - mu * sc;
    }
}

// -------- prep: weights + zero degrees + zero stats + detect dtype (ONE kernel) ------
__global__ void wprep_k(const float* __restrict__ W1, const float* __restrict__ W2,
                        const int* __restrict__ ei32)
{
    int b = blockIdx.x;                      // 384 blocks
    int wi = b >> 6;
    int id = ((b & 63) << 8) + threadIdx.x;
    const float* W = (wi < 3) ? (W1 + (size_t)wi * 16384) : (W2 + (size_t)(wi - 3) * 16384);
    int k = id >> 7, n = id & 127;
    float v = W[k * 128 + n];
    __nv_bfloat16 hb = __float2bfloat16(v);
    __nv_bfloat16 lb = __float2bfloat16(v - __bfloat162float(hb));
    g_whi[(size_t)wi * 16384 + n * 128 + k] = __bfloat16_as_ushort(hb);
    g_wlo[(size_t)wi * 16384 + n * 128 + k] = __bfloat16_as_ushort(lb);

    if (b < 196) g_deg[b * 256 + threadIdx.x] = 0;
    if (b >= 196 && b < 202) g_stats[(b - 196) * 256 + threadIdx.x] = 0.f;

    if (b == 0 && threadIdx.x == 0) {
        int is64 = 1;
#pragma unroll
        for (int i = 0; i < 8; i++)
            if (ei32[2 * i + 1] != 0) is64 = 0;
        g_is64 = is64;
    }
}

// ================= CSR build =================
__global__ void count_k(const int* __restrict__ ei32) {   // 3125 x 256
    int e = blockIdx.x * 256 + threadIdx.x;
    if (e >= EE) return;
    int d = g_is64 ? ei32[2 * (EE + e)] : ei32[EE + e];
    atomicAdd(&g_deg[d], 1);
}
__global__ void scan1_k() {                 // 49 x 1024
    __shared__ int sm[1024];
    int t = threadIdx.x;
    int gid = blockIdx.x * 1024 + t;
    int v = (gid < NN) ? g_deg[gid] : 0;
    sm[t] = v;
    __syncthreads();
    for (int o = 1; o < 1024; o <<= 1) {
        int tv = (t >= o) ? sm[t - o] : 0;
        __syncthreads();
        sm[t] += tv;
        __syncthreads();
    }
    g_scan[gid] = sm[t] - v;
    if (t == 1023) g_bsum[blockIdx.x] = sm[1023];
}
__global__ void scan3_k() {                 // 49 x 1024; block prefix from g_bsum inline
    __shared__ int sb[64];
    int t = threadIdx.x;
    if (t < 64) sb[t] = (t < blockIdx.x && t < 49) ? g_bsum[t] : 0;
    __syncthreads();
    if (t < 32) sb[t] += sb[t + 32];
    __syncthreads();
    if (t < 16) sb[t] += sb[t + 16];
    __syncthreads();
    if (t < 8) sb[t] += sb[t + 8];
    __syncthreads();
    if (t < 4) sb[t] += sb[t + 4];
    __syncthreads();
    if (t < 2) sb[t] += sb[t + 2];
    __syncthreads();
    if (t == 0) sb[0] += sb[1];
    __syncthreads();
    int gid = blockIdx.x * 1024 + t;
    int o = g_scan[gid] + sb[0];
    g_off[gid] = o;
    g_cursor[gid] = o;
}
__global__ void fill_k(const int* __restrict__ ei32) {    // 3125 x 256
    int e = blockIdx.x * 256 + threadIdx.x;
    if (e >= EE) return;
    int s, d;
    if (g_is64) { s = ei32[2 * e]; d = ei32[2 * (EE + e)]; }
    else        { s = ei32[e];     d = ei32[EE + e]; }
    int pos = atomicAdd(&g_cursor[d], 1);
    g_srcs[pos] = s;
}

// --------- quantize features to fp16 gather image ---------
// TRANS=0: g_hf = x ; TRANS=1: g_hf = relu(y2*s2 + t2), s2/t2 computed inline from bank
template <int TRANS>
__global__ void q_k(const float* __restrict__ P,
                    const float* __restrict__ statIn,
                    const float* __restrict__ bnG, const float* __restrict__ bnB)
{
    __shared__ float sN[128], tN[128];
    int tid = threadIdx.x;
    if (TRANS) {
        bn_inline(tid, statIn, bnG, bnB, sN, tN);
        __syncthreads();
    }
    int base = (blockIdx.x * 256 + tid) * 8;
    int col = base & 127;
    float4 p0 = *(const float4*)(P + base);
    float4 p1 = *(const float4*)(P + base + 4);
    float v[8] = {p0.x, p0.y, p0.z, p0.w, p1.x, p1.y, p1.z, p1.w};
    if (TRANS) {
#pragma unroll
        for (int j = 0; j < 8; j++)
            v[j] = fmaxf(fmaf(v[j], sN[col + j], tN[col + j]), 0.f);
    }
    unsigned short o[8];
#pragma unroll
    for (int j = 0; j < 8; j++) o[j] = __half_as_ushort(__float2half_rn(v[j]));
    uint32_t w0 = (uint32_t)o[0] | ((uint32_t)o[1] << 16);
    uint32_t w1 = (uint32_t)o[2] | ((uint32_t)o[3] << 16);
    uint32_t w2 = (uint32_t)o[4] | ((uint32_t)o[5] << 16);
    uint32_t w3 = (uint32_t)o[6] | ((uint32_t)o[7] << 16);
    *(uint4*)(g_hf + base) = make_uint4(w0, w1, w2, w3);
}

// ------- aggregation: fp16 gather + fp32 register sum (relu on the fly) ----
__device__ __forceinline__ void add4(float* acc, uint2 q) {
    float2 f0 = __half22float2(*(__half2*)&q.x);
    float2 f1 = __half22float2(*(__half2*)&q.y);
    acc[0] += fmaxf(f0.x, 0.f);
    acc[1] += fmaxf(f0.y, 0.f);
    acc[2] += fmaxf(f1.x, 0.f);
    acc[3] += fmaxf(f1.y, 0.f);
}
__global__ void __launch_bounds__(256) agg_k() {
    int w = blockIdx.x * 8 + (threadIdx.x >> 5);  // 6250 blocks -> 50000 warps
    int lane = threadIdx.x & 31;
    int s = g_off[w], t = g_off[w + 1];
    const unsigned short* H = g_hf;
    int lc = lane * 4;                            // 4 halves/lane; warp covers a row
    float acc[4] = {0.f, 0.f, 0.f, 0.f};
    int e = s;
    for (; e + 3 < t; e += 4) {
        int s0 = g_srcs[e], s1 = g_srcs[e + 1], s2i = g_srcs[e + 2], s3 = g_srcs[e + 3];
        uint2 q0 = *(const uint2*)(H + (size_t)s0 * DD + lc);
        uint2 q1 = *(const uint2*)(H + (size_t)s1 * DD + lc);
        uint2 q2 = *(const uint2*)(H + (size_t)s2i * DD + lc);
        uint2 q3 = *(const uint2*)(H + (size_t)s3 * DD + lc);
        add4(acc, q0); add4(acc, q1); add4(acc, q2); add4(acc, q3);
    }
    for (; e < t; e++) {
        int s0 = g_srcs[e];
        uint2 q0 = *(const uint2*)(H + (size_t)s0 * DD + lc);
        add4(acc, q0);
    }
    *(float4*)(g_agg + (size_t)w * DD + lc) = make_float4(acc[0], acc[1], acc[2], acc[3]);
}

// ---------------- persistent HMMA GEMM (grid-stride over 391 tiles) ----------------
// MODE 1: A = (1+eps)*own + agg ; own = A0 fp32 (TRANS=0) or g_hf fp16 (TRANS=1)
// MODE 2: A = relu(y1*s1+t1), s1/t1 inline from statIn + bn params
#define TSTRIDE 136
#define TBYTES  (128 * TSTRIDE * 2)
#define BIAS_OFF 0
#define AHI_OFF  1024
#define ALO_OFF  (AHI_OFF + TBYTES)
#define BHI_OFF  (ALO_OFF + TBYTES)
#define BLO_OFF  (BHI_OFF + TBYTES)
#define STAT_OFF (BLO_OFF + TBYTES)
#define SN_OFF   (STAT_OFF + 1024)
#define GEMM_SMEM (SN_OFF + 1024)

template <int MODE, int TRANS>
__global__ void __launch_bounds__(256, 1) gemm_tc_k(
    const float* __restrict__ A0, const float* __restrict__ epsp, int layer,
    const unsigned short* __restrict__ whi, const unsigned short* __restrict__ wlo,
    const float* __restrict__ bias, float* __restrict__ Y,
    float* __restrict__ statOut,
    const float* __restrict__ statIn, const float* __restrict__ bnG, const float* __restrict__ bnB)
{
    extern __shared__ __align__(16) char smem[];
    uint32_t sb = smem_to_u32(smem);
    int tid = threadIdx.x;
    int wid = tid >> 5, lane = tid & 31;

    if (tid < 128) *(float*)(smem + BIAS_OFF + tid * 4) = bias[tid];
    ((float*)(smem + STAT_OFF))[tid] = 0.f;

    float* sN = (float*)(smem + SN_OFF);   // inline s1/t1 for MODE 2
    float* tN = sN + 128;
    if (MODE == 2) bn_inline(tid, statIn, bnG, bnB, sN, tN);
    __syncthreads();   // sN/tN + bias visible to ALL threads before first A-transform

    // ---- B tiles: loaded ONCE per block ----
    {
        const uint4* sh = (const uint4*)whi;
        const uint4* sl = (const uint4*)wlo;
#pragma unroll
        for (int i = 0; i < 8; i++) {
            int id = i * 256 + tid;
            int r = id >> 4, c16 = id & 15;
            uint32_t dst = (uint32_t)(r * (TSTRIDE * 2) + c16 * 16);
            *(uint4*)(smem + BHI_OFF + dst) = sh[id];
            *(uint4*)(smem + BLO_OFF + dst) = sl[id];
        }
    }

    float epsv = (MODE == 1) ? (1.0f + epsp[layer]) : 0.0f;
    int wm = wid & 1, wn = wid >> 1;
    int m0 = wm * 64, n0 = wn * 32;
    uint32_t aOff = (uint32_t)((m0 + (lane & 15)) * (TSTRIDE * 2) + (lane >> 4) * 16);
    uint32_t bOff = (uint32_t)((n0 + (lane & 7) + (lane >> 4) * 8) * (TSTRIDE * 2) + ((lane >> 3) & 1) * 16);
    int rq = lane >> 2, cq = (lane & 3) * 2;

    // BN stats: accumulate in registers across tiles, flush once at end
    float ps[4][2], pq[4][2];
#pragma unroll
    for (int j = 0; j < 4; j++) { ps[j][0] = ps[j][1] = 0.f; pq[j][0] = pq[j][1] = 0.f; }

    for (int tile = blockIdx.x; tile < NTILES; tile += gridDim.x) {
        int rowBase = tile * 128;

        // ---- A tile: fused transform + bf16 split ----
#pragma unroll
        for (int it = 0; it < 8; it++) {
            int id = it * 256 + tid;
            int row = id >> 4;
            int col = (id & 15) * 8;
            int gr = rowBase + row;
            float v[8];
#pragma unroll
            for (int j = 0; j < 8; j++) v[j] = 0.f;
            if (gr < NN) {
                if (MODE == 1) {
                    float own[8];
                    if (TRANS) {
                        uint4 q = *(const uint4*)(g_hf + (size_t)gr * DD + col);
                        __half2* hp = (__half2*)&q;
#pragma unroll
                        for (int j = 0; j < 4; j++) {
                            float2 f = __half22float2(hp[j]);
                            own[2 * j] = f.x;
                            own[2 * j + 1] = f.y;
                        }
                    } else {
                        float4 p0 = *(const float4*)(A0 + (size_t)gr * DD + col);
                        float4 p1 = *(const float4*)(A0 + (size_t)gr * DD + col + 4);
                        own[0] = p0.x; own[1] = p0.y; own[2] = p0.z; own[3] = p0.w;
                        own[4] = p1.x; own[5] = p1.y; own[6] = p1.z; own[7] = p1.w;
                    }
                    float4 a0 = *(const float4*)(g_agg + (size_t)gr * DD + col);
                    float4 a1 = *(const float4*)(g_agg + (size_t)gr * DD + col + 4);
                    v[0] = fmaf(epsv, own[0], a0.x); v[1] = fmaf(epsv, own[1], a0.y);
                    v[2] = fmaf(epsv, own[2], a0.z); v[3] = fmaf(epsv, own[3], a0.w);
                    v[4] = fmaf(epsv, own[4], a1.x); v[5] = fmaf(epsv, own[5], a1.y);
                    v[6] = fmaf(epsv, own[6], a1.z); v[7] = fmaf(epsv, own[7], a1.w);
                } else {
                    float4 p0 = *(const float4*)(A0 + (size_t)gr * DD + col);
                    float4 p1 = *(const float4*)(A0 + (size_t)gr * DD + col + 4);
                    v[0] = p0.x; v[1] = p0.y; v[2] = p0.z; v[3] = p0.w;
                    v[4] = p1.x; v[5] = p1.y; v[6] = p1.z; v[7] = p1.w;
#pragma unroll
                    for (int j = 0; j < 8; j++)
                        v[j] = fmaxf(fmaf(v[j], sN[col + j], tN[col + j]), 0.f);
                }
            }
            uint32_t h[4], l[4];
#pragma unroll
            for (int j = 0; j < 4; j++) {
                __nv_bfloat16 h0 = __float2bfloat16(v[2 * j]);
                __nv_bfloat16 h1 = __float2bfloat16(v[2 * j + 1]);
                __nv_bfloat16 l0 = __float2bfloat16(v[2 * j] - __bfloat162float(h0));
                __nv_bfloat16 l1 = __float2bfloat16(v[2 * j + 1] - __bfloat162float(h1));
                h[j] = ((uint32_t)__bfloat16_as_ushort(h1) << 16) | __bfloat16_as_ushort(h0);
                l[j] = ((uint32_t)__bfloat16_as_ushort(l1) << 16) | __bfloat16_as_ushort(l0);
            }
            uint32_t off = (uint32_t)(row * (TSTRIDE * 2) + col * 2);
            *(uint4*)(smem + AHI_OFF + off) = make_uint4(h[0], h[1], h[2], h[3]);
            *(uint4*)(smem + ALO_OFF + off) = make_uint4(l[0], l[1], l[2], l[3]);
        }
        __syncthreads();

        // ---- warp MMA mainloop ----
        float acc[4][4][4];
#pragma unroll
        for (int i = 0; i < 4; i++)
#pragma unroll
            for (int j = 0; j < 4; j++)
#pragma unroll
                for (int q = 0; q < 4; q++) acc[i][j][q] = 0.f;

#pragma unroll
        for (int ks = 0; ks < 8; ks++) {
            uint32_t kByte = (uint32_t)(ks * 32);
            uint32_t ah[4][4], al[4][4], bh[4][2], bl[4][2];
#pragma unroll
            for (int i = 0; i < 4; i++) {
                uint32_t ad = sb + AHI_OFF + aOff + kByte + (uint32_t)(i * 16 * TSTRIDE * 2);
                LDMX4(ah[i][0], ah[i][1], ah[i][2], ah[i][3], ad);
            }
#pragma unroll
            for (int i = 0; i < 4; i++) {
                uint32_t ad = sb + ALO_OFF + aOff + kByte + (uint32_t)(i * 16 * TSTRIDE * 2);
                LDMX4(al[i][0], al[i][1], al[i][2], al[i][3], ad);
            }
#pragma unroll
            for (int jj = 0; jj < 2; jj++) {
                uint32_t bd = sb + BHI_OFF + bOff + kByte + (uint32_t)(jj * 16 * TSTRIDE * 2);
                uint32_t r0, r1, r2, r3;
                LDMX4(r0, r1, r2, r3, bd);
                bh[2 * jj][0] = r0; bh[2 * jj][1] = r1;
                bh[2 * jj + 1][0] = r2; bh[2 * jj + 1][1] = r3;
                bd = sb + BLO_OFF + bOff + kByte + (uint32_t)(jj * 16 * TSTRIDE * 2);
                LDMX4(r0, r1, r2, r3, bd);
                bl[2 * jj][0] = r0; bl[2 * jj][1] = r1;
                bl[2 * jj + 1][0] = r2; bl[2 * jj + 1][1] = r3;
            }
#pragma unroll
            for (int i = 0; i < 4; i++)
#pragma unroll
                for (int j = 0; j < 4; j++) MMA16816(acc[i][j], ah[i], bh[j]);
#pragma unroll
            for (int i = 0; i < 4; i++)
#pragma unroll
                for (int j = 0; j < 4; j++) MMA16816(acc[i][j], ah[i], bl[j]);
#pragma unroll
            for (int i = 0; i < 4; i++)
#pragma unroll
                for (int j = 0; j < 4; j++) MMA16816(acc[i][j], al[i], bh[j]);
        }

        // ---- epilogue: bias, store, accumulate BN stats into regs ----
        const float* bs = (const float*)(smem + BIAS_OFF);
#pragma unroll
        for (int i = 0; i < 4; i++) {
            int r0g = rowBase + m0 + i * 16 + rq;
#pragma unroll
            for (int j = 0; j < 4; j++) {
                int cg = n0 + j * 8 + cq;
                float bx = bs[cg], by = bs[cg + 1];
                if (r0g < NN) {
                    float v0 = acc[i][j][0] + bx, v1 = acc[i][j][1] + by;
                    *(float2*)(Y + (size_t)r0g * DD + cg) = make_float2(v0, v1);
                    ps[j][0] += v0; pq[j][0] += v0 * v0;
                    ps[j][1] += v1; pq[j][1] += v1 * v1;
                }
                if (r0g + 8 < NN) {
                    float v2 = acc[i][j][2] + bx, v3 = acc[i][j][3] + by;
                    *(float2*)(Y + (size_t)(r0g + 8) * DD + cg) = make_float2(v2, v3);
                    ps[j][0] += v2; pq[j][0] += v2 * v2;
                    ps[j][1] += v3; pq[j][1] += v3 * v3;
                }
            }
        }
        __syncthreads();   // mainloop reads done before next tile's A-store
    }

    // ---- one-time stats flush ----
    float* scs = (float*)(smem + STAT_OFF);
    float* scq = scs + 128;
#pragma unroll
    for (int j = 0; j < 4; j++)
#pragma unroll
        for (int c = 0; c < 2; c++) {
#pragma unroll
            for (int m = 4; m <= 16; m <<= 1) {
                ps[j][c] += __shfl_xor_sync(0xFFFFFFFFu, ps[j][c], m);
                pq[j][c] += __shfl_xor_sync(0xFFFFFFFFu, pq[j][c], m);
            }
        }
    if (rq == 0) {
#pragma unroll
        for (int j = 0; j < 4; j++)
#pragma unroll
            for (int c = 0; c < 2; c++) {
                atomicAdd(&scs[n0 + j * 8 + cq + c], ps[j][c]);
                atomicAdd(&scq[n0 + j * 8 + cq + c], pq[j][c]);
            }
    }
    __syncthreads();
    if (tid < 128) {
        atomicAdd(&statOut[tid],       scs[tid]);
        atomicAdd(&statOut[128 + tid], scq[tid]);
    }
}

// ---------------- final output: out = y2*s2+t2, s2/t2 inline from last bank ----------
__global__ void finalize_k(float* __restrict__ out,
                           const float* __restrict__ statIn,
                           const float* __restrict__ bnG, const float* __restrict__ bnB)
{
    __shared__ float sN[128], tN[128];
    int tid = threadIdx.x;
    bn_inline(tid, statIn, bnG, bnB, sN, tN);
    __syncthreads();
    int i = blockIdx.x * 256 + tid;
    int d4 = (i * 4) & 127;
    float4 v = ((const float4*)g_y2)[i];
    v.x = fmaf(v.x, sN[d4],     tN[d4]);
    v.y = fmaf(v.y, sN[d4 + 1], tN[d4 + 1]);
    v.z = fmaf(v.z, sN[d4 + 2], tN[d4 + 2]);
    v.w = fmaf(v.w, sN[d4 + 3], tN[d4 + 3]);
    ((float4*)out)[i] = v;
}

extern "C" void kernel_launch(void* const* d_in, const int* in_sizes, int n_in,
                              void* d_out, int out_size)
{
    const float* x    = (const float*)d_in[0];
    const int*   ei32 = (const int*)d_in[1];
    const float* eps  = (const float*)d_in[2];
    const float* W1   = (const float*)d_in[3];
    const float* b1   = (const float*)d_in[4];
    const float* bn1g = (const float*)d_in[5];
    const float* bn1b = (const float*)d_in[6];
    const float* W2   = (const float*)d_in[7];
    const float* b2   = (const float*)d_in[8];
    const float* bn2g = (const float*)d_in[9];
    const float* bn2b = (const float*)d_in[10];

    float *y1p, *y2p, *statsp;
    unsigned short *whip, *wlop;
    cudaGetSymbolAddress((void**)&y1p,    g_y1);
    cudaGetSymbolAddress((void**)&y2p,    g_y2);
    cudaGetSymbolAddress((void**)&statsp, g_stats);
    cudaGetSymbolAddress((void**)&whip,   g_whi);
    cudaGetSymbolAddress((void**)&wlop,   g_wlo);

    cudaFuncSetAttribute((const void*)gemm_tc_k<1, 0>, cudaFuncAttributeMaxDynamicSharedMemorySize, GEMM_SMEM);
    cudaFuncSetAttribute((const void*)gemm_tc_k<1, 1>, cudaFuncAttributeMaxDynamicSharedMemorySize, GEMM_SMEM);
    cudaFuncSetAttribute((const void*)gemm_tc_k<2, 0>, cudaFuncAttributeMaxDynamicSharedMemorySize, GEMM_SMEM);

    // one-time prep (also zeroes all 6 stat banks — first kernel of every replay)
    wprep_k<<<384, 256>>>(W1, W2, ei32);
    count_k<<<3125, 256>>>(ei32);
    scan1_k<<<49, 1024>>>();
    scan3_k<<<49, 1024>>>();
    fill_k<<<3125, 256>>>(ei32);

    for (int l = 0; l < 3; l++) {
        float* bank1 = statsp + (size_t)(2 * l) * 256;       // gemm1 stats
        float* bank2 = statsp + (size_t)(2 * l + 1) * 256;   // gemm2 stats
        if (l == 0) {
            q_k<0><<<3125, 256>>>(x, nullptr, nullptr, nullptr);
            agg_k<<<6250, 256>>>();
            gemm_tc_k<1, 0><<<GEMM_GRID, 256, GEMM_SMEM>>>(x, eps, l,
                whip + (size_t)l * 16384, wlop + (size_t)l * 16384,
                b1 + (size_t)l * DD, y1p, bank1, nullptr, nullptr, nullptr);
        } else {
            // q applies the PREVIOUS layer's outer BN inline (bank 2(l-1)+1)
            q_k<1><<<3125, 256>>>(y2p, statsp + (size_t)(2 * l - 1) * 256,
                                  bn2g + (size_t)(l - 1) * DD, bn2b + (size_t)(l - 1) * DD);
            agg_k<<<6250, 256>>>();
            gemm_tc_k<1, 1><<<GEMM_GRID, 256, GEMM_SMEM>>>(y2p, eps, l,
                whip + (size_t)l * 16384, wlop + (size_t)l * 16384,
                b1 + (size_t)l * DD, y1p, bank1, nullptr, nullptr, nullptr);
        }
        gemm_tc_k<2, 0><<<GEMM_GRID, 256, GEMM_SMEM>>>(y1p, eps, l,
            whip + (size_t)(3 + l) * 16384, wlop + (size_t)(3 + l) * 16384,
            b2 + (size_t)l * DD, y2p, bank2,
            bank1, bn1g + (size_t)l * DD, bn1b + (size_t)l * DD);
    }
    finalize_k<<<6250, 256>>>((float*)d_out, statsp + 5 * 256,
                              bn2g + (size_t)2 * DD, bn2b + (size_t)2 * DD);
}

// round 15
// speedup vs baseline: 1.4135x; 1.0143x over previous
#include <cuda_runtime.h>
#include <cuda_bf16.h>
#include <cuda_fp16.h>
#include <cstdint>

#define NN 50000
#define DD 128
#define EE 800000
#define NTILES 391
#define GEMM_GRID 148

// ---------------- scratch (static device globals: no allocation) ----------------
__device__ __align__(16) float g_agg[NN * DD];
__device__ __align__(16) float g_y1[NN * DD];
__device__ __align__(16) float g_y2[NN * DD];
__device__ __align__(16) unsigned short g_hf[NN * DD];   // fp16 gather image
__device__ __align__(16) float g_stats[1536];  // 6 banks x 256; zeroed by prep (invariant)
__device__ int g_is64;
__device__ __align__(16) unsigned short g_whi[6 * DD * DD];
__device__ __align__(16) unsigned short g_wlo[6 * DD * DD];
__device__ int g_deg[50176];     // zero at prep entry (zeroed by fill_k each replay)
__device__ int g_scan[50176];
__device__ int g_off[50176];
__device__ int g_cursor[50176];
__device__ int g_bsum[64];
__device__ int g_srcs[EE];

__device__ __forceinline__ uint32_t smem_to_u32(const void* p) {
    uint32_t a;
    asm("{ .reg .u64 t; cvta.to.shared.u64 t, %1; cvt.u32.u64 %0, t; }" : "=r"(a) : "l"(p));
    return a;
}

#define LDMX4(r0, r1, r2, r3, addr) \
    asm volatile("ldmatrix.sync.aligned.m8n8.x4.shared.b16 {%0,%1,%2,%3}, [%4];" \
                 : "=r"(r0), "=r"(r1), "=r"(r2), "=r"(r3) : "r"(addr))

#define MMA16816(d, a, b) \
    asm volatile("mma.sync.aligned.m16n8k16.row.col.f32.bf16.bf16.f32 " \
                 "{%0,%1,%2,%3}, {%4,%5,%6,%7}, {%8,%9}, {%0,%1,%2,%3};" \
                 : "+f"((d)[0]), "+f"((d)[1]), "+f"((d)[2]), "+f"((d)[3]) \
                 : "r"((a)[0]), "r"((a)[1]), "r"((a)[2]), "r"((a)[3]), "r"((b)[0]), "r"((b)[1]))

// BN scale/shift from a stats bank (tid < 128 computes into smem arrays)
__device__ __forceinline__ void bn_inline(int tid, const float* statIn,
                                          const float* bnG, const float* bnB,
                                          float* sN, float* tN)
{
    if (tid < 128) {
        float mu  = statIn[tid] * (1.0f / NN);
        float var = statIn[128 + tid] * (1.0f / NN) - mu * mu;
        float sc  = bnG[tid] * rsqrtf(var + 1e-5f);
        sN[tid] = sc;
        tN[tid] = bnB[tid] - mu * sc;
    }
}

// per-thread edge_index dtype detect (broadcast loads, L1-hot)
__device__ __forceinline__ int detect_is64(const int* __restrict__ ei32) {
    int is64 = 1;
#pragma unroll
    for (int i = 0; i < 8; i++)
        if (ei32[2 * i + 1] != 0) is64 = 0;
    return is64;
}

// ===== mega-prep: weights+stats-zero | edge count | layer-0 quantize — ONE kernel =====
// blocks [0,384): weight prep (+deg-range stats zero + g_is64 publish)
// blocks [384, 3509): count edges (per-thread dtype detect; g_deg pre-zeroed invariant)
// blocks [3509, 6634): quantize x -> g_hf
__global__ void prep_k(const float* __restrict__ W1, const float* __restrict__ W2,
                       const int* __restrict__ ei32, const float* __restrict__ x)
{
    int b = blockIdx.x;
    int tid = threadIdx.x;
    if (b < 384) {
        int wi = b >> 6;
        int id = ((b & 63) << 8) + tid;
        const float* W = (wi < 3) ? (W1 + (size_t)wi * 16384) : (W2 + (size_t)(wi - 3) * 16384);
        int k = id >> 7, n = id & 127;
        float v = W[k * 128 + n];
        __nv_bfloat16 hb = __float2bfloat16(v);
        __nv_bfloat16 lb = __float2bfloat16(v - __bfloat162float(hb));
        g_whi[(size_t)wi * 16384 + n * 128 + k] = __bfloat16_as_ushort(hb);
        g_wlo[(size_t)wi * 16384 + n * 128 + k] = __bfloat16_as_ushort(lb);
        if (b < 6) g_stats[b * 256 + tid] = 0.f;
        if (b == 0 && tid == 0) g_is64 = detect_is64(ei32);   // consumed by fill_k (next launch)
    } else if (b < 3509) {
        int e = (b - 384) * 256 + tid;
        if (e < EE) {
            int is64 = detect_is64(ei32);
            int d = is64 ? ei32[2 * (EE + e)] : ei32[EE + e];
            atomicAdd(&g_deg[d], 1);
        }
    } else {
        int base = ((b - 3509) * 256 + tid) * 8;
        float4 p0 = *(const float4*)(x + base);
        float4 p1 = *(const float4*)(x + base + 4);
        float v[8] = {p0.x, p0.y, p0.z, p0.w, p1.x, p1.y, p1.z, p1.w};
        unsigned short o[8];
#pragma unroll
        for (int j = 0; j < 8; j++) o[j] = __half_as_ushort(__float2half_rn(v[j]));
        uint32_t w0 = (uint32_t)o[0] | ((uint32_t)o[1] << 16);
        uint32_t w1 = (uint32_t)o[2] | ((uint32_t)o[3] << 16);
        uint32_t w2 = (uint32_t)o[4] | ((uint32_t)o[5] << 16);
        uint32_t w3 = (uint32_t)o[6] | ((uint32_t)o[7] << 16);
        *(uint4*)(g_hf + base) = make_uint4(w0, w1, w2, w3);
    }
}

// ================= CSR scan + fill =================
__global__ void scan1_k() {                 // 49 x 1024
    __shared__ int sm[1024];
    int t = threadIdx.x;
    int gid = blockIdx.x * 1024 + t;
    int v = (gid < NN) ? g_deg[gid] : 0;
    sm[t] = v;
    __syncthreads();
    for (int o = 1; o < 1024; o <<= 1) {
        int tv = (t >= o) ? sm[t - o] : 0;
        __syncthreads();
        sm[t] += tv;
        __syncthreads();
    }
    g_scan[gid] = sm[t] - v;
    if (t == 1023) g_bsum[blockIdx.x] = sm[1023];
}
__global__ void scan3_k() {                 // 49 x 1024; block prefix from g_bsum inline
    __shared__ int sb[64];
    int t = threadIdx.x;
    if (t < 64) sb[t] = (t < blockIdx.x && t < 49) ? g_bsum[t] : 0;
    __syncthreads();
    if (t < 32) sb[t] += sb[t + 32];
    __syncthreads();
    if (t < 16) sb[t] += sb[t + 16];
    __syncthreads();
    if (t < 8) sb[t] += sb[t + 8];
    __syncthreads();
    if (t < 4) sb[t] += sb[t + 4];
    __syncthreads();
    if (t < 2) sb[t] += sb[t + 2];
    __syncthreads();
    if (t == 0) sb[0] += sb[1];
    __syncthreads();
    int gid = blockIdx.x * 1024 + t;
    int o = g_scan[gid] + sb[0];
    g_off[gid] = o;
    g_cursor[gid] = o;
}
// fill also re-zeroes g_deg (scan done with it) to restore the prep-entry invariant
__global__ void fill_k(const int* __restrict__ ei32) {    // 3125 x 256
    int e = blockIdx.x * 256 + threadIdx.x;
    if (e < 50176) g_deg[e] = 0;
    if (e >= EE) return;
    int s, d;
    if (g_is64) { s = ei32[2 * e]; d = ei32[2 * (EE + e)]; }
    else        { s = ei32[e];     d = ei32[EE + e]; }
    int pos = atomicAdd(&g_cursor[d], 1);
    g_srcs[pos] = s;
}

// --------- quantize y2 with prev outer BN (layers 1,2) ---------
__global__ void q_k(const float* __restrict__ P,
                    const float* __restrict__ statIn,
                    const float* __restrict__ bnG, const float* __restrict__ bnB)
{
    __shared__ float sN[128], tN[128];
    int tid = threadIdx.x;
    bn_inline(tid, statIn, bnG, bnB, sN, tN);
    __syncthreads();
    int base = (blockIdx.x * 256 + tid) * 8;
    int col = base & 127;
    float4 p0 = *(const float4*)(P + base);
    float4 p1 = *(const float4*)(P + base + 4);
    float v[8] = {p0.x, p0.y, p0.z, p0.w, p1.x, p1.y, p1.z, p1.w};
#pragma unroll
    for (int j = 0; j < 8; j++)
        v[j] = fmaxf(fmaf(v[j], sN[col + j], tN[col + j]), 0.f);
    unsigned short o[8];
#pragma unroll
    for (int j = 0; j < 8; j++) o[j] = __half_as_ushort(__float2half_rn(v[j]));
    uint32_t w0 = (uint32_t)o[0] | ((uint32_t)o[1] << 16);
    uint32_t w1 = (uint32_t)o[2] | ((uint32_t)o[3] << 16);
    uint32_t w2 = (uint32_t)o[4] | ((uint32_t)o[5] << 16);
    uint32_t w3 = (uint32_t)o[6] | ((uint32_t)o[7] << 16);
    *(uint4*)(g_hf + base) = make_uint4(w0, w1, w2, w3);
}

// ------- aggregation: fp16 gather + fp32 register sum (relu on the fly) ----
__device__ __forceinline__ void add4(float* acc, uint2 q) {
    float2 f0 = __half22float2(*(__half2*)&q.x);
    float2 f1 = __half22float2(*(__half2*)&q.y);
    acc[0] += fmaxf(f0.x, 0.f);
    acc[1] += fmaxf(f0.y, 0.f);
    acc[2] += fmaxf(f1.x, 0.f);
    acc[3] += fmaxf(f1.y, 0.f);
}
__global__ void __launch_bounds__(256) agg_k() {
    int w = blockIdx.x * 8 + (threadIdx.x >> 5);  // 6250 blocks -> 50000 warps
    int lane = threadIdx.x & 31;
    int s = g_off[w], t = g_off[w + 1];
    const unsigned short* H = g_hf;
    int lc = lane * 4;                            // 4 halves/lane; warp covers a row
    float acc[4] = {0.f, 0.f, 0.f, 0.f};
    int e = s;
    for (; e + 3 < t; e += 4) {
        int s0 = g_srcs[e], s1 = g_srcs[e + 1], s2i = g_srcs[e + 2], s3 = g_srcs[e + 3];
        uint2 q0 = *(const uint2*)(H + (size_t)s0 * DD + lc);
        uint2 q1 = *(const uint2*)(H + (size_t)s1 * DD + lc);
        uint2 q2 = *(const uint2*)(H + (size_t)s2i * DD + lc);
        uint2 q3 = *(const uint2*)(H + (size_t)s3 * DD + lc);
        add4(acc, q0); add4(acc, q1); add4(acc, q2); add4(acc, q3);
    }
    for (; e < t; e++) {
        int s0 = g_srcs[e];
        uint2 q0 = *(const uint2*)(H + (size_t)s0 * DD + lc);
        add4(acc, q0);
    }
    *(float4*)(g_agg + (size_t)w * DD + lc) = make_float4(acc[0], acc[1], acc[2], acc[3]);
}

// ---------------- persistent HMMA GEMM (grid-stride over 391 tiles) ----------------
// MODE 1: A = (1+eps)*own + agg ; own = A0 fp32 (TRANS=0) or g_hf fp16 (TRANS=1)
// MODE 2: A = relu(y1*s1+t1), s1/t1 inline from statIn + bn params
#define TSTRIDE 136
#define TBYTES  (128 * TSTRIDE * 2)
#define BIAS_OFF 0
#define AHI_OFF  1024
#define ALO_OFF  (AHI_OFF + TBYTES)
#define BHI_OFF  (ALO_OFF + TBYTES)
#define BLO_OFF  (BHI_OFF + TBYTES)
#define STAT_OFF (BLO_OFF + TBYTES)
#define SN_OFF   (STAT_OFF + 1024)
#define GEMM_SMEM (SN_OFF + 1024)

template <int MODE, int TRANS>
__global__ void __launch_bounds__(256, 1) gemm_tc_k(
    const float* __restrict__ A0, const float* __restrict__ epsp, int layer,
    const unsigned short* __restrict__ whi, const unsigned short* __restrict__ wlo,
    const float* __restrict__ bias, float* __restrict__ Y,
    float* __restrict__ statOut,
    const float* __restrict__ statIn, const float* __restrict__ bnG, const float* __restrict__ bnB)
{
    extern __shared__ __align__(16) char smem[];
    uint32_t sb = smem_to_u32(smem);
    int tid = threadIdx.x;
    int wid = tid >> 5, lane = tid & 31;

    if (tid < 128) *(float*)(smem + BIAS_OFF + tid * 4) = bias[tid];
    ((float*)(smem + STAT_OFF))[tid] = 0.f;

    float* sN = (float*)(smem + SN_OFF);   // inline s1/t1 for MODE 2
    float* tN = sN + 128;
    if (MODE == 2) bn_inline(tid, statIn, bnG, bnB, sN, tN);
    __syncthreads();   // sN/tN + bias visible to ALL threads before first A-transform

    // ---- B tiles: loaded ONCE per block ----
    {
        const uint4* sh = (const uint4*)whi;
        const uint4* sl = (const uint4*)wlo;
#pragma unroll
        for (int i = 0; i < 8; i++) {
            int id = i * 256 + tid;
            int r = id >> 4, c16 = id & 15;
            uint32_t dst = (uint32_t)(r * (TSTRIDE * 2) + c16 * 16);
            *(uint4*)(smem + BHI_OFF + dst) = sh[id];
            *(uint4*)(smem + BLO_OFF + dst) = sl[id];
        }
    }

    float epsv = (MODE == 1) ? (1.0f + epsp[layer]) : 0.0f;
    int wm = wid & 1, wn = wid >> 1;
    int m0 = wm * 64, n0 = wn * 32;
    uint32_t aOff = (uint32_t)((m0 + (lane & 15)) * (TSTRIDE * 2) + (lane >> 4) * 16);
    uint32_t bOff = (uint32_t)((n0 + (lane & 7) + (lane >> 4) * 8) * (TSTRIDE * 2) + ((lane >> 3) & 1) * 16);
    int rq = lane >> 2, cq = (lane & 3) * 2;

    // BN stats: accumulate in registers across tiles, flush once at end
    float ps[4][2], pq[4][2];
#pragma unroll
    for (int j = 0; j < 4; j++) { ps[j][0] = ps[j][1] = 0.f; pq[j][0] = pq[j][1] = 0.f; }

    for (int tile = blockIdx.x; tile < NTILES; tile += gridDim.x) {
        int rowBase = tile * 128;

        // ---- A tile: fused transform + bf16 split ----
#pragma unroll
        for (int it = 0; it < 8; it++) {
            int id = it * 256 + tid;
            int row = id >> 4;
            int col = (id & 15) * 8;
            int gr = rowBase + row;
            float v[8];
#pragma unroll
            for (int j = 0; j < 8; j++) v[j] = 0.f;
            if (gr < NN) {
                if (MODE == 1) {
                    float own[8];
                    if (TRANS) {
                        uint4 q = *(const uint4*)(g_hf + (size_t)gr * DD + col);
                        __half2* hp = (__half2*)&q;
#pragma unroll
                        for (int j = 0; j < 4; j++) {
                            float2 f = __half22float2(hp[j]);
                            own[2 * j] = f.x;
                            own[2 * j + 1] = f.y;
                        }
                    } else {
                        float4 p0 = *(const float4*)(A0 + (size_t)gr * DD + col);
                        float4 p1 = *(const float4*)(A0 + (size_t)gr * DD + col + 4);
                        own[0] = p0.x; own[1] = p0.y; own[2] = p0.z; own[3] = p0.w;
                        own[4] = p1.x; own[5] = p1.y; own[6] = p1.z; own[7] = p1.w;
                    }
                    float4 a0 = *(const float4*)(g_agg + (size_t)gr * DD + col);
                    float4 a1 = *(const float4*)(g_agg + (size_t)gr * DD + col + 4);
                    v[0] = fmaf(epsv, own[0], a0.x); v[1] = fmaf(epsv, own[1], a0.y);
                    v[2] = fmaf(epsv, own[2], a0.z); v[3] = fmaf(epsv, own[3], a0.w);
                    v[4] = fmaf(epsv, own[4], a1.x); v[5] = fmaf(epsv, own[5], a1.y);
                    v[6] = fmaf(epsv, own[6], a1.z); v[7] = fmaf(epsv, own[7], a1.w);
                } else {
                    float4 p0 = *(const float4*)(A0 + (size_t)gr * DD + col);
                    float4 p1 = *(const float4*)(A0 + (size_t)gr * DD + col + 4);
                    v[0] = p0.x; v[1] = p0.y; v[2] = p0.z; v[3] = p0.w;
                    v[4] = p1.x; v[5] = p1.y; v[6] = p1.z; v[7] = p1.w;
#pragma unroll
                    for (int j = 0; j < 8; j++)
                        v[j] = fmaxf(fmaf(v[j], sN[col + j], tN[col + j]), 0.f);
                }
            }
            uint32_t h[4], l[4];
#pragma unroll
            for (int j = 0; j < 4; j++) {
                __nv_bfloat16 h0 = __float2bfloat16(v[2 * j]);
                __nv_bfloat16 h1 = __float2bfloat16(v[2 * j + 1]);
                __nv_bfloat16 l0 = __float2bfloat16(v[2 * j] - __bfloat162float(h0));
                __nv_bfloat16 l1 = __float2bfloat16(v[2 * j + 1] - __bfloat162float(h1));
                h[j] = ((uint32_t)__bfloat16_as_ushort(h1) << 16) | __bfloat16_as_ushort(h0);
                l[j] = ((uint32_t)__bfloat16_as_ushort(l1) << 16) | __bfloat16_as_ushort(l0);
            }
            uint32_t off = (uint32_t)(row * (TSTRIDE * 2) + col * 2);
            *(uint4*)(smem + AHI_OFF + off) = make_uint4(h[0], h[1], h[2], h[3]);
            *(uint4*)(smem + ALO_OFF + off) = make_uint4(l[0], l[1], l[2], l[3]);
        }
        __syncthreads();

        // ---- warp MMA mainloop ----
        float acc[4][4][4];
#pragma unroll
        for (int i = 0; i < 4; i++)
#pragma unroll
            for (int j = 0; j < 4; j++)
#pragma unroll
                for (int q = 0; q < 4; q++) acc[i][j][q] = 0.f;

#pragma unroll
        for (int ks = 0; ks < 8; ks++) {
            uint32_t kByte = (uint32_t)(ks * 32);
            uint32_t ah[4][4], al[4][4], bh[4][2], bl[4][2];
#pragma unroll
            for (int i = 0; i < 4; i++) {
                uint32_t ad = sb + AHI_OFF + aOff + kByte + (uint32_t)(i * 16 * TSTRIDE * 2);
                LDMX4(ah[i][0], ah[i][1], ah[i][2], ah[i][3], ad);
            }
#pragma unroll
            for (int i = 0; i < 4; i++) {
                uint32_t ad = sb + ALO_OFF + aOff + kByte + (uint32_t)(i * 16 * TSTRIDE * 2);
                LDMX4(al[i][0], al[i][1], al[i][2], al[i][3], ad);
            }
#pragma unroll
            for (int jj = 0; jj < 2; jj++) {
                uint32_t bd = sb + BHI_OFF + bOff + kByte + (uint32_t)(jj * 16 * TSTRIDE * 2);
                uint32_t r0, r1, r2, r3;
                LDMX4(r0, r1, r2, r3, bd);
                bh[2 * jj][0] = r0; bh[2 * jj][1] = r1;
                bh[2 * jj + 1][0] = r2; bh[2 * jj + 1][1] = r3;
                bd = sb + BLO_OFF + bOff + kByte + (uint32_t)(jj * 16 * TSTRIDE * 2);
                LDMX4(r0, r1, r2, r3, bd);
                bl[2 * jj][0] = r0; bl[2 * jj][1] = r1;
                bl[2 * jj + 1][0] = r2; bl[2 * jj + 1][1] = r3;
            }
#pragma unroll
            for (int i = 0; i < 4; i++)
#pragma unroll
                for (int j = 0; j < 4; j++) MMA16816(acc[i][j], ah[i], bh[j]);
#pragma unroll
            for (int i = 0; i < 4; i++)
#pragma unroll
                for (int j = 0; j < 4; j++) MMA16816(acc[i][j], ah[i], bl[j]);
#pragma unroll
            for (int i = 0; i < 4; i++)
#pragma unroll
                for (int j = 0; j < 4; j++) MMA16816(acc[i][j], al[i], bh[j]);
        }

        // ---- epilogue: bias, store, accumulate BN stats into regs ----
        const float* bs = (const float*)(smem + BIAS_OFF);
#pragma unroll
        for (int i = 0; i < 4; i++) {
            int r0g = rowBase + m0 + i * 16 + rq;
#pragma unroll
            for (int j = 0; j < 4; j++) {
                int cg = n0 + j * 8 + cq;
                float bx = bs[cg], by = bs[cg + 1];
                if (r0g < NN) {
                    float v0 = acc[i][j][0] + bx, v1 = acc[i][j][1] + by;
                    *(float2*)(Y + (size_t)r0g * DD + cg) = make_float2(v0, v1);
                    ps[j][0] += v0; pq[j][0] += v0 * v0;
                    ps[j][1] += v1; pq[j][1] += v1 * v1;
                }
                if (r0g + 8 < NN) {
                    float v2 = acc[i][j][2] + bx, v3 = acc[i][j][3] + by;
                    *(float2*)(Y + (size_t)(r0g + 8) * DD + cg) = make_float2(v2, v3);
                    ps[j][0] += v2; pq[j][0] += v2 * v2;
                    ps[j][1] += v3; pq[j][1] += v3 * v3;
                }
            }
        }
        __syncthreads();   // mainloop reads done before next tile's A-store
    }

    // ---- one-time stats flush ----
    float* scs = (float*)(smem + STAT_OFF);
    float* scq = scs + 128;
#pragma unroll
    for (int j = 0; j < 4; j++)
#pragma unroll
        for (int c = 0; c < 2; c++) {
#pragma unroll
            for (int m = 4; m <= 16; m <<= 1) {
                ps[j][c] += __shfl_xor_sync(0xFFFFFFFFu, ps[j][c], m);
                pq[j][c] += __shfl_xor_sync(0xFFFFFFFFu, pq[j][c], m);
            }
        }
    if (rq == 0) {
#pragma unroll
        for (int j = 0; j < 4; j++)
#pragma unroll
            for (int c = 0; c < 2; c++) {
                atomicAdd(&scs[n0 + j * 8 + cq + c], ps[j][c]);
                atomicAdd(&scq[n0 + j * 8 + cq + c], pq[j][c]);
            }
    }
    __syncthreads();
    if (tid < 128) {
        atomicAdd(&statOut[tid],       scs[tid]);
        atomicAdd(&statOut[128 + tid], scq[tid]);
    }
}

// ---------------- final output: out = y2*s2+t2, s2/t2 inline from last bank ----------
__global__ void finalize_k(float* __restrict__ out,
                           const float* __restrict__ statIn,
                           const float* __restrict__ bnG, const float* __restrict__ bnB)
{
    __shared__ float sN[128], tN[128];
    int tid = threadIdx.x;
    bn_inline(tid, statIn, bnG, bnB, sN, tN);
    __syncthreads();
    int i = blockIdx.x * 256 + tid;
    int d4 = (i * 4) & 127;
    float4 v = ((const float4*)g_y2)[i];
    v.x = fmaf(v.x, sN[d4],     tN[d4]);
    v.y = fmaf(v.y, sN[d4 + 1], tN[d4 + 1]);
    v.z = fmaf(v.z, sN[d4 + 2], tN[d4 + 2]);
    v.w = fmaf(v.w, sN[d4 + 3], tN[d4 + 3]);
    ((float4*)out)[i] = v;
}

extern "C" void kernel_launch(void* const* d_in, const int* in_sizes, int n_in,
                              void* d_out, int out_size)
{
    const float* x    = (const float*)d_in[0];
    const int*   ei32 = (const int*)d_in[1];
    const float* eps  = (const float*)d_in[2];
    const float* W1   = (const float*)d_in[3];
    const float* b1   = (const float*)d_in[4];
    const float* bn1g = (const float*)d_in[5];
    const float* bn1b = (const float*)d_in[6];
    const float* W2   = (const float*)d_in[7];
    const float* b2   = (const float*)d_in[8];
    const float* bn2g = (const float*)d_in[9];
    const float* bn2b = (const float*)d_in[10];

    float *y1p, *y2p, *statsp;
    unsigned short *whip, *wlop;
    cudaGetSymbolAddress((void**)&y1p,    g_y1);
    cudaGetSymbolAddress((void**)&y2p,    g_y2);
    cudaGetSymbolAddress((void**)&statsp, g_stats);
    cudaGetSymbolAddress((void**)&whip,   g_whi);
    cudaGetSymbolAddress((void**)&wlop,   g_wlo);

    cudaFuncSetAttribute((const void*)gemm_tc_k<1, 0>, cudaFuncAttributeMaxDynamicSharedMemorySize, GEMM_SMEM);
    cudaFuncSetAttribute((const void*)gemm_tc_k<1, 1>, cudaFuncAttributeMaxDynamicSharedMemorySize, GEMM_SMEM);
    cudaFuncSetAttribute((const void*)gemm_tc_k<2, 0>, cudaFuncAttributeMaxDynamicSharedMemorySize, GEMM_SMEM);

    // mega-prep: weights + stats-zero + edge count + layer-0 quantize (g_deg zero invariant)
    prep_k<<<6634, 256>>>(W1, W2, ei32, x);
    scan1_k<<<49, 1024>>>();
    scan3_k<<<49, 1024>>>();
    fill_k<<<3125, 256>>>(ei32);   // also re-zeroes g_deg for next replay

    for (int l = 0; l < 3; l++) {
        float* bank1 = statsp + (size_t)(2 * l) * 256;       // gemm1 stats
        float* bank2 = statsp + (size_t)(2 * l + 1) * 256;   // gemm2 stats
        if (l == 0) {
            agg_k<<<6250, 256>>>();
            gemm_tc_k<1, 0><<<GEMM_GRID, 256, GEMM_SMEM>>>(x, eps, l,
                whip + (size_t)l * 16384, wlop + (size_t)l * 16384,
                b1 + (size_t)l * DD, y1p, bank1, nullptr, nullptr, nullptr);
        } else {
            // q applies the PREVIOUS layer's outer BN inline (bank 2(l-1)+1)
            q_k<<<3125, 256>>>(y2p, statsp + (size_t)(2 * l - 1) * 256,
                               bn2g + (size_t)(l - 1) * DD, bn2b + (size_t)(l - 1) * DD);
            agg_k<<<6250, 256>>>();
            gemm_tc_k<1, 1><<<GEMM_GRID, 256, GEMM_SMEM>>>(y2p, eps, l,
                whip + (size_t)l * 16384, wlop + (size_t)l * 16384,
                b1 + (size_t)l * DD, y1p, bank1, nullptr, nullptr, nullptr);
        }
        gemm_tc_k<2, 0><<<GEMM_GRID, 256, GEMM_SMEM>>>(y1p, eps, l,
            whip + (size_t)(3 + l) * 16384, wlop + (size_t)(3 + l) * 16384,
            b2 + (size_t)l * DD, y2p, bank2,
            bank1, bn1g + (size_t)l * DD, bn1b + (size_t)l * DD);
    }
    finalize_k<<<6250, 256>>>((float*)d_out, statsp + 5 * 256,
                              bn2g + (size_t)2 * DD, bn2b + (size_t)2 * DD);
}

// round 16
// speedup vs baseline: 1.4700x; 1.0400x over previous
#include <cuda_runtime.h>
#include <cuda_bf16.h>
#include <cuda_fp16.h>
#include <cstdint>

#define NN 50000
#define DD 128
#define EE 800000
#define NTILES 391
#define GEMM_GRID 148

// ---------------- scratch (static device globals: no allocation) ----------------
__device__ __align__(16) float g_y1[NN * DD];
__device__ __align__(16) float g_y2[NN * DD];
__device__ __align__(16) unsigned short g_hf[NN * DD];    // fp16 gather image
__device__ __align__(16) unsigned short g_ahi[NN * DD];   // pre-split GEMM1 A (hi)
__device__ __align__(16) unsigned short g_alo[NN * DD];   // pre-split GEMM1 A (lo)
__device__ __align__(16) float g_stats[1536];  // 6 banks x 256; zeroed by prep (invariant)
__device__ int g_is64;
__device__ __align__(16) unsigned short g_whi[6 * DD * DD];
__device__ __align__(16) unsigned short g_wlo[6 * DD * DD];
__device__ int g_deg[50176];     // zero at prep entry (re-zeroed by fill_k)
__device__ int g_off[50176];
__device__ int g_cursor[50176];
__device__ int g_flag[64];       // lookback flags: zero at scan entry (re-zeroed by fill_k)
__device__ int g_srcs[EE];

__device__ __forceinline__ uint32_t smem_to_u32(const void* p) {
    uint32_t a;
    asm("{ .reg .u64 t; cvta.to.shared.u64 t, %1; cvt.u32.u64 %0, t; }" : "=r"(a) : "l"(p));
    return a;
}

#define LDMX4(r0, r1, r2, r3, addr) \
    asm volatile("ldmatrix.sync.aligned.m8n8.x4.shared.b16 {%0,%1,%2,%3}, [%4];" \
                 : "=r"(r0), "=r"(r1), "=r"(r2), "=r"(r3) : "r"(addr))

#define MMA16816(d, a, b) \
    asm volatile("mma.sync.aligned.m16n8k16.row.col.f32.bf16.bf16.f32 " \
                 "{%0,%1,%2,%3}, {%4,%5,%6,%7}, {%8,%9}, {%0,%1,%2,%3};" \
                 : "+f"((d)[0]), "+f"((d)[1]), "+f"((d)[2]), "+f"((d)[3]) \
                 : "r"((a)[0]), "r"((a)[1]), "r"((a)[2]), "r"((a)[3]), "r"((b)[0]), "r"((b)[1]))

// BN scale/shift from a stats bank (tid < 128 computes into smem arrays)
__device__ __forceinline__ void bn_inline(int tid, const float* statIn,
                                          const float* bnG, const float* bnB,
                                          float* sN, float* tN)
{
    if (tid < 128) {
        float mu  = statIn[tid] * (1.0f / NN);
        float var = statIn[128 + tid] * (1.0f / NN) - mu * mu;
        float sc  = bnG[tid] * rsqrtf(var + 1e-5f);
        sN[tid] = sc;
        tN[tid] = bnB[tid] - mu * sc;
    }
}

__device__ __forceinline__ int detect_is64(const int* __restrict__ ei32) {
    int is64 = 1;
#pragma unroll
    for (int i = 0; i < 8; i++)
        if (ei32[2 * i + 1] != 0) is64 = 0;
    return is64;
}

// ===== mega-prep: weights+stats-zero | edge count | layer-0 quantize — ONE kernel =====
__global__ void prep_k(const float* __restrict__ W1, const float* __restrict__ W2,
                       const int* __restrict__ ei32, const float* __restrict__ x)
{
    int b = blockIdx.x;
    int tid = threadIdx.x;
    if (b < 384) {
        int wi = b >> 6;
        int id = ((b & 63) << 8) + tid;
        const float* W = (wi < 3) ? (W1 + (size_t)wi * 16384) : (W2 + (size_t)(wi - 3) * 16384);
        int k = id >> 7, n = id & 127;
        float v = W[k * 128 + n];
        __nv_bfloat16 hb = __float2bfloat16(v);
        __nv_bfloat16 lb = __float2bfloat16(v - __bfloat162float(hb));
        g_whi[(size_t)wi * 16384 + n * 128 + k] = __bfloat16_as_ushort(hb);
        g_wlo[(size_t)wi * 16384 + n * 128 + k] = __bfloat16_as_ushort(lb);
        if (b < 6) g_stats[b * 256 + tid] = 0.f;
        if (b == 0 && tid == 0) g_is64 = detect_is64(ei32);
    } else if (b < 3509) {
        int e = (b - 384) * 256 + tid;
        if (e < EE) {
            int is64 = detect_is64(ei32);
            int d = is64 ? ei32[2 * (EE + e)] : ei32[EE + e];
            atomicAdd(&g_deg[d], 1);
        }
    } else {
        int base = ((b - 3509) * 256 + tid) * 8;
        float4 p0 = *(const float4*)(x + base);
        float4 p1 = *(const float4*)(x + base + 4);
        float v[8] = {p0.x, p0.y, p0.z, p0.w, p1.x, p1.y, p1.z, p1.w};
        unsigned short o[8];
#pragma unroll
        for (int j = 0; j < 8; j++) o[j] = __half_as_ushort(__float2half_rn(v[j]));
        uint32_t w0 = (uint32_t)o[0] | ((uint32_t)o[1] << 16);
        uint32_t w1 = (uint32_t)o[2] | ((uint32_t)o[3] << 16);
        uint32_t w2 = (uint32_t)o[4] | ((uint32_t)o[5] << 16);
        uint32_t w3 = (uint32_t)o[6] | ((uint32_t)o[7] << 16);
        *(uint4*)(g_hf + base) = make_uint4(w0, w1, w2, w3);
    }
}

// ===== single-pass exclusive scan over 50176 degrees (decoupled lookback) =====
// 49 blocks x 1024, all co-resident (49 < 148 SMs) -> spin is deadlock-free.
__global__ void scan_k() {
    __shared__ int sm[1024];
    __shared__ int sb[64];
    int t = threadIdx.x, b = blockIdx.x;
    int gid = b * 1024 + t;
    int v = (gid < NN) ? g_deg[gid] : 0;
    sm[t] = v;
    __syncthreads();
    for (int o = 1; o < 1024; o <<= 1) {
        int tv = (t >= o) ? sm[t - o] : 0;
        __syncthreads();
        sm[t] += tv;
        __syncthreads();
    }
    if (t == 1023) atomicExch(&g_flag[b], sm[1023] + 1);  // publish total (+1 = flag)
    if (t < 64) sb[t] = 0;
    __syncthreads();
    if (t < b) {                                          // t in [0,48]
        int f;
        do { f = atomicAdd(&g_flag[t], 0); } while (f == 0);
        sb[t] = f - 1;
    }
    __syncthreads();
    if (t < 32) sb[t] += sb[t + 32];
    __syncthreads();
    if (t < 16) sb[t] += sb[t + 16];
    __syncthreads();
    if (t < 8) sb[t] += sb[t + 8];
    __syncthreads();
    if (t < 4) sb[t] += sb[t + 4];
    __syncthreads();
    if (t < 2) sb[t] += sb[t + 2];
    __syncthreads();
    if (t == 0) sb[0] += sb[1];
    __syncthreads();
    int o = sb[0] + sm[t] - v;                            // global exclusive prefix
    g_off[gid] = o;
    g_cursor[gid] = o;
}

// fill: scatter srcs; restore g_deg/g_flag zero invariants (scan has consumed them)
__global__ void fill_k(const int* __restrict__ ei32) {    // 3125 x 256
    int e = blockIdx.x * 256 + threadIdx.x;
    if (e < 50176) g_deg[e] = 0;
    if (e < 64) g_flag[e] = 0;
    if (e >= EE) return;
    int s, d;
    if (g_is64) { s = ei32[2 * e]; d = ei32[2 * (EE + e)]; }
    else        { s = ei32[e];     d = ei32[EE + e]; }
    int pos = atomicAdd(&g_cursor[d], 1);
    g_srcs[pos] = s;
}

// --------- quantize y2 with prev outer BN (layers 1,2) ---------
__global__ void q_k(const float* __restrict__ P,
                    const float* __restrict__ statIn,
                    const float* __restrict__ bnG, const float* __restrict__ bnB)
{
    __shared__ float sN[128], tN[128];
    int tid = threadIdx.x;
    bn_inline(tid, statIn, bnG, bnB, sN, tN);
    __syncthreads();
    int base = (blockIdx.x * 256 + tid) * 8;
    int col = base & 127;
    float4 p0 = *(const float4*)(P + base);
    float4 p1 = *(const float4*)(P + base + 4);
    float v[8] = {p0.x, p0.y, p0.z, p0.w, p1.x, p1.y, p1.z, p1.w};
#pragma unroll
    for (int j = 0; j < 8; j++)
        v[j] = fmaxf(fmaf(v[j], sN[col + j], tN[col + j]), 0.f);
    unsigned short o[8];
#pragma unroll
    for (int j = 0; j < 8; j++) o[j] = __half_as_ushort(__float2half_rn(v[j]));
    uint32_t w0 = (uint32_t)o[0] | ((uint32_t)o[1] << 16);
    uint32_t w1 = (uint32_t)o[2] | ((uint32_t)o[3] << 16);
    uint32_t w2 = (uint32_t)o[4] | ((uint32_t)o[5] << 16);
    uint32_t w3 = (uint32_t)o[6] | ((uint32_t)o[7] << 16);
    *(uint4*)(g_hf + base) = make_uint4(w0, w1, w2, w3);
}

// ------- aggregation + GIN combine + bf16 split: writes GEMM-ready A images -------
// TRANS=0: own = x fp32 ; TRANS=1: own = g_hf (already BN'd + relu'd)
__device__ __forceinline__ void add4(float* acc, uint2 q) {
    float2 f0 = __half22float2(*(__half2*)&q.x);
    float2 f1 = __half22float2(*(__half2*)&q.y);
    acc[0] += fmaxf(f0.x, 0.f);
    acc[1] += fmaxf(f0.y, 0.f);
    acc[2] += fmaxf(f1.x, 0.f);
    acc[3] += fmaxf(f1.y, 0.f);
}
template <int TRANS>
__global__ void __launch_bounds__(256) agg_k(const float* __restrict__ x,
                                             const float* __restrict__ epsp, int layer)
{
    int w = blockIdx.x * 8 + (threadIdx.x >> 5);  // 6250 blocks -> 50000 warps
    int lane = threadIdx.x & 31;
    int s = g_off[w], t = g_off[w + 1];
    const unsigned short* H = g_hf;
    int lc = lane * 4;                            // 4 halves/lane; warp covers a row
    float acc[4] = {0.f, 0.f, 0.f, 0.f};
    int e = s;
    for (; e + 3 < t; e += 4) {
        int s0 = g_srcs[e], s1 = g_srcs[e + 1], s2i = g_srcs[e + 2], s3 = g_srcs[e + 3];
        uint2 q0 = *(const uint2*)(H + (size_t)s0 * DD + lc);
        uint2 q1 = *(const uint2*)(H + (size_t)s1 * DD + lc);
        uint2 q2 = *(const uint2*)(H + (size_t)s2i * DD + lc);
        uint2 q3 = *(const uint2*)(H + (size_t)s3 * DD + lc);
        add4(acc, q0); add4(acc, q1); add4(acc, q2); add4(acc, q3);
    }
    for (; e < t; e++) {
        int s0 = g_srcs[e];
        uint2 q0 = *(const uint2*)(H + (size_t)s0 * DD + lc);
        add4(acc, q0);
    }
    // GIN combine with own row
    float epsv = 1.0f + epsp[layer];
    float own[4];
    if (TRANS) {
        uint2 q = *(const uint2*)(H + (size_t)w * DD + lc);
        float2 f0 = __half22float2(*(__half2*)&q.x);
        float2 f1 = __half22float2(*(__half2*)&q.y);
        own[0] = f0.x; own[1] = f0.y; own[2] = f1.x; own[3] = f1.y;
    } else {
        float4 p = *(const float4*)(x + (size_t)w * DD + lc);
        own[0] = p.x; own[1] = p.y; own[2] = p.z; own[3] = p.w;
    }
    unsigned short hi[4], lo[4];
#pragma unroll
    for (int j = 0; j < 4; j++) {
        float A = fmaf(epsv, own[j], acc[j]);
        __nv_bfloat16 h = __float2bfloat16(A);
        __nv_bfloat16 l = __float2bfloat16(A - __bfloat162float(h));
        hi[j] = __bfloat16_as_ushort(h);
        lo[j] = __bfloat16_as_ushort(l);
    }
    uint2 ph = make_uint2((uint32_t)hi[0] | ((uint32_t)hi[1] << 16),
                          (uint32_t)hi[2] | ((uint32_t)hi[3] << 16));
    uint2 pl = make_uint2((uint32_t)lo[0] | ((uint32_t)lo[1] << 16),
                          (uint32_t)lo[2] | ((uint32_t)lo[3] << 16));
    *(uint2*)(g_ahi + (size_t)w * DD + lc) = ph;
    *(uint2*)(g_alo + (size_t)w * DD + lc) = pl;
}

// ---------------- persistent HMMA GEMM (grid-stride over 391 tiles) ----------------
// MODE 1: A = pre-split images g_ahi/g_alo (pure copy prologue)
// MODE 2: A = relu(y1*s1+t1), s1/t1 inline from statIn + bn params (transform prologue)
#define TSTRIDE 136
#define TBYTES  (128 * TSTRIDE * 2)
#define BIAS_OFF 0
#define AHI_OFF  1024
#define ALO_OFF  (AHI_OFF + TBYTES)
#define BHI_OFF  (ALO_OFF + TBYTES)
#define BLO_OFF  (BHI_OFF + TBYTES)
#define STAT_OFF (BLO_OFF + TBYTES)
#define SN_OFF   (STAT_OFF + 1024)
#define GEMM_SMEM (SN_OFF + 1024)

template <int MODE>
__global__ void __launch_bounds__(256, 1) gemm_tc_k(
    const float* __restrict__ A0,
    const unsigned short* __restrict__ whi, const unsigned short* __restrict__ wlo,
    const float* __restrict__ bias, float* __restrict__ Y,
    float* __restrict__ statOut,
    const float* __restrict__ statIn, const float* __restrict__ bnG, const float* __restrict__ bnB)
{
    extern __shared__ __align__(16) char smem[];
    uint32_t sb = smem_to_u32(smem);
    int tid = threadIdx.x;
    int wid = tid >> 5, lane = tid & 31;

    if (tid < 128) *(float*)(smem + BIAS_OFF + tid * 4) = bias[tid];
    ((float*)(smem + STAT_OFF))[tid] = 0.f;

    float* sN = (float*)(smem + SN_OFF);   // inline s1/t1 for MODE 2
    float* tN = sN + 128;
    if (MODE == 2) bn_inline(tid, statIn, bnG, bnB, sN, tN);
    __syncthreads();

    // ---- B tiles: loaded ONCE per block ----
    {
        const uint4* sh = (const uint4*)whi;
        const uint4* sl = (const uint4*)wlo;
#pragma unroll
        for (int i = 0; i < 8; i++) {
            int id = i * 256 + tid;
            int r = id >> 4, c16 = id & 15;
            uint32_t dst = (uint32_t)(r * (TSTRIDE * 2) + c16 * 16);
            *(uint4*)(smem + BHI_OFF + dst) = sh[id];
            *(uint4*)(smem + BLO_OFF + dst) = sl[id];
        }
    }

    int wm = wid & 1, wn = wid >> 1;
    int m0 = wm * 64, n0 = wn * 32;
    uint32_t aOff = (uint32_t)((m0 + (lane & 15)) * (TSTRIDE * 2) + (lane >> 4) * 16);
    uint32_t bOff = (uint32_t)((n0 + (lane & 7) + (lane >> 4) * 8) * (TSTRIDE * 2) + ((lane >> 3) & 1) * 16);
    int rq = lane >> 2, cq = (lane & 3) * 2;

    float ps[4][2], pq[4][2];
#pragma unroll
    for (int j = 0; j < 4; j++) { ps[j][0] = ps[j][1] = 0.f; pq[j][0] = pq[j][1] = 0.f; }

    for (int tile = blockIdx.x; tile < NTILES; tile += gridDim.x) {
        int rowBase = tile * 128;

        // ---- A tile prologue ----
        if (MODE == 1) {
            // pure copy of pre-split images
#pragma unroll
            for (int it = 0; it < 8; it++) {
                int id = it * 256 + tid;
                int r = id >> 4, c16 = id & 15;
                int gr = rowBase + r;
                uint4 vh = make_uint4(0, 0, 0, 0), vl = make_uint4(0, 0, 0, 0);
                if (gr < NN) {
                    size_t so = (size_t)gr * DD + c16 * 8;
                    vh = *(const uint4*)(g_ahi + so);
                    vl = *(const uint4*)(g_alo + so);
                }
                uint32_t off = (uint32_t)(r * (TSTRIDE * 2) + c16 * 16);
                *(uint4*)(smem + AHI_OFF + off) = vh;
                *(uint4*)(smem + ALO_OFF + off) = vl;
            }
        } else {
            // transform: relu(y1*s1+t1) + bf16 split
#pragma unroll
            for (int it = 0; it < 8; it++) {
                int id = it * 256 + tid;
                int row = id >> 4;
                int col = (id & 15) * 8;
                int gr = rowBase + row;
                float v[8];
#pragma unroll
                for (int j = 0; j < 8; j++) v[j] = 0.f;
                if (gr < NN) {
                    float4 p0 = *(const float4*)(A0 + (size_t)gr * DD + col);
                    float4 p1 = *(const float4*)(A0 + (size_t)gr * DD + col + 4);
                    v[0] = p0.x; v[1] = p0.y; v[2] = p0.z; v[3] = p0.w;
                    v[4] = p1.x; v[5] = p1.y; v[6] = p1.z; v[7] = p1.w;
#pragma unroll
                    for (int j = 0; j < 8; j++)
                        v[j] = fmaxf(fmaf(v[j], sN[col + j], tN[col + j]), 0.f);
                }
                uint32_t h[4], l[4];
#pragma unroll
                for (int j = 0; j < 4; j++) {
                    __nv_bfloat16 h0 = __float2bfloat16(v[2 * j]);
                    __nv_bfloat16 h1 = __float2bfloat16(v[2 * j + 1]);
                    __nv_bfloat16 l0 = __float2bfloat16(v[2 * j] - __bfloat162float(h0));
                    __nv_bfloat16 l1 = __float2bfloat16(v[2 * j + 1] - __bfloat162float(h1));
                    h[j] = ((uint32_t)__bfloat16_as_ushort(h1) << 16) | __bfloat16_as_ushort(h0);
                    l[j] = ((uint32_t)__bfloat16_as_ushort(l1) << 16) | __bfloat16_as_ushort(l0);
                }
                uint32_t off = (uint32_t)(row * (TSTRIDE * 2) + col * 2);
                *(uint4*)(smem + AHI_OFF + off) = make_uint4(h[0], h[1], h[2], h[3]);
                *(uint4*)(smem + ALO_OFF + off) = make_uint4(l[0], l[1], l[2], l[3]);
            }
        }
        __syncthreads();

        // ---- warp MMA mainloop ----
        float acc[4][4][4];
#pragma unroll
        for (int i = 0; i < 4; i++)
#pragma unroll
            for (int j = 0; j < 4; j++)
#pragma unroll
                for (int q = 0; q < 4; q++) acc[i][j][q] = 0.f;

#pragma unroll
        for (int ks = 0; ks < 8; ks++) {
            uint32_t kByte = (uint32_t)(ks * 32);
            uint32_t ah[4][4], al[4][4], bh[4][2], bl[4][2];
#pragma unroll
            for (int i = 0; i < 4; i++) {
                uint32_t ad = sb + AHI_OFF + aOff + kByte + (uint32_t)(i * 16 * TSTRIDE * 2);
                LDMX4(ah[i][0], ah[i][1], ah[i][2], ah[i][3], ad);
            }
#pragma unroll
            for (int i = 0; i < 4; i++) {
                uint32_t ad = sb + ALO_OFF + aOff + kByte + (uint32_t)(i * 16 * TSTRIDE * 2);
                LDMX4(al[i][0], al[i][1], al[i][2], al[i][3], ad);
            }
#pragma unroll
            for (int jj = 0; jj < 2; jj++) {
                uint32_t bd = sb + BHI_OFF + bOff + kByte + (uint32_t)(jj * 16 * TSTRIDE * 2);
                uint32_t r0, r1, r2, r3;
                LDMX4(r0, r1, r2, r3, bd);
                bh[2 * jj][0] = r0; bh[2 * jj][1] = r1;
                bh[2 * jj + 1][0] = r2; bh[2 * jj + 1][1] = r3;
                bd = sb + BLO_OFF + bOff + kByte + (uint32_t)(jj * 16 * TSTRIDE * 2);
                LDMX4(r0, r1, r2, r3, bd);
                bl[2 * jj][0] = r0; bl[2 * jj][1] = r1;
                bl[2 * jj + 1][0] = r2; bl[2 * jj + 1][1] = r3;
            }
#pragma unroll
            for (int i = 0; i < 4; i++)
#pragma unroll
                for (int j = 0; j < 4; j++) MMA16816(acc[i][j], ah[i], bh[j]);
#pragma unroll
            for (int i = 0; i < 4; i++)
#pragma unroll
                for (int j = 0; j < 4; j++) MMA16816(acc[i][j], ah[i], bl[j]);
#pragma unroll
            for (int i = 0; i < 4; i++)
#pragma unroll
                for (int j = 0; j < 4; j++) MMA16816(acc[i][j], al[i], bh[j]);
        }

        // ---- epilogue: bias, store, accumulate BN stats into regs ----
        const float* bs = (const float*)(smem + BIAS_OFF);
#pragma unroll
        for (int i = 0; i < 4; i++) {
            int r0g = rowBase + m0 + i * 16 + rq;
#pragma unroll
            for (int j = 0; j < 4; j++) {
                int cg = n0 + j * 8 + cq;
                float bx = bs[cg], by = bs[cg + 1];
                if (r0g < NN) {
                    float v0 = acc[i][j][0] + bx, v1 = acc[i][j][1] + by;
                    *(float2*)(Y + (size_t)r0g * DD + cg) = make_float2(v0, v1);
                    ps[j][0] += v0; pq[j][0] += v0 * v0;
                    ps[j][1] += v1; pq[j][1] += v1 * v1;
                }
                if (r0g + 8 < NN) {
                    float v2 = acc[i][j][2] + bx, v3 = acc[i][j][3] + by;
                    *(float2*)(Y + (size_t)(r0g + 8) * DD + cg) = make_float2(v2, v3);
                    ps[j][0] += v2; pq[j][0] += v2 * v2;
                    ps[j][1] += v3; pq[j][1] += v3 * v3;
                }
            }
        }
        __syncthreads();
    }

    // ---- one-time stats flush ----
    float* scs = (float*)(smem + STAT_OFF);
    float* scq = scs + 128;
#pragma unroll
    for (int j = 0; j < 4; j++)
#pragma unroll
        for (int c = 0; c < 2; c++) {
#pragma unroll
            for (int m = 4; m <= 16; m <<= 1) {
                ps[j][c] += __shfl_xor_sync(0xFFFFFFFFu, ps[j][c], m);
                pq[j][c] += __shfl_xor_sync(0xFFFFFFFFu, pq[j][c], m);
            }
        }
    if (rq == 0) {
#pragma unroll
        for (int j = 0; j < 4; j++)
#pragma unroll
            for (int c = 0; c < 2; c++) {
                atomicAdd(&scs[n0 + j * 8 + cq + c], ps[j][c]);
                atomicAdd(&scq[n0 + j * 8 + cq + c], pq[j][c]);
            }
    }
    __syncthreads();
    if (tid < 128) {
        atomicAdd(&statOut[tid],       scs[tid]);
        atomicAdd(&statOut[128 + tid], scq[tid]);
    }
}

// ---------------- final output: out = y2*s2+t2, s2/t2 inline from last bank ----------
__global__ void finalize_k(float* __restrict__ out,
                           const float* __restrict__ statIn,
                           const float* __restrict__ bnG, const float* __restrict__ bnB)
{
    __shared__ float sN[128], tN[128];
    int tid = threadIdx.x;
    bn_inline(tid, statIn, bnG, bnB, sN, tN);
    __syncthreads();
    int i = blockIdx.x * 256 + tid;
    int d4 = (i * 4) & 127;
    float4 v = ((const float4*)g_y2)[i];
    v.x = fmaf(v.x, sN[d4],     tN[d4]);
    v.y = fmaf(v.y, sN[d4 + 1], tN[d4 + 1]);
    v.z = fmaf(v.z, sN[d4 + 2], tN[d4 + 2]);
    v.w = fmaf(v.w, sN[d4 + 3], tN[d4 + 3]);
    ((float4*)out)[i] = v;
}

extern "C" void kernel_launch(void* const* d_in, const int* in_sizes, int n_in,
                              void* d_out, int out_size)
{
    const float* x    = (const float*)d_in[0];
    const int*   ei32 = (const int*)d_in[1];
    const float* eps  = (const float*)d_in[2];
    const float* W1   = (const float*)d_in[3];
    const float* b1   = (const float*)d_in[4];
    const float* bn1g = (const float*)d_in[5];
    const float* bn1b = (const float*)d_in[6];
    const float* W2   = (const float*)d_in[7];
    const float* b2   = (const float*)d_in[8];
    const float* bn2g = (const float*)d_in[9];
    const float* bn2b = (const float*)d_in[10];

    float *y1p, *y2p, *statsp;
    unsigned short *whip, *wlop;
    cudaGetSymbolAddress((void**)&y1p,    g_y1);
    cudaGetSymbolAddress((void**)&y2p,    g_y2);
    cudaGetSymbolAddress((void**)&statsp, g_stats);
    cudaGetSymbolAddress((void**)&whip,   g_whi);
    cudaGetSymbolAddress((void**)&wlop,   g_wlo);

    cudaFuncSetAttribute((const void*)gemm_tc_k<1>, cudaFuncAttributeMaxDynamicSharedMemorySize, GEMM_SMEM);
    cudaFuncSetAttribute((const void*)gemm_tc_k<2>, cudaFuncAttributeMaxDynamicSharedMemorySize, GEMM_SMEM);

    // prep: weights + stats-zero + edge count + layer-0 quantize
    prep_k<<<6634, 256>>>(W1, W2, ei32, x);
    scan_k<<<49, 1024>>>();
    fill_k<<<3125, 256>>>(ei32);   // also re-zeroes g_deg / g_flag for next replay

    for (int l = 0; l < 3; l++) {
        float* bank1 = statsp + (size_t)(2 * l) * 256;
        float* bank2 = statsp + (size_t)(2 * l + 1) * 256;
        if (l == 0) {
            agg_k<0><<<6250, 256>>>(x, eps, l);
        } else {
            q_k<<<3125, 256>>>(y2p, statsp + (size_t)(2 * l - 1) * 256,
                               bn2g + (size_t)(l - 1) * DD, bn2b + (size_t)(l - 1) * DD);
            agg_k<1><<<6250, 256>>>(nullptr, eps, l);
        }
        gemm_tc_k<1><<<GEMM_GRID, 256, GEMM_SMEM>>>(nullptr,
            whip + (size_t)l * 16384, wlop + (size_t)l * 16384,
            b1 + (size_t)l * DD, y1p, bank1, nullptr, nullptr, nullptr);
        gemm_tc_k<2><<<GEMM_GRID, 256, GEMM_SMEM>>>(y1p,
            whip + (size_t)(3 + l) * 16384, wlop + (size_t)(3 + l) * 16384,
            b2 + (size_t)l * DD, y2p, bank2,
            bank1, bn1g + (size_t)l * DD, bn1b + (size_t)l * DD);
    }
    finalize_k<<<6250, 256>>>((float*)d_out, statsp + 5 * 256,
                              bn2g + (size_t)2 * DD, bn2b + (size_t)2 * DD);
}

// round 17
// speedup vs baseline: 1.4965x; 1.0180x over previous
#include <cuda_runtime.h>
#include <cuda_bf16.h>
#include <cuda_fp16.h>
#include <cstdint>

#define NN 50000
#define DD 128
#define EE 800000
#define NTILES 391
#define GEMM_GRID 148

// ---------------- scratch (static device globals: no allocation) ----------------
__device__ __align__(16) float g_y1[NN * DD];
__device__ __align__(16) float g_y2[NN * DD];
__device__ __align__(16) unsigned short g_hf[NN * DD];    // fp16 gather image (ALWAYS relu'd)
__device__ __align__(16) unsigned short g_ahi[NN * DD];   // pre-split GEMM1 A (hi)
__device__ __align__(16) unsigned short g_alo[NN * DD];   // pre-split GEMM1 A (lo)
__device__ __align__(16) float g_stats[1536];  // 6 banks x 256; zeroed by prep (invariant)
__device__ int g_is64;
__device__ __align__(16) unsigned short g_whi[6 * DD * DD];
__device__ __align__(16) unsigned short g_wlo[6 * DD * DD];
__device__ int g_deg[50176];     // zero at prep entry (re-zeroed by fill_k)
__device__ int g_off[50176];
__device__ int g_cursor[50176];
__device__ int g_flag[64];       // lookback flags: zero at scan entry (re-zeroed by fill_k)
__device__ int g_srcs[EE];

__device__ __forceinline__ uint32_t smem_to_u32(const void* p) {
    uint32_t a;
    asm("{ .reg .u64 t; cvta.to.shared.u64 t, %1; cvt.u32.u64 %0, t; }" : "=r"(a) : "l"(p));
    return a;
}

#define LDMX4(r0, r1, r2, r3, addr) \
    asm volatile("ldmatrix.sync.aligned.m8n8.x4.shared.b16 {%0,%1,%2,%3}, [%4];" \
                 : "=r"(r0), "=r"(r1), "=r"(r2), "=r"(r3) : "r"(addr))

#define MMA16816(d, a, b) \
    asm volatile("mma.sync.aligned.m16n8k16.row.col.f32.bf16.bf16.f32 " \
                 "{%0,%1,%2,%3}, {%4,%5,%6,%7}, {%8,%9}, {%0,%1,%2,%3};" \
                 : "+f"((d)[0]), "+f"((d)[1]), "+f"((d)[2]), "+f"((d)[3]) \
                 : "r"((a)[0]), "r"((a)[1]), "r"((a)[2]), "r"((a)[3]), "r"((b)[0]), "r"((b)[1]))

// BN scale/shift from a stats bank (tid < 128 computes into smem arrays)
__device__ __forceinline__ void bn_inline(int tid, const float* statIn,
                                          const float* bnG, const float* bnB,
                                          float* sN, float* tN)
{
    if (tid < 128) {
        float mu  = statIn[tid] * (1.0f / NN);
        float var = statIn[128 + tid] * (1.0f / NN) - mu * mu;
        float sc  = bnG[tid] * rsqrtf(var + 1e-5f);
        sN[tid] = sc;
        tN[tid] = bnB[tid] - mu * sc;
    }
}

__device__ __forceinline__ int detect_is64(const int* __restrict__ ei32) {
    int is64 = 1;
#pragma unroll
    for (int i = 0; i < 8; i++)
        if (ei32[2 * i + 1] != 0) is64 = 0;
    return is64;
}

// ===== mega-prep: weights+stats-zero | edge count | layer-0 quantize — ONE kernel =====
// quantize stores fp16(relu(x)) so agg needs NO relu (messages = relu(x)[src]).
__global__ void prep_k(const float* __restrict__ W1, const float* __restrict__ W2,
                       const int* __restrict__ ei32, const float* __restrict__ x)
{
    int b = blockIdx.x;
    int tid = threadIdx.x;
    if (b < 384) {
        int wi = b >> 6;
        int id = ((b & 63) << 8) + tid;
        const float* W = (wi < 3) ? (W1 + (size_t)wi * 16384) : (W2 + (size_t)(wi - 3) * 16384);
        int k = id >> 7, n = id & 127;
        float v = W[k * 128 + n];
        __nv_bfloat16 hb = __float2bfloat16(v);
        __nv_bfloat16 lb = __float2bfloat16(v - __bfloat162float(hb));
        g_whi[(size_t)wi * 16384 + n * 128 + k] = __bfloat16_as_ushort(hb);
        g_wlo[(size_t)wi * 16384 + n * 128 + k] = __bfloat16_as_ushort(lb);
        if (b < 6) g_stats[b * 256 + tid] = 0.f;
        if (b == 0 && tid == 0) g_is64 = detect_is64(ei32);
    } else if (b < 3509) {
        int e = (b - 384) * 256 + tid;
        if (e < EE) {
            int is64 = detect_is64(ei32);
            int d = is64 ? ei32[2 * (EE + e)] : ei32[EE + e];
            atomicAdd(&g_deg[d], 1);
        }
    } else {
        int base = ((b - 3509) * 256 + tid) * 8;
        float4 p0 = *(const float4*)(x + base);
        float4 p1 = *(const float4*)(x + base + 4);
        float v[8] = {p0.x, p0.y, p0.z, p0.w, p1.x, p1.y, p1.z, p1.w};
        unsigned short o[8];
#pragma unroll
        for (int j = 0; j < 8; j++)
            o[j] = __half_as_ushort(__float2half_rn(fmaxf(v[j], 0.f)));   // relu HERE
        uint32_t w0 = (uint32_t)o[0] | ((uint32_t)o[1] << 16);
        uint32_t w1 = (uint32_t)o[2] | ((uint32_t)o[3] << 16);
        uint32_t w2 = (uint32_t)o[4] | ((uint32_t)o[5] << 16);
        uint32_t w3 = (uint32_t)o[6] | ((uint32_t)o[7] << 16);
        *(uint4*)(g_hf + base) = make_uint4(w0, w1, w2, w3);
    }
}

// ===== single-pass exclusive scan over 50176 degrees (decoupled lookback) =====
__global__ void scan_k() {
    __shared__ int sm[1024];
    __shared__ int sb[64];
    int t = threadIdx.x, b = blockIdx.x;
    int gid = b * 1024 + t;
    int v = (gid < NN) ? g_deg[gid] : 0;
    sm[t] = v;
    __syncthreads();
    for (int o = 1; o < 1024; o <<= 1) {
        int tv = (t >= o) ? sm[t - o] : 0;
        __syncthreads();
        sm[t] += tv;
        __syncthreads();
    }
    if (t == 1023) atomicExch(&g_flag[b], sm[1023] + 1);
    if (t < 64) sb[t] = 0;
    __syncthreads();
    if (t < b) {
        int f;
        do { f = atomicAdd(&g_flag[t], 0); } while (f == 0);
        sb[t] = f - 1;
    }
    __syncthreads();
    if (t < 32) sb[t] += sb[t + 32];
    __syncthreads();
    if (t < 16) sb[t] += sb[t + 16];
    __syncthreads();
    if (t < 8) sb[t] += sb[t + 8];
    __syncthreads();
    if (t < 4) sb[t] += sb[t + 4];
    __syncthreads();
    if (t < 2) sb[t] += sb[t + 2];
    __syncthreads();
    if (t == 0) sb[0] += sb[1];
    __syncthreads();
    int o = sb[0] + sm[t] - v;
    g_off[gid] = o;
    g_cursor[gid] = o;
}

// fill: scatter srcs; restore g_deg/g_flag zero invariants
__global__ void fill_k(const int* __restrict__ ei32) {    // 3125 x 256
    int e = blockIdx.x * 256 + threadIdx.x;
    if (e < 50176) g_deg[e] = 0;
    if (e < 64) g_flag[e] = 0;
    if (e >= EE) return;
    int s, d;
    if (g_is64) { s = ei32[2 * e]; d = ei32[2 * (EE + e)]; }
    else        { s = ei32[e];     d = ei32[EE + e]; }
    int pos = atomicAdd(&g_cursor[d], 1);
    g_srcs[pos] = s;
}

// --------- quantize y2 with prev outer BN + relu (layers 1,2) ---------
__global__ void q_k(const float* __restrict__ P,
                    const float* __restrict__ statIn,
                    const float* __restrict__ bnG, const float* __restrict__ bnB)
{
    __shared__ float sN[128], tN[128];
    int tid = threadIdx.x;
    bn_inline(tid, statIn, bnG, bnB, sN, tN);
    __syncthreads();
    int base = (blockIdx.x * 256 + tid) * 8;
    int col = base & 127;
    float4 p0 = *(const float4*)(P + base);
    float4 p1 = *(const float4*)(P + base + 4);
    float v[8] = {p0.x, p0.y, p0.z, p0.w, p1.x, p1.y, p1.z, p1.w};
#pragma unroll
    for (int j = 0; j < 8; j++)
        v[j] = fmaxf(fmaf(v[j], sN[col + j], tN[col + j]), 0.f);
    unsigned short o[8];
#pragma unroll
    for (int j = 0; j < 8; j++) o[j] = __half_as_ushort(__float2half_rn(v[j]));
    uint32_t w0 = (uint32_t)o[0] | ((uint32_t)o[1] << 16);
    uint32_t w1 = (uint32_t)o[2] | ((uint32_t)o[3] << 16);
    uint32_t w2 = (uint32_t)o[4] | ((uint32_t)o[5] << 16);
    uint32_t w3 = (uint32_t)o[6] | ((uint32_t)o[7] << 16);
    *(uint4*)(g_hf + base) = make_uint4(w0, w1, w2, w3);
}

// ------- aggregation + GIN combine + bf16 split: writes GEMM-ready A images -------
// g_hf is pre-relu'd -> pure sum, no fmaxf in the hot loop
__device__ __forceinline__ void add4(float* acc, uint2 q) {
    float2 f0 = __half22float2(*(__half2*)&q.x);
    float2 f1 = __half22float2(*(__half2*)&q.y);
    acc[0] += f0.x;
    acc[1] += f0.y;
    acc[2] += f1.x;
    acc[3] += f1.y;
}
template <int TRANS>
__global__ void __launch_bounds__(256) agg_k(const float* __restrict__ x,
                                             const float* __restrict__ epsp, int layer)
{
    int w = blockIdx.x * 8 + (threadIdx.x >> 5);  // 6250 blocks -> 50000 warps
    int lane = threadIdx.x & 31;
    int s = g_off[w], t = g_off[w + 1];
    const unsigned short* H = g_hf;
    int lc = lane * 4;                            // 4 halves/lane; warp covers a row
    float acc[4] = {0.f, 0.f, 0.f, 0.f};
    int e = s;
    for (; e + 3 < t; e += 4) {
        int s0 = g_srcs[e], s1 = g_srcs[e + 1], s2i = g_srcs[e + 2], s3 = g_srcs[e + 3];
        uint2 q0 = *(const uint2*)(H + (size_t)s0 * DD + lc);
        uint2 q1 = *(const uint2*)(H + (size_t)s1 * DD + lc);
        uint2 q2 = *(const uint2*)(H + (size_t)s2i * DD + lc);
        uint2 q3 = *(const uint2*)(H + (size_t)s3 * DD + lc);
        add4(acc, q0); add4(acc, q1); add4(acc, q2); add4(acc, q3);
    }
    for (; e < t; e++) {
        int s0 = g_srcs[e];
        uint2 q0 = *(const uint2*)(H + (size_t)s0 * DD + lc);
        add4(acc, q0);
    }
    // GIN combine with own row
    float epsv = 1.0f + epsp[layer];
    float own[4];
    if (TRANS) {
        uint2 q = *(const uint2*)(H + (size_t)w * DD + lc);   // already relu(BN(y2))
        float2 f0 = __half22float2(*(__half2*)&q.x);
        float2 f1 = __half22float2(*(__half2*)&q.y);
        own[0] = f0.x; own[1] = f0.y; own[2] = f1.x; own[3] = f1.y;
    } else {
        float4 p = *(const float4*)(x + (size_t)w * DD + lc); // raw fp32 x
        own[0] = p.x; own[1] = p.y; own[2] = p.z; own[3] = p.w;
    }
    unsigned short hi[4], lo[4];
#pragma unroll
    for (int j = 0; j < 4; j++) {
        float A = fmaf(epsv, own[j], acc[j]);
        __nv_bfloat16 h = __float2bfloat16(A);
        __nv_bfloat16 l = __float2bfloat16(A - __bfloat162float(h));
        hi[j] = __bfloat16_as_ushort(h);
        lo[j] = __bfloat16_as_ushort(l);
    }
    uint2 ph = make_uint2((uint32_t)hi[0] | ((uint32_t)hi[1] << 16),
                          (uint32_t)hi[2] | ((uint32_t)hi[3] << 16));
    uint2 pl = make_uint2((uint32_t)lo[0] | ((uint32_t)lo[1] << 16),
                          (uint32_t)lo[2] | ((uint32_t)lo[3] << 16));
    *(uint2*)(g_ahi + (size_t)w * DD + lc) = ph;
    *(uint2*)(g_alo + (size_t)w * DD + lc) = pl;
}

// ---------------- persistent HMMA GEMM (grid-stride over 391 tiles) ----------------
#define TSTRIDE 136
#define TBYTES  (128 * TSTRIDE * 2)
#define BIAS_OFF 0
#define AHI_OFF  1024
#define ALO_OFF  (AHI_OFF + TBYTES)
#define BHI_OFF  (ALO_OFF + TBYTES)
#define BLO_OFF  (BHI_OFF + TBYTES)
#define STAT_OFF (BLO_OFF + TBYTES)
#define SN_OFF   (STAT_OFF + 1024)
#define GEMM_SMEM (SN_OFF + 1024)

template <int MODE>
__global__ void __launch_bounds__(256, 1) gemm_tc_k(
    const float* __restrict__ A0,
    const unsigned short* __restrict__ whi, const unsigned short* __restrict__ wlo,
    const float* __restrict__ bias, float* __restrict__ Y,
    float* __restrict__ statOut,
    const float* __restrict__ statIn, const float* __restrict__ bnG, const float* __restrict__ bnB)
{
    extern __shared__ __align__(16) char smem[];
    uint32_t sb = smem_to_u32(smem);
    int tid = threadIdx.x;
    int wid = tid >> 5, lane = tid & 31;

    if (tid < 128) *(float*)(smem + BIAS_OFF + tid * 4) = bias[tid];
    ((float*)(smem + STAT_OFF))[tid] = 0.f;

    float* sN = (float*)(smem + SN_OFF);
    float* tN = sN + 128;
    if (MODE == 2) bn_inline(tid, statIn, bnG, bnB, sN, tN);
    __syncthreads();

    // ---- B tiles: loaded ONCE per block ----
    {
        const uint4* sh = (const uint4*)whi;
        const uint4* sl = (const uint4*)wlo;
#pragma unroll
        for (int i = 0; i < 8; i++) {
            int id = i * 256 + tid;
            int r = id >> 4, c16 = id & 15;
            uint32_t dst = (uint32_t)(r * (TSTRIDE * 2) + c16 * 16);
            *(uint4*)(smem + BHI_OFF + dst) = sh[id];
            *(uint4*)(smem + BLO_OFF + dst) = sl[id];
        }
    }

    int wm = wid & 1, wn = wid >> 1;
    int m0 = wm * 64, n0 = wn * 32;
    uint32_t aOff = (uint32_t)((m0 + (lane & 15)) * (TSTRIDE * 2) + (lane >> 4) * 16);
    uint32_t bOff = (uint32_t)((n0 + (lane & 7) + (lane >> 4) * 8) * (TSTRIDE * 2) + ((lane >> 3) & 1) * 16);
    int rq = lane >> 2, cq = (lane & 3) * 2;

    float ps[4][2], pq[4][2];
#pragma unroll
    for (int j = 0; j < 4; j++) { ps[j][0] = ps[j][1] = 0.f; pq[j][0] = pq[j][1] = 0.f; }

    for (int tile = blockIdx.x; tile < NTILES; tile += gridDim.x) {
        int rowBase = tile * 128;

        // ---- A tile prologue ----
        if (MODE == 1) {
#pragma unroll
            for (int it = 0; it < 8; it++) {
                int id = it * 256 + tid;
                int r = id >> 4, c16 = id & 15;
                int gr = rowBase + r;
                uint4 vh = make_uint4(0, 0, 0, 0), vl = make_uint4(0, 0, 0, 0);
                if (gr < NN) {
                    size_t so = (size_t)gr * DD + c16 * 8;
                    vh = *(const uint4*)(g_ahi + so);
                    vl = *(const uint4*)(g_alo + so);
                }
                uint32_t off = (uint32_t)(r * (TSTRIDE * 2) + c16 * 16);
                *(uint4*)(smem + AHI_OFF + off) = vh;
                *(uint4*)(smem + ALO_OFF + off) = vl;
            }
        } else {
#pragma unroll
            for (int it = 0; it < 8; it++) {
                int id = it * 256 + tid;
                int row = id >> 4;
                int col = (id & 15) * 8;
                int gr = rowBase + row;
                float v[8];
#pragma unroll
                for (int j = 0; j < 8; j++) v[j] = 0.f;
                if (gr < NN) {
                    float4 p0 = *(const float4*)(A0 + (size_t)gr * DD + col);
                    float4 p1 = *(const float4*)(A0 + (size_t)gr * DD + col + 4);
                    v[0] = p0.x; v[1] = p0.y; v[2] = p0.z; v[3] = p0.w;
                    v[4] = p1.x; v[5] = p1.y; v[6] = p1.z; v[7] = p1.w;
#pragma unroll
                    for (int j = 0; j < 8; j++)
                        v[j] = fmaxf(fmaf(v[j], sN[col + j], tN[col + j]), 0.f);
                }
                uint32_t h[4], l[4];
#pragma unroll
                for (int j = 0; j < 4; j++) {
                    __nv_bfloat16 h0 = __float2bfloat16(v[2 * j]);
                    __nv_bfloat16 h1 = __float2bfloat16(v[2 * j + 1]);
                    __nv_bfloat16 l0 = __float2bfloat16(v[2 * j] - __bfloat162float(h0));
                    __nv_bfloat16 l1 = __float2bfloat16(v[2 * j + 1] - __bfloat162float(h1));
                    h[j] = ((uint32_t)__bfloat16_as_ushort(h1) << 16) | __bfloat16_as_ushort(h0);
                    l[j] = ((uint32_t)__bfloat16_as_ushort(l1) << 16) | __bfloat16_as_ushort(l0);
                }
                uint32_t off = (uint32_t)(row * (TSTRIDE * 2) + col * 2);
                *(uint4*)(smem + AHI_OFF + off) = make_uint4(h[0], h[1], h[2], h[3]);
                *(uint4*)(smem + ALO_OFF + off) = make_uint4(l[0], l[1], l[2], l[3]);
            }
        }
        __syncthreads();

        // ---- warp MMA mainloop ----
        float acc[4][4][4];
#pragma unroll
        for (int i = 0; i < 4; i++)
#pragma unroll
            for (int j = 0; j < 4; j++)
#pragma unroll
                for (int q = 0; q < 4; q++) acc[i][j][q] = 0.f;

#pragma unroll
        for (int ks = 0; ks < 8; ks++) {
            uint32_t kByte = (uint32_t)(ks * 32);
            uint32_t ah[4][4], al[4][4], bh[4][2], bl[4][2];
#pragma unroll
            for (int i = 0; i < 4; i++) {
                uint32_t ad = sb + AHI_OFF + aOff + kByte + (uint32_t)(i * 16 * TSTRIDE * 2);
                LDMX4(ah[i][0], ah[i][1], ah[i][2], ah[i][3], ad);
            }
#pragma unroll
            for (int i = 0; i < 4; i++) {
                uint32_t ad = sb + ALO_OFF + aOff + kByte + (uint32_t)(i * 16 * TSTRIDE * 2);
                LDMX4(al[i][0], al[i][1], al[i][2], al[i][3], ad);
            }
#pragma unroll
            for (int jj = 0; jj < 2; jj++) {
                uint32_t bd = sb + BHI_OFF + bOff + kByte + (uint32_t)(jj * 16 * TSTRIDE * 2);
                uint32_t r0, r1, r2, r3;
                LDMX4(r0, r1, r2, r3, bd);
                bh[2 * jj][0] = r0; bh[2 * jj][1] = r1;
                bh[2 * jj + 1][0] = r2; bh[2 * jj + 1][1] = r3;
                bd = sb + BLO_OFF + bOff + kByte + (uint32_t)(jj * 16 * TSTRIDE * 2);
                LDMX4(r0, r1, r2, r3, bd);
                bl[2 * jj][0] = r0; bl[2 * jj][1] = r1;
                bl[2 * jj + 1][0] = r2; bl[2 * jj + 1][1] = r3;
            }
#pragma unroll
            for (int i = 0; i < 4; i++)
#pragma unroll
                for (int j = 0; j < 4; j++) MMA16816(acc[i][j], ah[i], bh[j]);
#pragma unroll
            for (int i = 0; i < 4; i++)
#pragma unroll
                for (int j = 0; j < 4; j++) MMA16816(acc[i][j], ah[i], bl[j]);
#pragma unroll
            for (int i = 0; i < 4; i++)
#pragma unroll
                for (int j = 0; j < 4; j++) MMA16816(acc[i][j], al[i], bh[j]);
        }

        // ---- epilogue: bias, store, accumulate BN stats into regs ----
        const float* bs = (const float*)(smem + BIAS_OFF);
#pragma unroll
        for (int i = 0; i < 4; i++) {
            int r0g = rowBase + m0 + i * 16 + rq;
#pragma unroll
            for (int j = 0; j < 4; j++) {
                int cg = n0 + j * 8 + cq;
                float bx = bs[cg], by = bs[cg + 1];
                if (r0g < NN) {
                    float v0 = acc[i][j][0] + bx, v1 = acc[i][j][1] + by;
                    *(float2*)(Y + (size_t)r0g * DD + cg) = make_float2(v0, v1);
                    ps[j][0] += v0; pq[j][0] += v0 * v0;
                    ps[j][1] += v1; pq[j][1] += v1 * v1;
                }
                if (r0g + 8 < NN) {
                    float v2 = acc[i][j][2] + bx, v3 = acc[i][j][3] + by;
                    *(float2*)(Y + (size_t)(r0g + 8) * DD + cg) = make_float2(v2, v3);
                    ps[j][0] += v2; pq[j][0] += v2 * v2;
                    ps[j][1] += v3; pq[j][1] += v3 * v3;
                }
            }
        }
        __syncthreads();
    }

    // ---- one-time stats flush ----
    float* scs = (float*)(smem + STAT_OFF);
    float* scq = scs + 128;
#pragma unroll
    for (int j = 0; j < 4; j++)
#pragma unroll
        for (int c = 0; c < 2; c++) {
#pragma unroll
            for (int m = 4; m <= 16; m <<= 1) {
                ps[j][c] += __shfl_xor_sync(0xFFFFFFFFu, ps[j][c], m);
                pq[j][c] += __shfl_xor_sync(0xFFFFFFFFu, pq[j][c], m);
            }
        }
    if (rq == 0) {
#pragma unroll
        for (int j = 0; j < 4; j++)
#pragma unroll
            for (int c = 0; c < 2; c++) {
                atomicAdd(&scs[n0 + j * 8 + cq + c], ps[j][c]);
                atomicAdd(&scq[n0 + j * 8 + cq + c], pq[j][c]);
            }
    }
    __syncthreads();
    if (tid < 128) {
        atomicAdd(&statOut[tid],       scs[tid]);
        atomicAdd(&statOut[128 + tid], scq[tid]);
    }
}

// ---------------- final output: out = y2*s2+t2, s2/t2 inline from last bank ----------
__global__ void finalize_k(float* __restrict__ out,
                           const float* __restrict__ statIn,
                           const float* __restrict__ bnG, const float* __restrict__ bnB)
{
    __shared__ float sN[128], tN[128];
    int tid = threadIdx.x;
    bn_inline(tid, statIn, bnG, bnB, sN, tN);
    __syncthreads();
    int i = blockIdx.x * 256 + tid;
    int d4 = (i * 4) & 127;
    float4 v = ((const float4*)g_y2)[i];
    v.x = fmaf(v.x, sN[d4],     tN[d4]);
    v.y = fmaf(v.y, sN[d4 + 1], tN[d4 + 1]);
    v.z = fmaf(v.z, sN[d4 + 2], tN[d4 + 2]);
    v.w = fmaf(v.w, sN[d4 + 3], tN[d4 + 3]);
    ((float4*)out)[i] = v;
}

extern "C" void kernel_launch(void* const* d_in, const int* in_sizes, int n_in,
                              void* d_out, int out_size)
{
    const float* x    = (const float*)d_in[0];
    const int*   ei32 = (const int*)d_in[1];
    const float* eps  = (const float*)d_in[2];
    const float* W1   = (const float*)d_in[3];
    const float* b1   = (const float*)d_in[4];
    const float* bn1g = (const float*)d_in[5];
    const float* bn1b = (const float*)d_in[6];
    const float* W2   = (const float*)d_in[7];
    const float* b2   = (const float*)d_in[8];
    const float* bn2g = (const float*)d_in[9];
    const float* bn2b = (const float*)d_in[10];

    float *y1p, *y2p, *statsp;
    unsigned short *whip, *wlop;
    cudaGetSymbolAddress((void**)&y1p,    g_y1);
    cudaGetSymbolAddress((void**)&y2p,    g_y2);
    cudaGetSymbolAddress((void**)&statsp, g_stats);
    cudaGetSymbolAddress((void**)&whip,   g_whi);
    cudaGetSymbolAddress((void**)&wlop,   g_wlo);

    cudaFuncSetAttribute((const void*)gemm_tc_k<1>, cudaFuncAttributeMaxDynamicSharedMemorySize, GEMM_SMEM);
    cudaFuncSetAttribute((const void*)gemm_tc_k<2>, cudaFuncAttributeMaxDynamicSharedMemorySize, GEMM_SMEM);

    // prep: weights + stats-zero + edge count + layer-0 quantize (relu'd)
    prep_k<<<6634, 256>>>(W1, W2, ei32, x);
    scan_k<<<49, 1024>>>();
    fill_k<<<3125, 256>>>(ei32);   // also re-zeroes g_deg / g_flag for next replay

    for (int l = 0; l < 3; l++) {
        float* bank1 = statsp + (size_t)(2 * l) * 256;
        float* bank2 = statsp + (size_t)(2 * l + 1) * 256;
        if (l == 0) {
            agg_k<0><<<6250, 256>>>(x, eps, l);
        } else {
            q_k<<<3125, 256>>>(y2p, statsp + (size_t)(2 * l - 1) * 256,
                               bn2g + (size_t)(l - 1) * DD, bn2b + (size_t)(l - 1) * DD);
            agg_k<1><<<6250, 256>>>(nullptr, eps, l);
        }
        gemm_tc_k<1><<<GEMM_GRID, 256, GEMM_SMEM>>>(nullptr,
            whip + (size_t)l * 16384, wlop + (size_t)l * 16384,
            b1 + (size_t)l * DD, y1p, bank1, nullptr, nullptr, nullptr);
        gemm_tc_k<2><<<GEMM_GRID, 256, GEMM_SMEM>>>(y1p,
            whip + (size_t)(3 + l) * 16384, wlop + (size_t)(3 + l) * 16384,
            b2 + (size_t)l * DD, y2p, bank2,
            bank1, bn1g + (size_t)l * DD, bn1b + (size_t)l * DD);
    }
    finalize_k<<<6250, 256>>>((float*)d_out, statsp + 5 * 256,
                              bn2g + (size_t)2 * DD, bn2b + (size_t)2 * DD);
}